// round 1
// baseline (speedup 1.0000x reference)
#include <cuda_runtime.h>
#include <math.h>

#define S_    1536
#define HID_  6144
#define NH_   64
#define DN_   128
#define DR_   64
#define DV_   128
#define QL_   1536
#define KVL_  512
#define DF_   576        // KVL + DR
#define QDIM_ 192        // DN + DR

#define SM_SCALE_  0.07216878364870322f   // (DN+DR)^-0.5
#define SCALE_Q_   2.0f                   // sqrt(HID/QL)
#define SCALE_KV_  3.4641016151377544f    // sqrt(HID/KVL)

// ---------------- scratch (device globals; no allocation allowed) -----------
__device__ float g_qlat   [(size_t)S_ * QL_];          // 9.4 MB
__device__ float g_q      [(size_t)S_ * NH_ * QDIM_];  // 75 MB
__device__ float g_latent [(size_t)S_ * DF_];          // 3.5 MB
__device__ float g_kfull  [(size_t)S_ * DF_];          // 3.5 MB
__device__ float g_qfull  [(size_t)NH_ * S_ * DF_];    // 226 MB
__device__ float g_scores [(size_t)NH_ * S_ * S_];     // 604 MB
__device__ float g_ctx    [(size_t)NH_ * S_ * KVL_];   // 201 MB
__device__ float g_attnout[(size_t)S_ * NH_ * DV_];    // 50 MB

// ---------------- generic batched SGEMM: C = alpha * A * op(B) --------------
// A: [M,K] row-major (lda).  TB=false: B [K,N] (ldb).  TB=true: B [N,K] (ldb).
// Requires M % 128 == 0, K % 16 == 0. N arbitrary (guarded).
template <bool TB>
__global__ __launch_bounds__(256) void sgemm(
    const float* __restrict__ A, const float* __restrict__ B, float* __restrict__ C,
    int M, int N, int K, int lda, int ldb, int ldc,
    long long sA, long long sB, long long sC, float alpha)
{
    __shared__ float As[16][128];
    __shared__ float Bs[16][128];

    const long long bz = blockIdx.z;
    A += bz * sA;  B += bz * sB;  C += bz * sC;

    const int row0 = blockIdx.y * 128;
    const int col0 = blockIdx.x * 128;
    const int tid  = threadIdx.x;
    const int tr   = tid >> 4;        // 0..15
    const int tc   = tid & 15;        // 0..15

    // loader indices
    const int a_m = tid >> 2;         // 0..63 (also NT n-index)
    const int a_k = (tid & 3) * 4;    // 0,4,8,12
    const int b_k = tid >> 4;         // 0..15  (NN)
    const int b_n = (tid & 15) * 4;   // 0..60  (NN)

    float acc[8][8];
#pragma unroll
    for (int i = 0; i < 8; i++)
#pragma unroll
        for (int j = 0; j < 8; j++) acc[i][j] = 0.f;

    for (int k0 = 0; k0 < K; k0 += 16) {
        // ---- load A tile (always in-bounds: M%128==0, K%16==0) ----
#pragma unroll
        for (int h = 0; h < 2; h++) {
            int m = a_m + h * 64;
            float4 v = *reinterpret_cast<const float4*>(
                &A[(long long)(row0 + m) * lda + k0 + a_k]);
            As[a_k + 0][m] = v.x; As[a_k + 1][m] = v.y;
            As[a_k + 2][m] = v.z; As[a_k + 3][m] = v.w;
        }
        // ---- load B tile ----
        if (!TB) {
#pragma unroll
            for (int h = 0; h < 2; h++) {
                int n  = b_n + h * 64;
                int gn = col0 + n;
                if (gn + 3 < N) {
                    float4 v = *reinterpret_cast<const float4*>(
                        &B[(long long)(k0 + b_k) * ldb + gn]);
                    Bs[b_k][n]   = v.x; Bs[b_k][n+1] = v.y;
                    Bs[b_k][n+2] = v.z; Bs[b_k][n+3] = v.w;
                } else {
#pragma unroll
                    for (int j = 0; j < 4; j++)
                        Bs[b_k][n + j] = (gn + j < N)
                            ? B[(long long)(k0 + b_k) * ldb + gn + j] : 0.f;
                }
            }
        } else {
#pragma unroll
            for (int h = 0; h < 2; h++) {
                int n  = a_m + h * 64;
                int gn = col0 + n;
                if (gn < N) {
                    float4 v = *reinterpret_cast<const float4*>(
                        &B[(long long)gn * ldb + k0 + a_k]);
                    Bs[a_k + 0][n] = v.x; Bs[a_k + 1][n] = v.y;
                    Bs[a_k + 2][n] = v.z; Bs[a_k + 3][n] = v.w;
                } else {
                    Bs[a_k + 0][n] = 0.f; Bs[a_k + 1][n] = 0.f;
                    Bs[a_k + 2][n] = 0.f; Bs[a_k + 3][n] = 0.f;
                }
            }
        }
        __syncthreads();

        // ---- 8x8 microtile FMA (128-bit conflict-free shared reads) ----
#pragma unroll
        for (int kk = 0; kk < 16; kk++) {
            float4 a0 = *reinterpret_cast<const float4*>(&As[kk][tr * 4]);
            float4 a1 = *reinterpret_cast<const float4*>(&As[kk][64 + tr * 4]);
            float4 b0 = *reinterpret_cast<const float4*>(&Bs[kk][tc * 4]);
            float4 b1 = *reinterpret_cast<const float4*>(&Bs[kk][64 + tc * 4]);
            float av[8] = {a0.x, a0.y, a0.z, a0.w, a1.x, a1.y, a1.z, a1.w};
            float bv[8] = {b0.x, b0.y, b0.z, b0.w, b1.x, b1.y, b1.z, b1.w};
#pragma unroll
            for (int i = 0; i < 8; i++)
#pragma unroll
                for (int j = 0; j < 8; j++) acc[i][j] += av[i] * bv[j];
        }
        __syncthreads();
    }

    // ---- store ----
#pragma unroll
    for (int i = 0; i < 8; i++) {
        int m = row0 + ((i < 4) ? (tr * 4 + i) : (64 + tr * 4 + i - 4));
#pragma unroll
        for (int j = 0; j < 8; j++) {
            int n = col0 + ((j < 4) ? (tc * 4 + j) : (64 + tc * 4 + j - 4));
            if (n < N) C[(long long)m * ldc + n] = alpha * acc[i][j];
        }
    }
}

// ---------------- RMSNorm over q_lat rows (in place) ------------------------
__global__ void rmsnorm_q(float* __restrict__ x, const float* __restrict__ w)
{
    const int s = blockIdx.x;
    float* row = x + (long long)s * QL_;
    const int tid = threadIdx.x;
    __shared__ float red[256];
    float ss = 0.f;
    for (int j = tid; j < QL_; j += 256) { float v = row[j]; ss += v * v; }
    red[tid] = ss; __syncthreads();
    for (int off = 128; off > 0; off >>= 1) {
        if (tid < off) red[tid] += red[tid + off];
        __syncthreads();
    }
    const float inv = rsqrtf(red[0] / QL_ + 1e-6f) * SCALE_Q_;
    for (int j = tid; j < QL_; j += 256) row[j] = w[j] * row[j] * inv;
}

// ---------------- kva RMSNorm + k_pe RoPE -> k_full --------------------------
__global__ void kva_norm_rope(const float* __restrict__ latent,
                              const float* __restrict__ w,
                              const float* __restrict__ cosb,
                              const float* __restrict__ sinb,
                              float* __restrict__ kfull)
{
    const int s = blockIdx.x;
    const int tid = threadIdx.x;           // 128 threads
    const float* row = latent + (long long)s * DF_;
    __shared__ float red[128];
    float ss = 0.f;
    for (int j = tid; j < KVL_; j += 128) { float v = row[j]; ss += v * v; }
    red[tid] = ss; __syncthreads();
    for (int off = 64; off > 0; off >>= 1) {
        if (tid < off) red[tid] += red[tid + off];
        __syncthreads();
    }
    const float inv = rsqrtf(red[0] / KVL_ + 1e-6f) * SCALE_KV_;
    float* out = kfull + (long long)s * DF_;
    for (int j = tid; j < KVL_; j += 128) out[j] = w[j] * row[j] * inv;
    if (tid < DR_) {
        const int r = tid;
        float x = row[KVL_ + r];
        float o = (r < 32) ? -row[KVL_ + r + 32] : row[KVL_ + r - 32];
        out[KVL_ + r] = x * cosb[s * DR_ + r] + o * sinb[s * DR_ + r];
    }
}

// ---------------- q_pe RoPE, scattered into q_full[h][s][512+r] --------------
__global__ void rope_q(const float* __restrict__ q,
                       const float* __restrict__ cosb,
                       const float* __restrict__ sinb,
                       float* __restrict__ qfull)
{
    long long idx = (long long)blockIdx.x * blockDim.x + threadIdx.x;
    if (idx >= (long long)S_ * NH_ * DR_) return;
    const int r = (int)(idx % DR_);
    const int h = (int)((idx / DR_) % NH_);
    const int s = (int)(idx / ((long long)DR_ * NH_));
    const float* qr = q + (long long)s * NH_ * QDIM_ + h * QDIM_ + DN_;
    float x = qr[r];
    float o = (r < 32) ? -qr[r + 32] : qr[r - 32];
    qfull[((long long)h * S_ + s) * DF_ + KVL_ + r] =
        x * cosb[s * DR_ + r] + o * sinb[s * DR_ + r];
}

// ---------------- causal softmax over scores[h][s][:] ------------------------
__global__ void softmax_causal(float* __restrict__ scores)
{
    const int s = blockIdx.x, h = blockIdx.y;
    float* row = scores + ((long long)h * S_ + s) * (long long)S_;
    const int tid = threadIdx.x;
    __shared__ float red[256];

    float m = -1e30f;
    for (int t = tid; t <= s; t += 256) m = fmaxf(m, row[t]);
    red[tid] = m; __syncthreads();
    for (int off = 128; off > 0; off >>= 1) {
        if (tid < off) red[tid] = fmaxf(red[tid], red[tid + off]);
        __syncthreads();
    }
    m = red[0]; __syncthreads();

    float sum = 0.f;
    for (int t = tid; t <= s; t += 256) {
        float e = __expf(row[t] - m);
        row[t] = e; sum += e;
    }
    red[tid] = sum; __syncthreads();
    for (int off = 128; off > 0; off >>= 1) {
        if (tid < off) red[tid] += red[tid + off];
        __syncthreads();
    }
    const float inv = 1.f / red[0];
    for (int t = tid; t < S_; t += 256) row[t] = (t <= s) ? row[t] * inv : 0.f;
}

// =============================================================================
extern "C" void kernel_launch(void* const* d_in, const int* in_sizes, int n_in,
                              void* d_out, int out_size)
{
    const float* hidden = (const float*)d_in[0];
    const float* cosb   = (const float*)d_in[1];
    const float* sinb   = (const float*)d_in[2];
    const float* w_qa   = (const float*)d_in[3];
    const float* qa_ln  = (const float*)d_in[4];
    const float* w_qb   = (const float*)d_in[5];
    const float* w_kva  = (const float*)d_in[6];
    const float* kva_ln = (const float*)d_in[7];
    const float* w_k    = (const float*)d_in[8];
    const float* w_v    = (const float*)d_in[9];
    const float* w_o    = (const float*)d_in[10];
    float* out = (float*)d_out;

    float *qlat, *q, *latent, *kfull, *qfull, *scores, *ctx, *attnout;
    cudaGetSymbolAddress((void**)&qlat,    g_qlat);
    cudaGetSymbolAddress((void**)&q,       g_q);
    cudaGetSymbolAddress((void**)&latent,  g_latent);
    cudaGetSymbolAddress((void**)&kfull,   g_kfull);
    cudaGetSymbolAddress((void**)&qfull,   g_qfull);
    cudaGetSymbolAddress((void**)&scores,  g_scores);
    cudaGetSymbolAddress((void**)&ctx,     g_ctx);
    cudaGetSymbolAddress((void**)&attnout, g_attnout);

    const dim3 blk(256);

    // 1) q_lat = hidden @ w_qa                      [1536,1536] K=6144
    sgemm<false><<<dim3(QL_ / 128, S_ / 128, 1), blk>>>(
        hidden, w_qa, qlat, S_, QL_, HID_, HID_, QL_, QL_, 0, 0, 0, 1.f);

    // 2) RMSNorm(q_lat) * SCALE_Q  (in place)
    rmsnorm_q<<<S_, 256>>>(qlat, qa_ln);

    // 3) q = q_lat @ w_qb                           [1536,12288] K=1536
    sgemm<false><<<dim3(NH_ * QDIM_ / 128, S_ / 128, 1), blk>>>(
        qlat, w_qb, q, S_, NH_ * QDIM_, QL_, QL_, NH_ * QDIM_, NH_ * QDIM_,
        0, 0, 0, 1.f);

    // 4) latent = hidden @ w_kva                    [1536,576] K=6144
    sgemm<false><<<dim3((DF_ + 127) / 128, S_ / 128, 1), blk>>>(
        hidden, w_kva, latent, S_, DF_, HID_, HID_, DF_, DF_, 0, 0, 0, 1.f);

    // 5) k_full = [rmsnorm(c_kv)*SCALE_KV | rope(k_pe)]
    kva_norm_rope<<<S_, 128>>>(latent, kva_ln, cosb, sinb, kfull);

    // 6) q_full[.., 512:576] = rope(q_pe)
    {
        long long tot = (long long)S_ * NH_ * DR_;
        rope_q<<<(unsigned)((tot + 255) / 256), 256>>>(q, cosb, sinb, qfull);
    }

    // 7) q_full[h][:, :512] = q_nope[h] @ w_k[h]    batched x64, K=128
    sgemm<false><<<dim3(KVL_ / 128, S_ / 128, NH_), blk>>>(
        q, w_k, qfull, S_, KVL_, DN_, NH_ * QDIM_, KVL_, DF_,
        (long long)QDIM_, (long long)DN_ * KVL_, (long long)S_ * DF_, 1.f);

    // 8) scores[h] = SM_SCALE * q_full[h] @ k_full^T   batched x64 (NT), K=576
    sgemm<true><<<dim3(S_ / 128, S_ / 128, NH_), blk>>>(
        qfull, kfull, scores, S_, S_, DF_, DF_, DF_, S_,
        (long long)S_ * DF_, 0LL, (long long)S_ * S_, SM_SCALE_);

    // 9) causal softmax (in place, zeros above diagonal)
    softmax_causal<<<dim3(S_, NH_), 256>>>(scores);

    // 10) ctx[h] = attn[h] @ c_kv                   batched x64, K=1536
    sgemm<false><<<dim3(KVL_ / 128, S_ / 128, NH_), blk>>>(
        scores, kfull, ctx, S_, KVL_, S_, S_, DF_, KVL_,
        (long long)S_ * S_, 0LL, (long long)S_ * KVL_, 1.f);

    // 11) attn_out[:, h*128:] = ctx[h] @ w_v[h]     batched x64, K=512
    sgemm<false><<<dim3(1, S_ / 128, NH_), blk>>>(
        ctx, w_v, attnout, S_, DV_, KVL_, KVL_, DV_, NH_ * DV_,
        (long long)S_ * KVL_, (long long)KVL_ * DV_, (long long)DV_, 1.f);

    // 12) out = attn_out @ w_o                      [1536,6144] K=8192
    sgemm<false><<<dim3(HID_ / 128, S_ / 128, 1), blk>>>(
        attnout, w_o, out, S_, HID_, NH_ * DV_, NH_ * DV_, HID_, HID_,
        0, 0, 0, 1.f);
}

// round 4
// speedup vs baseline: 3.1610x; 3.1610x over previous
#include <cuda_runtime.h>
#include <cstdint>
#include <math.h>

#define S_    1536
#define HID_  6144
#define NH_   64
#define DN_   128
#define DR_   64
#define DV_   128
#define QL_   1536
#define KVL_  512
#define DF_   576        // KVL + DR
#define QDIM_ 192        // DN + DR

#define SM_SCALE_  0.07216878364870322f
#define SCALE_Q_   2.0f
#define SCALE_KV_  3.4641016151377544f

#define TILE_M 128
#define TILE_N 128
#define KC     32
#define STAGES 4
#define ROWF   40                      // 32 k-floats + 8 pad (conflict-free float2 LDS)
#define A_STAGE_FLOATS (128 * ROWF)    // 5120
#define STAGE_BYTES    (2u * 128u * ROWF * 4u)   // 40960
#define SMEM_BYTES     (STAGES * STAGE_BYTES)    // 163840

// ---------------- scratch (device globals; allocation is forbidden) ---------
__device__ __align__(256) float g_qlat   [(size_t)S_ * QL_];
__device__ __align__(256) float g_q      [(size_t)S_ * NH_ * QDIM_];
__device__ __align__(256) float g_latent [(size_t)S_ * DF_];
__device__ __align__(256) float g_kfull  [(size_t)S_ * DF_];
__device__ __align__(256) float g_qfull  [(size_t)NH_ * S_ * DF_];
__device__ __align__(256) float g_scores [(size_t)NH_ * S_ * S_];
__device__ __align__(256) float g_ctx    [(size_t)NH_ * S_ * KVL_];
__device__ __align__(256) float g_attnout[(size_t)S_ * NH_ * DV_];
// K-major (transposed) B operands
__device__ __align__(256) float g_wqaT [(size_t)QL_ * HID_];
__device__ __align__(256) float g_wqbT [(size_t)NH_ * QDIM_ * QL_];
__device__ __align__(256) float g_wkvaT[(size_t)DF_ * HID_];
__device__ __align__(256) float g_wkT  [(size_t)NH_ * KVL_ * DN_];
__device__ __align__(256) float g_wvT  [(size_t)NH_ * DV_ * KVL_];
__device__ __align__(256) float g_woT  [(size_t)HID_ * NH_ * DV_];
__device__ __align__(256) float g_ckvT [(size_t)KVL_ * S_];

// ---------------- helpers ----------------------------------------------------
__device__ __forceinline__ uint32_t smem_u32(const void* p) {
    uint32_t a;
    asm("{ .reg .u64 t; cvta.to.shared.u64 t, %1; cvt.u32.u64 %0, t; }" : "=r"(a) : "l"(p));
    return a;
}
#define CP_ASYNC16(dst, src, sz) \
    asm volatile("cp.async.cg.shared.global [%0], [%1], 16, %2;" :: "r"(dst), "l"(src), "r"(sz))
#define CP_COMMIT() asm volatile("cp.async.commit_group;" ::: "memory")
#define CP_WAIT(n)  asm volatile("cp.async.wait_group %0;" :: "n"(n) : "memory")

// split (x0, x1) into packed bf16x2 hi + bf16x2 lo (lo = residual)
__device__ __forceinline__ void split2(float x0, float x1, unsigned& hi, unsigned& lo) {
    unsigned h;
    asm("cvt.rn.bf16x2.f32 %0, %1, %2;" : "=r"(h) : "f"(x1), "f"(x0));
    float h0 = __uint_as_float(h << 16);
    float h1 = __uint_as_float(h & 0xffff0000u);
    unsigned l;
    asm("cvt.rn.bf16x2.f32 %0, %1, %2;" : "=r"(l) : "f"(x1 - h1), "f"(x0 - h0));
    hi = h; lo = l;
}
__device__ __forceinline__ void mma_bf16(float* d, const unsigned* a, const unsigned* b) {
    asm volatile(
        "mma.sync.aligned.m16n8k16.row.col.f32.bf16.bf16.f32 "
        "{%0,%1,%2,%3}, {%4,%5,%6,%7}, {%8,%9}, {%0,%1,%2,%3};"
        : "+f"(d[0]), "+f"(d[1]), "+f"(d[2]), "+f"(d[3])
        : "r"(a[0]), "r"(a[1]), "r"(a[2]), "r"(a[3]), "r"(b[0]), "r"(b[1]));
}

// flags: bit0 = causal tile skip, bit1 = K limited to row0+128
__global__ __launch_bounds__(256, 1) void mma_gemm(
    const float* __restrict__ A, const float* __restrict__ B, float* __restrict__ C,
    int M, int N, int K, int lda, int ldb, int ldc,
    long long sA, long long sB, long long sC, float alpha, int flags)
{
    const int row0 = blockIdx.y * TILE_M;
    const int col0 = blockIdx.x * TILE_N;
    if ((flags & 1) && col0 >= row0 + TILE_M) return;   // fully-masked causal tile

    A += (long long)blockIdx.z * sA;
    B += (long long)blockIdx.z * sB;
    C += (long long)blockIdx.z * sC;

    const int Keff = (flags & 2) ? min(K, row0 + TILE_M) : K;
    const int KT = Keff / KC;

    extern __shared__ float sm[];
    const uint32_t sbase = smem_u32(sm);
    const int tid  = threadIdx.x;
    const int wid  = tid >> 5;
    const int lane = tid & 31;
    const int g    = lane >> 2;          // 0..7
    const int c    = lane & 3;           // 0..3
    const int m0   = (wid & 1) * 64;     // warp M offset
    const int n0   = (wid >> 1) * 32;    // warp N offset

    const int lr = tid >> 3;             // loader base row (step 32)
    const int lc = (tid & 7) * 16;       // byte offset within 128B row chunk

    auto load_stage = [&](int kt) {
        const uint32_t base = sbase + (uint32_t)(kt % STAGES) * STAGE_BYTES;
        const uint32_t bBase = base + A_STAGE_FLOATS * 4u;
        const float* Ag = A + (long long)row0 * lda + (long long)kt * KC;
        const float* Bg = B + (long long)kt * KC;
#pragma unroll
        for (int j = 0; j < 4; j++) {
            int r = lr + j * 32;
            CP_ASYNC16(base + r * (ROWF * 4) + lc,
                       Ag + (long long)r * lda + (lc >> 2), 16);
        }
#pragma unroll
        for (int j = 0; j < 4; j++) {
            int r = lr + j * 32;
            int n = col0 + r;
            const float* src = Bg + (long long)(n < N ? n : 0) * ldb + (lc >> 2);
            CP_ASYNC16(bBase + r * (ROWF * 4) + lc, src, (n < N) ? 16 : 0);
        }
        CP_COMMIT();
    };

    float acc[4][4][4];
#pragma unroll
    for (int i = 0; i < 4; i++)
#pragma unroll
        for (int j = 0; j < 4; j++)
#pragma unroll
            for (int e = 0; e < 4; e++) acc[i][j][e] = 0.f;

    for (int kt = 0; kt < STAGES - 1; kt++) load_stage(kt);

    for (int kt = 0; kt < KT; kt++) {
        CP_WAIT(STAGES - 2);
        __syncthreads();
        const int pf = kt + STAGES - 1;
        if (pf < KT) load_stage(pf); else CP_COMMIT();

        const float* As = sm + (size_t)(kt % STAGES) * (2 * A_STAGE_FLOATS);
        const float* Bs = As + A_STAGE_FLOATS;
#pragma unroll
        for (int ks = 0; ks < 2; ks++) {
            const int kb = ks * 16;
            unsigned ah[4][4], al[4][4], bh[4][2], bl[4][2];
#pragma unroll
            for (int mi = 0; mi < 4; mi++) {
                const float* ap = As + (m0 + mi * 16 + g) * ROWF + kb + 2 * c;
                float2 v0 = *reinterpret_cast<const float2*>(ap);
                float2 v1 = *reinterpret_cast<const float2*>(ap + 8 * ROWF);
                float2 v2 = *reinterpret_cast<const float2*>(ap + 8);
                float2 v3 = *reinterpret_cast<const float2*>(ap + 8 * ROWF + 8);
                split2(v0.x, v0.y, ah[mi][0], al[mi][0]);
                split2(v1.x, v1.y, ah[mi][1], al[mi][1]);
                split2(v2.x, v2.y, ah[mi][2], al[mi][2]);
                split2(v3.x, v3.y, ah[mi][3], al[mi][3]);
            }
#pragma unroll
            for (int ni = 0; ni < 4; ni++) {
                const float* bp = Bs + (n0 + ni * 8 + g) * ROWF + kb + 2 * c;
                float2 w0 = *reinterpret_cast<const float2*>(bp);
                float2 w1 = *reinterpret_cast<const float2*>(bp + 8);
                split2(w0.x, w0.y, bh[ni][0], bl[ni][0]);
                split2(w1.x, w1.y, bh[ni][1], bl[ni][1]);
            }
#pragma unroll
            for (int mi = 0; mi < 4; mi++)
#pragma unroll
                for (int ni = 0; ni < 4; ni++) {
                    mma_bf16(acc[mi][ni], ah[mi], bh[ni]);
                    mma_bf16(acc[mi][ni], ah[mi], bl[ni]);
                    mma_bf16(acc[mi][ni], al[mi], bh[ni]);
                }
        }
    }
    CP_WAIT(0);

    // ---------------- epilogue: direct register -> GMEM ---------------------
#pragma unroll
    for (int mi = 0; mi < 4; mi++) {
#pragma unroll
        for (int ni = 0; ni < 4; ni++) {
            const int n = col0 + n0 + ni * 8 + 2 * c;
#pragma unroll
            for (int h = 0; h < 2; h++) {
                const int r = row0 + m0 + mi * 16 + g + h * 8;
                float v0 = alpha * acc[mi][ni][2 * h];
                float v1 = alpha * acc[mi][ni][2 * h + 1];
                if (n + 1 < N) {
                    *reinterpret_cast<float2*>(&C[(long long)r * ldc + n]) =
                        make_float2(v0, v1);
                } else if (n < N) {
                    C[(long long)r * ldc + n] = v0;
                }
            }
        }
    }
}

// ---------------- transpose: T[c][r] = X[r][c] -------------------------------
__global__ void transpose_k(const float* __restrict__ X, float* __restrict__ T,
                            int R, int C, int ldx, long long sX, long long sT)
{
    __shared__ float t[32][33];
    X += (long long)blockIdx.z * sX;
    T += (long long)blockIdx.z * sT;
    const int c0 = blockIdx.x * 32, r0 = blockIdx.y * 32;
    const int tx = threadIdx.x, ty = threadIdx.y;
#pragma unroll
    for (int i = 0; i < 32; i += 8) {
        int r = r0 + ty + i;
        if (r < R && c0 + tx < C) t[ty + i][tx] = X[(long long)r * ldx + c0 + tx];
    }
    __syncthreads();
#pragma unroll
    for (int i = 0; i < 32; i += 8) {
        int cc = c0 + ty + i;
        if (cc < C && r0 + tx < R)
            T[(long long)cc * R + r0 + tx] = t[tx][ty + i];
    }
}

// ---------------- RMSNorm over q_lat rows (in place) ------------------------
__global__ void rmsnorm_q(float* __restrict__ x, const float* __restrict__ w)
{
    const int s = blockIdx.x;
    float* row = x + (long long)s * QL_;
    const int tid = threadIdx.x;
    __shared__ float red[256];
    float ss = 0.f;
    for (int j = tid; j < QL_; j += 256) { float v = row[j]; ss += v * v; }
    red[tid] = ss; __syncthreads();
    for (int off = 128; off > 0; off >>= 1) {
        if (tid < off) red[tid] += red[tid + off];
        __syncthreads();
    }
    const float inv = rsqrtf(red[0] / QL_ + 1e-6f) * SCALE_Q_;
    for (int j = tid; j < QL_; j += 256) row[j] = w[j] * row[j] * inv;
}

// ---------------- kva RMSNorm + k_pe RoPE -> k_full --------------------------
__global__ void kva_norm_rope(const float* __restrict__ latent,
                              const float* __restrict__ w,
                              const float* __restrict__ cosb,
                              const float* __restrict__ sinb,
                              float* __restrict__ kfull)
{
    const int s = blockIdx.x;
    const int tid = threadIdx.x;           // 128 threads
    const float* row = latent + (long long)s * DF_;
    __shared__ float red[128];
    float ss = 0.f;
    for (int j = tid; j < KVL_; j += 128) { float v = row[j]; ss += v * v; }
    red[tid] = ss; __syncthreads();
    for (int off = 64; off > 0; off >>= 1) {
        if (tid < off) red[tid] += red[tid + off];
        __syncthreads();
    }
    const float inv = rsqrtf(red[0] / KVL_ + 1e-6f) * SCALE_KV_;
    float* out = kfull + (long long)s * DF_;
    for (int j = tid; j < KVL_; j += 128) out[j] = w[j] * row[j] * inv;
    if (tid < DR_) {
        const int r = tid;
        float x = row[KVL_ + r];
        float o = (r < 32) ? -row[KVL_ + r + 32] : row[KVL_ + r - 32];
        out[KVL_ + r] = x * cosb[s * DR_ + r] + o * sinb[s * DR_ + r];
    }
}

// ---------------- q_pe RoPE -> q_full[h][s][512+r] ---------------------------
__global__ void rope_q(const float* __restrict__ q,
                       const float* __restrict__ cosb,
                       const float* __restrict__ sinb,
                       float* __restrict__ qfull)
{
    long long idx = (long long)blockIdx.x * blockDim.x + threadIdx.x;
    if (idx >= (long long)S_ * NH_ * DR_) return;
    const int r = (int)(idx % DR_);
    const int h = (int)((idx / DR_) % NH_);
    const int s = (int)(idx / ((long long)DR_ * NH_));
    const float* qr = q + (long long)s * NH_ * QDIM_ + h * QDIM_ + DN_;
    float x = qr[r];
    float o = (r < 32) ? -qr[r + 32] : qr[r - 32];
    qfull[((long long)h * S_ + s) * DF_ + KVL_ + r] =
        x * cosb[s * DR_ + r] + o * sinb[s * DR_ + r];
}

// ------- causal softmax (in place; zero-fill only up to row-block end) ------
__global__ void softmax_causal(float* __restrict__ scores)
{
    const int s = blockIdx.x, h = blockIdx.y;
    float* row = scores + ((long long)h * S_ + s) * (long long)S_;
    const int tid = threadIdx.x;
    __shared__ float red[256];

    float m = -1e30f;
    for (int t = tid; t <= s; t += 256) m = fmaxf(m, row[t]);
    red[tid] = m; __syncthreads();
    for (int off = 128; off > 0; off >>= 1) {
        if (tid < off) red[tid] = fmaxf(red[tid], red[tid + off]);
        __syncthreads();
    }
    m = red[0]; __syncthreads();

    float sum = 0.f;
    for (int t = tid; t <= s; t += 256) {
        float e = __expf(row[t] - m);
        row[t] = e; sum += e;
    }
    red[tid] = sum; __syncthreads();
    for (int off = 128; off > 0; off >>= 1) {
        if (tid < off) red[tid] += red[tid + off];
        __syncthreads();
    }
    const float inv = 1.f / red[0];
    const int rowEnd = (s & ~(TILE_M - 1)) + TILE_M;   // ctx GEMM reads k < rowEnd
    for (int t = tid; t < rowEnd; t += 256)
        row[t] = (t <= s) ? row[t] * inv : 0.f;
}

// =============================================================================
extern "C" void kernel_launch(void* const* d_in, const int* in_sizes, int n_in,
                              void* d_out, int out_size)
{
    const float* hidden = (const float*)d_in[0];
    const float* cosb   = (const float*)d_in[1];
    const float* sinb   = (const float*)d_in[2];
    const float* w_qa   = (const float*)d_in[3];
    const float* qa_ln  = (const float*)d_in[4];
    const float* w_qb   = (const float*)d_in[5];
    const float* w_kva  = (const float*)d_in[6];
    const float* kva_ln = (const float*)d_in[7];
    const float* w_k    = (const float*)d_in[8];
    const float* w_v    = (const float*)d_in[9];
    const float* w_o    = (const float*)d_in[10];
    float* out = (float*)d_out;

    float *qlat, *q, *latent, *kfull, *qfull, *scores, *ctx, *attnout;
    float *wqaT, *wqbT, *wkvaT, *wkT, *wvT, *woT, *ckvT;
    cudaGetSymbolAddress((void**)&qlat,    g_qlat);
    cudaGetSymbolAddress((void**)&q,       g_q);
    cudaGetSymbolAddress((void**)&latent,  g_latent);
    cudaGetSymbolAddress((void**)&kfull,   g_kfull);
    cudaGetSymbolAddress((void**)&qfull,   g_qfull);
    cudaGetSymbolAddress((void**)&scores,  g_scores);
    cudaGetSymbolAddress((void**)&ctx,     g_ctx);
    cudaGetSymbolAddress((void**)&attnout, g_attnout);
    cudaGetSymbolAddress((void**)&wqaT,    g_wqaT);
    cudaGetSymbolAddress((void**)&wqbT,    g_wqbT);
    cudaGetSymbolAddress((void**)&wkvaT,   g_wkvaT);
    cudaGetSymbolAddress((void**)&wkT,     g_wkT);
    cudaGetSymbolAddress((void**)&wvT,     g_wvT);
    cudaGetSymbolAddress((void**)&woT,     g_woT);
    cudaGetSymbolAddress((void**)&ckvT,    g_ckvT);

    cudaFuncSetAttribute(mma_gemm, cudaFuncAttributeMaxDynamicSharedMemorySize, SMEM_BYTES);

    const dim3 tb(32, 8);

    // ---- weight transposes to K-major ----
    transpose_k<<<dim3(QL_ / 32, HID_ / 32, 1), tb>>>(w_qa, wqaT, HID_, QL_, QL_, 0, 0);
    transpose_k<<<dim3(NH_ * QDIM_ / 32, QL_ / 32, 1), tb>>>(w_qb, wqbT, QL_, NH_ * QDIM_, NH_ * QDIM_, 0, 0);
    transpose_k<<<dim3(DF_ / 32, HID_ / 32, 1), tb>>>(w_kva, wkvaT, HID_, DF_, DF_, 0, 0);
    transpose_k<<<dim3(KVL_ / 32, DN_ / 32, NH_), tb>>>(w_k, wkT, DN_, KVL_, KVL_,
        (long long)DN_ * KVL_, (long long)KVL_ * DN_);
    transpose_k<<<dim3(DV_ / 32, KVL_ / 32, NH_), tb>>>(w_v, wvT, KVL_, DV_, DV_,
        (long long)KVL_ * DV_, (long long)DV_ * KVL_);
    transpose_k<<<dim3(HID_ / 32, (NH_ * DV_) / 32, 1), tb>>>(w_o, woT, NH_ * DV_, HID_, HID_, 0, 0);

    // 1) q_lat = hidden @ w_qa
    mma_gemm<<<dim3(QL_ / TILE_N, S_ / TILE_M, 1), 256, SMEM_BYTES>>>(
        hidden, wqaT, qlat, S_, QL_, HID_, HID_, HID_, QL_, 0, 0, 0, 1.f, 0);
    // 2) RMSNorm(q_lat) * SCALE_Q
    rmsnorm_q<<<S_, 256>>>(qlat, qa_ln);
    // 3) q = q_lat @ w_qb
    mma_gemm<<<dim3(NH_ * QDIM_ / TILE_N, S_ / TILE_M, 1), 256, SMEM_BYTES>>>(
        qlat, wqbT, q, S_, NH_ * QDIM_, QL_, QL_, QL_, NH_ * QDIM_, 0, 0, 0, 1.f, 0);
    // 4) latent = hidden @ w_kva   (N=576, last tile partial)
    mma_gemm<<<dim3((DF_ + TILE_N - 1) / TILE_N, S_ / TILE_M, 1), 256, SMEM_BYTES>>>(
        hidden, wkvaT, latent, S_, DF_, HID_, HID_, HID_, DF_, 0, 0, 0, 1.f, 0);
    // 5) k_full = [rmsnorm(c_kv)*SCALE_KV | rope(k_pe)]
    kva_norm_rope<<<S_, 128>>>(latent, kva_ln, cosb, sinb, kfull);
    // 5b) ckvT = c_kv^T (B of ctx GEMM)
    transpose_k<<<dim3(KVL_ / 32, S_ / 32, 1), tb>>>(kfull, ckvT, S_, KVL_, DF_, 0, 0);
    // 6) q_full[.., 512:576] = rope(q_pe)
    {
        long long tot = (long long)S_ * NH_ * DR_;
        rope_q<<<(unsigned)((tot + 255) / 256), 256>>>(q, cosb, sinb, qfull);
    }
    // 7) q_full[h][:, :512] = q_nope[h] @ w_k[h]   batched x64
    mma_gemm<<<dim3(KVL_ / TILE_N, S_ / TILE_M, NH_), 256, SMEM_BYTES>>>(
        q, wkT, qfull, S_, KVL_, DN_, NH_ * QDIM_, DN_, DF_,
        (long long)QDIM_, (long long)KVL_ * DN_, (long long)S_ * DF_, 1.f, 0);
    // 8) scores[h] = SM_SCALE * q_full[h] @ k_full^T  (causal tile skip)
    mma_gemm<<<dim3(S_ / TILE_N, S_ / TILE_M, NH_), 256, SMEM_BYTES>>>(
        qfull, kfull, scores, S_, S_, DF_, DF_, DF_, S_,
        (long long)S_ * DF_, 0LL, (long long)S_ * S_, SM_SCALE_, 1);
    // 9) causal softmax
    softmax_causal<<<dim3(S_, NH_), 256>>>(scores);
    // 10) ctx[h] = attn[h] @ c_kv   (K limited to row0+128)
    mma_gemm<<<dim3(KVL_ / TILE_N, S_ / TILE_M, NH_), 256, SMEM_BYTES>>>(
        scores, ckvT, ctx, S_, KVL_, S_, S_, S_, KVL_,
        (long long)S_ * S_, 0LL, (long long)S_ * KVL_, 1.f, 2);
    // 11) attn_out[:, h*128:+128] = ctx[h] @ w_v[h]   batched x64
    mma_gemm<<<dim3(1, S_ / TILE_M, NH_), 256, SMEM_BYTES>>>(
        ctx, wvT, attnout, S_, DV_, KVL_, KVL_, KVL_, NH_ * DV_,
        (long long)S_ * KVL_, (long long)DV_ * KVL_, (long long)DV_, 1.f, 0);
    // 12) out = attn_out @ w_o
    mma_gemm<<<dim3(HID_ / TILE_N, S_ / TILE_M, 1), 256, SMEM_BYTES>>>(
        attnout, woT, out, S_, HID_, NH_ * DV_, NH_ * DV_, NH_ * DV_, HID_,
        0, 0, 0, 1.f, 0);
}

// round 5
// speedup vs baseline: 3.4030x; 1.0765x over previous
#include <cuda_runtime.h>
#include <cuda_bf16.h>
#include <cstdint>
#include <math.h>

#define S_    1536
#define HID_  6144
#define NH_   64
#define DN_   128
#define DR_   64
#define DV_   128
#define QL_   1536
#define KVL_  512
#define DF_   576        // KVL + DR
#define QDIM_ 192        // DN + DR

#define SM_SCALE_  0.07216878364870322f
#define SCALE_Q_   2.0f
#define SCALE_KV_  3.4641016151377544f

#define TILE_M 128
#define TILE_N 128
#define KC     32
#define STAGES 4
#define BUF_BYTES   8192u            // 128 rows x 32 bf16 (swizzled 128B lines)
#define STAGE_BYTES 32768u           // Ahi, Alo, Bhi, Blo
#define SMEM_BYTES  (STAGES * STAGE_BYTES)   // 131072

typedef __nv_bfloat16 bf16;

// ---------------- scratch: all activations/weights as (hi, lo) bf16 pairs ---
#define N_HID  ((size_t)S_ * HID_)
#define N_QLAT ((size_t)S_ * QL_)
#define N_Q    ((size_t)S_ * NH_ * QDIM_)
#define N_LAT  ((size_t)S_ * DF_)
#define N_KF   ((size_t)S_ * DF_)
#define N_QF   ((size_t)NH_ * S_ * DF_)
#define N_SC   ((size_t)NH_ * S_ * S_)
#define N_CTX  ((size_t)NH_ * S_ * KVL_)
#define N_AO   ((size_t)S_ * NH_ * DV_)
#define N_WQA  ((size_t)QL_ * HID_)
#define N_WQB  ((size_t)NH_ * QDIM_ * QL_)
#define N_WKVA ((size_t)DF_ * HID_)
#define N_WK   ((size_t)NH_ * KVL_ * DN_)
#define N_WV   ((size_t)NH_ * DV_ * KVL_)
#define N_WO   ((size_t)HID_ * NH_ * DV_)
#define N_CKVT ((size_t)KVL_ * S_)

__device__ __align__(256) unsigned short g_hid2 [2 * N_HID];
__device__ __align__(256) unsigned short g_qlat2[2 * N_QLAT];
__device__ __align__(256) unsigned short g_q2   [2 * N_Q];
__device__ __align__(256) unsigned short g_lat2 [2 * N_LAT];
__device__ __align__(256) unsigned short g_kf2  [2 * N_KF];
__device__ __align__(256) unsigned short g_qf2  [2 * N_QF];
__device__ __align__(256) unsigned short g_sc2  [2 * N_SC];
__device__ __align__(256) unsigned short g_ctx2 [2 * N_CTX];
__device__ __align__(256) unsigned short g_ao2  [2 * N_AO];
__device__ __align__(256) unsigned short g_wqa2 [2 * N_WQA];
__device__ __align__(256) unsigned short g_wqb2 [2 * N_WQB];
__device__ __align__(256) unsigned short g_wkva2[2 * N_WKVA];
__device__ __align__(256) unsigned short g_wk2  [2 * N_WK];
__device__ __align__(256) unsigned short g_wv2  [2 * N_WV];
__device__ __align__(256) unsigned short g_wo2  [2 * N_WO];
__device__ __align__(256) unsigned short g_ckvt2[2 * N_CKVT];

// ---------------- helpers ----------------------------------------------------
__device__ __forceinline__ uint32_t smem_u32(const void* p) {
    uint32_t a;
    asm("{ .reg .u64 t; cvta.to.shared.u64 t, %1; cvt.u32.u64 %0, t; }" : "=r"(a) : "l"(p));
    return a;
}
#define CP_ASYNC16(dst, src, sz) \
    asm volatile("cp.async.cg.shared.global [%0], [%1], 16, %2;" :: "r"(dst), "l"(src), "r"(sz))
#define CP_COMMIT() asm volatile("cp.async.commit_group;" ::: "memory")
#define CP_WAIT(n)  asm volatile("cp.async.wait_group %0;" :: "n"(n) : "memory")

#define LDSM4(r0, r1, r2, r3, a) \
    asm volatile("ldmatrix.sync.aligned.m8n8.x4.shared.b16 {%0,%1,%2,%3}, [%4];" \
                 : "=r"(r0), "=r"(r1), "=r"(r2), "=r"(r3) : "r"(a))

__device__ __forceinline__ void mma_bf16(float* d, const unsigned* a, const unsigned* b) {
    asm volatile(
        "mma.sync.aligned.m16n8k16.row.col.f32.bf16.bf16.f32 "
        "{%0,%1,%2,%3}, {%4,%5,%6,%7}, {%8,%9}, {%0,%1,%2,%3};"
        : "+f"(d[0]), "+f"(d[1]), "+f"(d[2]), "+f"(d[3])
        : "r"(a[0]), "r"(a[1]), "r"(a[2]), "r"(a[3]), "r"(b[0]), "r"(b[1]));
}

// swizzled byte offset of 16B chunk (row, kc) in an 8KB tile buffer
// rows paired into 128B lines; chunk XOR line index -> ldmatrix conflict-free
__device__ __forceinline__ uint32_t off_swz(int row, int kc) {
    return (uint32_t)(row >> 1) * 128u +
           (uint32_t)(((((row & 1) << 2) + kc) ^ ((row >> 1) & 7)) * 16);
}

__device__ __forceinline__ float pget(const bf16* h, const bf16* l, long long i) {
    return __bfloat162float(h[i]) + __bfloat162float(l[i]);
}
__device__ __forceinline__ void pset(bf16* h, bf16* l, long long i, float v) {
    bf16 a = __float2bfloat16(v);
    h[i] = a;
    l[i] = __float2bfloat16(v - __bfloat162float(a));
}

// flags: bit0 = causal tile skip, bit1 = K limited to row0+128, bit2 = fp32 C
__global__ __launch_bounds__(256, 1) void mma_gemm(
    const bf16* __restrict__ Ahi, const bf16* __restrict__ Alo,
    const bf16* __restrict__ Bhi, const bf16* __restrict__ Blo,
    bf16* __restrict__ Chi, bf16* __restrict__ Clo, float* __restrict__ Cf,
    int M, int N, int K, int lda, int ldb, int ldc,
    long long sA, long long sB, long long sC, float alpha, int flags)
{
    const int row0 = blockIdx.y * TILE_M;
    const int col0 = blockIdx.x * TILE_N;
    if ((flags & 1) && col0 >= row0 + TILE_M) return;

    const long long bz = blockIdx.z;
    Ahi += bz * sA;  Alo += bz * sA;
    Bhi += bz * sB;  Blo += bz * sB;
    if (flags & 4) Cf += bz * sC; else { Chi += bz * sC; Clo += bz * sC; }

    const int Keff = (flags & 2) ? min(K, row0 + TILE_M) : K;
    const int KT = Keff / KC;

    extern __shared__ char smraw[];
    const uint32_t sbase = smem_u32(smraw);
    const int tid  = threadIdx.x;
    const int wid  = tid >> 5;
    const int lane = tid & 31;
    const int g    = lane >> 2;
    const int c    = lane & 3;
    const int m0   = (wid & 1) * 64;
    const int n0   = (wid >> 1) * 32;

    // ldmatrix lane roles
    const int am_l = (lane & 7) + ((lane >> 3) & 1) * 8;  // A row within 16
    const int ak_l = lane >> 4;                           // A k-chunk add
    const int bn_l = (lane & 7) + ((lane >> 4) & 1) * 8;  // B row within 16
    const int bk_l = (lane >> 3) & 1;                     // B k-chunk add

    auto load_stage = [&](int kt) {
        const uint32_t base = sbase + (uint32_t)(kt % STAGES) * STAGE_BYTES;
        const bf16* AgH = Ahi + (long long)row0 * lda + (long long)kt * KC;
        const bf16* AgL = Alo + (long long)row0 * lda + (long long)kt * KC;
        const bf16* BgH = Bhi + (long long)kt * KC;
        const bf16* BgL = Blo + (long long)kt * KC;
#pragma unroll
        for (int j = 0; j < 2; j++) {
            const int i  = tid + j * 256;
            const int m  = i >> 2;
            const int kc = i & 3;
            const uint32_t so = off_swz(m, kc);
            CP_ASYNC16(base + so,                 AgH + (long long)m * lda + kc * 8, 16);
            CP_ASYNC16(base + BUF_BYTES + so,     AgL + (long long)m * lda + kc * 8, 16);
            const int n = col0 + m;
            const long long bo = (long long)(n < N ? n : 0) * ldb + kc * 8;
            const int sz = (n < N) ? 16 : 0;
            CP_ASYNC16(base + 2 * BUF_BYTES + so, BgH + bo, sz);
            CP_ASYNC16(base + 3 * BUF_BYTES + so, BgL + bo, sz);
        }
        CP_COMMIT();
    };

    float acc[4][4][4];
#pragma unroll
    for (int i = 0; i < 4; i++)
#pragma unroll
        for (int j = 0; j < 4; j++)
#pragma unroll
            for (int e = 0; e < 4; e++) acc[i][j][e] = 0.f;

    const int PRE = (KT < STAGES - 1) ? KT : (STAGES - 1);
    for (int kt = 0; kt < PRE; kt++) load_stage(kt);

    for (int kt = 0; kt < KT; kt++) {
        CP_WAIT(STAGES - 2);
        __syncthreads();
        const int pf = kt + STAGES - 1;
        if (pf < KT) load_stage(pf); else CP_COMMIT();

        const uint32_t sb   = sbase + (uint32_t)(kt % STAGES) * STAGE_BYTES;
        const uint32_t aHiB = sb;
        const uint32_t aLoB = sb + BUF_BYTES;
        const uint32_t bHiB = sb + 2 * BUF_BYTES;
        const uint32_t bLoB = sb + 3 * BUF_BYTES;

#pragma unroll
        for (int ks = 0; ks < 2; ks++) {
            const int kcb = ks * 2;
            unsigned ah[4][4], al[4][4], bh[4][2], bl[4][2];
#pragma unroll
            for (int mi = 0; mi < 4; mi++) {
                const uint32_t so = off_swz(m0 + mi * 16 + am_l, kcb + ak_l);
                LDSM4(ah[mi][0], ah[mi][1], ah[mi][2], ah[mi][3], aHiB + so);
                LDSM4(al[mi][0], al[mi][1], al[mi][2], al[mi][3], aLoB + so);
            }
#pragma unroll
            for (int hB = 0; hB < 2; hB++) {
                const uint32_t so = off_swz(n0 + hB * 16 + bn_l, kcb + bk_l);
                LDSM4(bh[2*hB][0], bh[2*hB][1], bh[2*hB+1][0], bh[2*hB+1][1], bHiB + so);
                LDSM4(bl[2*hB][0], bl[2*hB][1], bl[2*hB+1][0], bl[2*hB+1][1], bLoB + so);
            }
#pragma unroll
            for (int mi = 0; mi < 4; mi++)
#pragma unroll
                for (int ni = 0; ni < 4; ni++) {
                    mma_bf16(acc[mi][ni], ah[mi], bh[ni]);
                    mma_bf16(acc[mi][ni], ah[mi], bl[ni]);
                    mma_bf16(acc[mi][ni], al[mi], bh[ni]);
                }
        }
    }
    CP_WAIT(0);

    // ---------------- epilogue -----------------------------------------------
#pragma unroll
    for (int mi = 0; mi < 4; mi++) {
#pragma unroll
        for (int ni = 0; ni < 4; ni++) {
            const int n = col0 + n0 + ni * 8 + 2 * c;
#pragma unroll
            for (int h = 0; h < 2; h++) {
                const int r = row0 + m0 + mi * 16 + g + h * 8;
                float v0 = alpha * acc[mi][ni][2 * h];
                float v1 = alpha * acc[mi][ni][2 * h + 1];
                if (flags & 4) {
                    if (n + 1 < N)
                        *reinterpret_cast<float2*>(&Cf[(long long)r * ldc + n]) =
                            make_float2(v0, v1);
                    else if (n < N) Cf[(long long)r * ldc + n] = v0;
                } else {
                    bf16 h0 = __float2bfloat16(v0), h1 = __float2bfloat16(v1);
                    bf16 l0 = __float2bfloat16(v0 - __bfloat162float(h0));
                    bf16 l1 = __float2bfloat16(v1 - __bfloat162float(h1));
                    const long long o = (long long)r * ldc + n;
                    if (n + 1 < N) {
                        __nv_bfloat162 hh; hh.x = h0; hh.y = h1;
                        __nv_bfloat162 ll; ll.x = l0; ll.y = l1;
                        *reinterpret_cast<__nv_bfloat162*>(&Chi[o]) = hh;
                        *reinterpret_cast<__nv_bfloat162*>(&Clo[o]) = ll;
                    } else if (n < N) { Chi[o] = h0; Clo[o] = l0; }
                }
            }
        }
    }
}

// ---------------- fp32 -> (hi, lo) split -------------------------------------
__global__ void split_f32(const float* __restrict__ x, bf16* __restrict__ hi,
                          bf16* __restrict__ lo, long long n)
{
    long long i = (long long)blockIdx.x * blockDim.x + threadIdx.x;
    if (i >= n) return;
    float v = x[i];
    bf16 h = __float2bfloat16(v);
    hi[i] = h;
    lo[i] = __float2bfloat16(v - __bfloat162float(h));
}

// ---------------- fp32 transpose -> K-major (hi, lo) -------------------------
__global__ void transpose_split(const float* __restrict__ X, bf16* __restrict__ Thi,
                                bf16* __restrict__ Tlo, int R, int C, int ldx,
                                long long sX, long long sT)
{
    __shared__ float t[32][33];
    X   += (long long)blockIdx.z * sX;
    Thi += (long long)blockIdx.z * sT;
    Tlo += (long long)blockIdx.z * sT;
    const int c0 = blockIdx.x * 32, r0 = blockIdx.y * 32;
    const int tx = threadIdx.x, ty = threadIdx.y;
#pragma unroll
    for (int i = 0; i < 32; i += 8) {
        int r = r0 + ty + i;
        if (r < R && c0 + tx < C) t[ty + i][tx] = X[(long long)r * ldx + c0 + tx];
    }
    __syncthreads();
#pragma unroll
    for (int i = 0; i < 32; i += 8) {
        int cc = c0 + ty + i;
        if (cc < C && r0 + tx < R) {
            float v = t[tx][ty + i];
            long long o = (long long)cc * R + r0 + tx;
            bf16 h = __float2bfloat16(v);
            Thi[o] = h;
            Tlo[o] = __float2bfloat16(v - __bfloat162float(h));
        }
    }
}

// ---------------- bf16 transpose (applied to hi and lo independently) -------
__global__ void transpose_bf16(const bf16* __restrict__ X, bf16* __restrict__ T,
                               int R, int C, int ldx)
{
    __shared__ bf16 t[32][33];
    const int c0 = blockIdx.x * 32, r0 = blockIdx.y * 32;
    const int tx = threadIdx.x, ty = threadIdx.y;
#pragma unroll
    for (int i = 0; i < 32; i += 8) {
        int r = r0 + ty + i;
        if (r < R && c0 + tx < C) t[ty + i][tx] = X[(long long)r * ldx + c0 + tx];
    }
    __syncthreads();
#pragma unroll
    for (int i = 0; i < 32; i += 8) {
        int cc = c0 + ty + i;
        if (cc < C && r0 + tx < R) T[(long long)cc * R + r0 + tx] = t[tx][ty + i];
    }
}

// ---------------- RMSNorm (pair in place) ------------------------------------
__global__ void rmsnorm_q(bf16* __restrict__ xh, bf16* __restrict__ xl,
                          const float* __restrict__ w)
{
    const int s = blockIdx.x;
    const long long base = (long long)s * QL_;
    const int tid = threadIdx.x;
    __shared__ float red[256];
    float ss = 0.f;
    for (int j = tid; j < QL_; j += 256) { float v = pget(xh, xl, base + j); ss += v * v; }
    red[tid] = ss; __syncthreads();
    for (int off = 128; off > 0; off >>= 1) {
        if (tid < off) red[tid] += red[tid + off];
        __syncthreads();
    }
    const float inv = rsqrtf(red[0] / QL_ + 1e-6f) * SCALE_Q_;
    for (int j = tid; j < QL_; j += 256)
        pset(xh, xl, base + j, w[j] * pget(xh, xl, base + j) * inv);
}

// ---------------- kva RMSNorm + k_pe RoPE -> k_full (pairs) ------------------
__global__ void kva_norm_rope(const bf16* __restrict__ lh, const bf16* __restrict__ ll,
                              const float* __restrict__ w,
                              const float* __restrict__ cosb, const float* __restrict__ sinb,
                              bf16* __restrict__ kh, bf16* __restrict__ kl)
{
    const int s = blockIdx.x;
    const int tid = threadIdx.x;           // 128 threads
    const long long base = (long long)s * DF_;
    __shared__ float red[128];
    float ss = 0.f;
    for (int j = tid; j < KVL_; j += 128) { float v = pget(lh, ll, base + j); ss += v * v; }
    red[tid] = ss; __syncthreads();
    for (int off = 64; off > 0; off >>= 1) {
        if (tid < off) red[tid] += red[tid + off];
        __syncthreads();
    }
    const float inv = rsqrtf(red[0] / KVL_ + 1e-6f) * SCALE_KV_;
    for (int j = tid; j < KVL_; j += 128)
        pset(kh, kl, base + j, w[j] * pget(lh, ll, base + j) * inv);
    if (tid < DR_) {
        const int r = tid;
        float x = pget(lh, ll, base + KVL_ + r);
        float o = (r < 32) ? -pget(lh, ll, base + KVL_ + r + 32)
                           :  pget(lh, ll, base + KVL_ + r - 32);
        pset(kh, kl, base + KVL_ + r, x * cosb[s * DR_ + r] + o * sinb[s * DR_ + r]);
    }
}

// ---------------- q_pe RoPE -> q_full[h][s][512+r] (pairs) -------------------
__global__ void rope_q(const bf16* __restrict__ qh, const bf16* __restrict__ ql,
                       const float* __restrict__ cosb, const float* __restrict__ sinb,
                       bf16* __restrict__ fh, bf16* __restrict__ fl)
{
    long long idx = (long long)blockIdx.x * blockDim.x + threadIdx.x;
    if (idx >= (long long)S_ * NH_ * DR_) return;
    const int r = (int)(idx % DR_);
    const int h = (int)((idx / DR_) % NH_);
    const int s = (int)(idx / ((long long)DR_ * NH_));
    const long long qb = (long long)s * NH_ * QDIM_ + h * QDIM_ + DN_;
    float x = pget(qh, ql, qb + r);
    float o = (r < 32) ? -pget(qh, ql, qb + r + 32) : pget(qh, ql, qb + r - 32);
    pset(fh, fl, ((long long)h * S_ + s) * DF_ + KVL_ + r,
         x * cosb[s * DR_ + r] + o * sinb[s * DR_ + r]);
}

// ------- causal softmax on pairs (zero-fill up to row-block end) -------------
__global__ void softmax_causal(bf16* __restrict__ sh, bf16* __restrict__ sl)
{
    const int s = blockIdx.x, h = blockIdx.y;
    const long long base = ((long long)h * S_ + s) * (long long)S_;
    const int tid = threadIdx.x;
    __shared__ float red[256];

    float m = -1e30f;
    for (int t = tid; t <= s; t += 256) m = fmaxf(m, pget(sh, sl, base + t));
    red[tid] = m; __syncthreads();
    for (int off = 128; off > 0; off >>= 1) {
        if (tid < off) red[tid] = fmaxf(red[tid], red[tid + off]);
        __syncthreads();
    }
    m = red[0]; __syncthreads();

    float sum = 0.f;
    for (int t = tid; t <= s; t += 256) {
        float e = __expf(pget(sh, sl, base + t) - m);
        pset(sh, sl, base + t, e);
        sum += e;
    }
    red[tid] = sum; __syncthreads();
    for (int off = 128; off > 0; off >>= 1) {
        if (tid < off) red[tid] += red[tid + off];
        __syncthreads();
    }
    const float inv = 1.f / red[0];
    const int rowEnd = (s & ~(TILE_M - 1)) + TILE_M;
    for (int t = tid; t < rowEnd; t += 256) {
        float v = (t <= s) ? pget(sh, sl, base + t) * inv : 0.f;
        pset(sh, sl, base + t, v);
    }
}

// =============================================================================
extern "C" void kernel_launch(void* const* d_in, const int* in_sizes, int n_in,
                              void* d_out, int out_size)
{
    const float* hidden = (const float*)d_in[0];
    const float* cosb   = (const float*)d_in[1];
    const float* sinb   = (const float*)d_in[2];
    const float* w_qa   = (const float*)d_in[3];
    const float* qa_ln  = (const float*)d_in[4];
    const float* w_qb   = (const float*)d_in[5];
    const float* w_kva  = (const float*)d_in[6];
    const float* kva_ln = (const float*)d_in[7];
    const float* w_k    = (const float*)d_in[8];
    const float* w_v    = (const float*)d_in[9];
    const float* w_o    = (const float*)d_in[10];
    float* out = (float*)d_out;

    bf16 *hid, *qlat, *q, *lat, *kf, *qf, *sc, *ctx, *ao;
    bf16 *wqa, *wqb, *wkva, *wk, *wv, *wo, *ckvt;
    cudaGetSymbolAddress((void**)&hid,  g_hid2);
    cudaGetSymbolAddress((void**)&qlat, g_qlat2);
    cudaGetSymbolAddress((void**)&q,    g_q2);
    cudaGetSymbolAddress((void**)&lat,  g_lat2);
    cudaGetSymbolAddress((void**)&kf,   g_kf2);
    cudaGetSymbolAddress((void**)&qf,   g_qf2);
    cudaGetSymbolAddress((void**)&sc,   g_sc2);
    cudaGetSymbolAddress((void**)&ctx,  g_ctx2);
    cudaGetSymbolAddress((void**)&ao,   g_ao2);
    cudaGetSymbolAddress((void**)&wqa,  g_wqa2);
    cudaGetSymbolAddress((void**)&wqb,  g_wqb2);
    cudaGetSymbolAddress((void**)&wkva, g_wkva2);
    cudaGetSymbolAddress((void**)&wk,   g_wk2);
    cudaGetSymbolAddress((void**)&wv,   g_wv2);
    cudaGetSymbolAddress((void**)&wo,   g_wo2);
    cudaGetSymbolAddress((void**)&ckvt, g_ckvt2);

    // pair halves
    bf16 *hidL = hid + N_HID,  *qlatL = qlat + N_QLAT, *qL = q + N_Q;
    bf16 *latL = lat + N_LAT,  *kfL = kf + N_KF,       *qfL = qf + N_QF;
    bf16 *scL  = sc + N_SC,    *ctxL = ctx + N_CTX,    *aoL = ao + N_AO;
    bf16 *wqaL = wqa + N_WQA,  *wqbL = wqb + N_WQB,    *wkvaL = wkva + N_WKVA;
    bf16 *wkL  = wk + N_WK,    *wvL = wv + N_WV,       *woL = wo + N_WO;
    bf16 *ckvtL = ckvt + N_CKVT;

    cudaFuncSetAttribute(mma_gemm, cudaFuncAttributeMaxDynamicSharedMemorySize, SMEM_BYTES);

    const dim3 tb(32, 8);

    // ---- split hidden; transpose+split weights to K-major ----
    {
        long long n = (long long)N_HID;
        split_f32<<<(unsigned)((n + 255) / 256), 256>>>(hidden, hid, hidL, n);
    }
    transpose_split<<<dim3(QL_ / 32, HID_ / 32, 1), tb>>>(w_qa, wqa, wqaL, HID_, QL_, QL_, 0, 0);
    transpose_split<<<dim3(NH_ * QDIM_ / 32, QL_ / 32, 1), tb>>>(w_qb, wqb, wqbL, QL_, NH_ * QDIM_, NH_ * QDIM_, 0, 0);
    transpose_split<<<dim3(DF_ / 32, HID_ / 32, 1), tb>>>(w_kva, wkva, wkvaL, HID_, DF_, DF_, 0, 0);
    transpose_split<<<dim3(KVL_ / 32, DN_ / 32, NH_), tb>>>(w_k, wk, wkL, DN_, KVL_, KVL_,
        (long long)DN_ * KVL_, (long long)KVL_ * DN_);
    transpose_split<<<dim3(DV_ / 32, KVL_ / 32, NH_), tb>>>(w_v, wv, wvL, KVL_, DV_, DV_,
        (long long)KVL_ * DV_, (long long)DV_ * KVL_);
    transpose_split<<<dim3(HID_ / 32, (NH_ * DV_) / 32, 1), tb>>>(w_o, wo, woL, NH_ * DV_, HID_, HID_, 0, 0);

    // 1) q_lat = hidden @ w_qa
    mma_gemm<<<dim3(QL_ / TILE_N, S_ / TILE_M, 1), 256, SMEM_BYTES>>>(
        hid, hidL, wqa, wqaL, qlat, qlatL, nullptr,
        S_, QL_, HID_, HID_, HID_, QL_, 0, 0, 0, 1.f, 0);
    // 2) RMSNorm(q_lat) * SCALE_Q
    rmsnorm_q<<<S_, 256>>>(qlat, qlatL, qa_ln);
    // 3) q = q_lat @ w_qb
    mma_gemm<<<dim3(NH_ * QDIM_ / TILE_N, S_ / TILE_M, 1), 256, SMEM_BYTES>>>(
        qlat, qlatL, wqb, wqbL, q, qL, nullptr,
        S_, NH_ * QDIM_, QL_, QL_, QL_, NH_ * QDIM_, 0, 0, 0, 1.f, 0);
    // 4) latent = hidden @ w_kva   (N=576)
    mma_gemm<<<dim3((DF_ + TILE_N - 1) / TILE_N, S_ / TILE_M, 1), 256, SMEM_BYTES>>>(
        hid, hidL, wkva, wkvaL, lat, latL, nullptr,
        S_, DF_, HID_, HID_, HID_, DF_, 0, 0, 0, 1.f, 0);
    // 5) k_full = [rmsnorm(c_kv)*SCALE_KV | rope(k_pe)]
    kva_norm_rope<<<S_, 128>>>(lat, latL, kva_ln, cosb, sinb, kf, kfL);
    // 5b) ckvT = c_kv^T  (hi and lo transposed independently — exact)
    transpose_bf16<<<dim3(KVL_ / 32, S_ / 32), tb>>>(kf,  ckvt,  S_, KVL_, DF_);
    transpose_bf16<<<dim3(KVL_ / 32, S_ / 32), tb>>>(kfL, ckvtL, S_, KVL_, DF_);
    // 6) q_full[.., 512:576] = rope(q_pe)
    {
        long long tot = (long long)S_ * NH_ * DR_;
        rope_q<<<(unsigned)((tot + 255) / 256), 256>>>(q, qL, cosb, sinb, qf, qfL);
    }
    // 7) q_full[h][:, :512] = q_nope[h] @ w_k[h]
    mma_gemm<<<dim3(KVL_ / TILE_N, S_ / TILE_M, NH_), 256, SMEM_BYTES>>>(
        q, qL, wk, wkL, qf, qfL, nullptr,
        S_, KVL_, DN_, NH_ * QDIM_, DN_, DF_,
        (long long)QDIM_, (long long)KVL_ * DN_, (long long)S_ * DF_, 1.f, 0);
    // 8) scores[h] = SM_SCALE * q_full[h] @ k_full^T  (causal tile skip)
    mma_gemm<<<dim3(S_ / TILE_N, S_ / TILE_M, NH_), 256, SMEM_BYTES>>>(
        qf, qfL, kf, kfL, sc, scL, nullptr,
        S_, S_, DF_, DF_, DF_, S_,
        (long long)S_ * DF_, 0LL, (long long)S_ * S_, SM_SCALE_, 1);
    // 9) causal softmax
    softmax_causal<<<dim3(S_, NH_), 256>>>(sc, scL);
    // 10) ctx[h] = attn[h] @ c_kv   (K limited)
    mma_gemm<<<dim3(KVL_ / TILE_N, S_ / TILE_M, NH_), 256, SMEM_BYTES>>>(
        sc, scL, ckvt, ckvtL, ctx, ctxL, nullptr,
        S_, KVL_, S_, S_, S_, KVL_,
        (long long)S_ * S_, 0LL, (long long)S_ * KVL_, 1.f, 2);
    // 11) attn_out[:, h*128:+128] = ctx[h] @ w_v[h]
    mma_gemm<<<dim3(1, S_ / TILE_M, NH_), 256, SMEM_BYTES>>>(
        ctx, ctxL, wv, wvL, ao, aoL, nullptr,
        S_, DV_, KVL_, KVL_, KVL_, NH_ * DV_,
        (long long)S_ * KVL_, (long long)DV_ * KVL_, (long long)DV_, 1.f, 0);
    // 12) out = attn_out @ w_o   (fp32 output)
    mma_gemm<<<dim3(HID_ / TILE_N, S_ / TILE_M, 1), 256, SMEM_BYTES>>>(
        ao, aoL, wo, woL, nullptr, nullptr, out,
        S_, HID_, NH_ * DV_, NH_ * DV_, NH_ * DV_, HID_, 0, 0, 0, 1.f, 4);
}

// round 6
// speedup vs baseline: 3.5351x; 1.0388x over previous
#include <cuda_runtime.h>
#include <cuda_bf16.h>
#include <cstdint>
#include <math.h>

#define S_    1536
#define HID_  6144
#define NH_   64
#define DN_   128
#define DR_   64
#define DV_   128
#define QL_   1536
#define KVL_  512
#define DF_   576        // KVL + DR
#define QDIM_ 192        // DN + DR

#define SM_SCALE_  0.07216878364870322f
#define SCALE_Q_   2.0f
#define SCALE_KV_  3.4641016151377544f

#define TILE_M 128
#define KC     32

typedef __nv_bfloat16 bf16;

// ---------------- scratch: all activations/weights as (hi, lo) bf16 pairs ---
#define N_HID  ((size_t)S_ * HID_)
#define N_QLAT ((size_t)S_ * QL_)
#define N_Q    ((size_t)S_ * NH_ * QDIM_)
#define N_LAT  ((size_t)S_ * DF_)
#define N_KF   ((size_t)S_ * DF_)
#define N_QF   ((size_t)NH_ * S_ * DF_)
#define N_SC   ((size_t)NH_ * S_ * S_)
#define N_CTX  ((size_t)NH_ * S_ * KVL_)
#define N_AO   ((size_t)S_ * NH_ * DV_)
#define N_WQA  ((size_t)QL_ * HID_)
#define N_WQB  ((size_t)NH_ * QDIM_ * QL_)
#define N_WKVA ((size_t)DF_ * HID_)
#define N_WK   ((size_t)NH_ * KVL_ * DN_)
#define N_WV   ((size_t)NH_ * DV_ * KVL_)
#define N_WO   ((size_t)HID_ * NH_ * DV_)
#define N_CKVT ((size_t)KVL_ * S_)

__device__ __align__(256) unsigned short g_hid2 [2 * N_HID];
__device__ __align__(256) unsigned short g_qlat2[2 * N_QLAT];
__device__ __align__(256) unsigned short g_q2   [2 * N_Q];
__device__ __align__(256) unsigned short g_lat2 [2 * N_LAT];
__device__ __align__(256) unsigned short g_kf2  [2 * N_KF];
__device__ __align__(256) unsigned short g_qf2  [2 * N_QF];
__device__ __align__(256) unsigned short g_sc2  [2 * N_SC];
__device__ __align__(256) unsigned short g_ctx2 [2 * N_CTX];
__device__ __align__(256) unsigned short g_ao2  [2 * N_AO];
__device__ __align__(256) unsigned short g_wqa2 [2 * N_WQA];
__device__ __align__(256) unsigned short g_wqb2 [2 * N_WQB];
__device__ __align__(256) unsigned short g_wkva2[2 * N_WKVA];
__device__ __align__(256) unsigned short g_wk2  [2 * N_WK];
__device__ __align__(256) unsigned short g_wv2  [2 * N_WV];
__device__ __align__(256) unsigned short g_wo2  [2 * N_WO];
__device__ __align__(256) unsigned short g_ckvt2[2 * N_CKVT];

// ---------------- helpers ----------------------------------------------------
__device__ __forceinline__ uint32_t smem_u32(const void* p) {
    uint32_t a;
    asm("{ .reg .u64 t; cvta.to.shared.u64 t, %1; cvt.u32.u64 %0, t; }" : "=r"(a) : "l"(p));
    return a;
}
#define CP_ASYNC16(dst, src, sz) \
    asm volatile("cp.async.cg.shared.global [%0], [%1], 16, %2;" :: "r"(dst), "l"(src), "r"(sz))
#define CP_COMMIT() asm volatile("cp.async.commit_group;" ::: "memory")
#define CP_WAIT(n)  asm volatile("cp.async.wait_group %0;" :: "n"(n) : "memory")

#define LDSM4(r0, r1, r2, r3, a) \
    asm volatile("ldmatrix.sync.aligned.m8n8.x4.shared.b16 {%0,%1,%2,%3}, [%4];" \
                 : "=r"(r0), "=r"(r1), "=r"(r2), "=r"(r3) : "r"(a))

__device__ __forceinline__ void mma_bf16(float* d, const unsigned* a, const unsigned* b) {
    asm volatile(
        "mma.sync.aligned.m16n8k16.row.col.f32.bf16.bf16.f32 "
        "{%0,%1,%2,%3}, {%4,%5,%6,%7}, {%8,%9}, {%0,%1,%2,%3};"
        : "+f"(d[0]), "+f"(d[1]), "+f"(d[2]), "+f"(d[3])
        : "r"(a[0]), "r"(a[1]), "r"(a[2]), "r"(a[3]), "r"(b[0]), "r"(b[1]));
}

// swizzled byte offset of 16B chunk (row, kc) in a tile buffer
__device__ __forceinline__ uint32_t off_swz(int row, int kc) {
    return (uint32_t)(row >> 1) * 128u +
           (uint32_t)(((((row & 1) << 2) + kc) ^ ((row >> 1) & 7)) * 16);
}

__device__ __forceinline__ float pget(const bf16* h, const bf16* l, long long i) {
    return __bfloat162float(h[i]) + __bfloat162float(l[i]);
}
__device__ __forceinline__ void pset(bf16* h, bf16* l, long long i, float v) {
    bf16 a = __float2bfloat16(v);
    h[i] = a;
    l[i] = __float2bfloat16(v - __bfloat162float(a));
}

// flags: bit0 = causal tile skip, bit1 = K limited to row0+128, bit2 = fp32 C
template <int TN, int NSTAGE>
__global__ __launch_bounds__(256, 1) void mma_gemm(
    const bf16* __restrict__ Ahi, const bf16* __restrict__ Alo,
    const bf16* __restrict__ Bhi, const bf16* __restrict__ Blo,
    bf16* __restrict__ Chi, bf16* __restrict__ Clo, float* __restrict__ Cf,
    int M, int N, int K, int lda, int ldb, int ldc,
    long long sA, long long sB, long long sC, float alpha, int flags)
{
    constexpr uint32_t BUFA = 8192u;          // 128 rows x 32 bf16
    constexpr uint32_t BUFB = (uint32_t)TN * 64u;
    constexpr uint32_t STB  = 2u * BUFA + 2u * BUFB;
    constexpr int NFR = TN / 32;              // B n8-fragments per warp
    constexpr int NLD = TN / 64;              // B LDSM4s per buf per ks

    const int row0 = blockIdx.y * TILE_M;
    const int col0 = blockIdx.x * TN;
    if ((flags & 1) && col0 >= row0 + TILE_M) return;

    const long long bz = blockIdx.z;
    Ahi += bz * sA;  Alo += bz * sA;
    Bhi += bz * sB;  Blo += bz * sB;
    if (flags & 4) Cf += bz * sC; else { Chi += bz * sC; Clo += bz * sC; }

    const int Keff = (flags & 2) ? min(K, row0 + TILE_M) : K;
    const int KT = Keff / KC;

    extern __shared__ char smraw[];
    const uint32_t sbase = smem_u32(smraw);
    const int tid  = threadIdx.x;
    const int wid  = tid >> 5;
    const int lane = tid & 31;
    const int g    = lane >> 2;
    const int c    = lane & 3;
    const int m0   = (wid & 1) * 64;
    const int n0   = (wid >> 1) * (TN / 4);

    const int am_l = (lane & 7) + ((lane >> 3) & 1) * 8;
    const int ak_l = lane >> 4;
    const int bn_l = (lane & 7) + ((lane >> 4) & 1) * 8;
    const int bk_l = (lane >> 3) & 1;

    auto load_stage = [&](int kt) {
        const uint32_t base = sbase + (uint32_t)(kt % NSTAGE) * STB;
        const bf16* AgH = Ahi + (long long)row0 * lda + (long long)kt * KC;
        const bf16* AgL = Alo + (long long)row0 * lda + (long long)kt * KC;
        const bf16* BgH = Bhi + (long long)kt * KC;
        const bf16* BgL = Blo + (long long)kt * KC;
#pragma unroll
        for (int j = 0; j < 2; j++) {            // A: 512 chunks
            const int i  = tid + j * 256;
            const int m  = i >> 2;
            const int kc = i & 3;
            const uint32_t so = off_swz(m, kc);
            CP_ASYNC16(base + so,        AgH + (long long)m * lda + kc * 8, 16);
            CP_ASYNC16(base + BUFA + so, AgL + (long long)m * lda + kc * 8, 16);
        }
#pragma unroll
        for (int j = 0; j < TN / 64; j++) {      // B: TN*4 chunks
            const int i  = tid + j * 256;
            const int m  = i >> 2;
            const int kc = i & 3;
            const uint32_t so = off_swz(m, kc);
            const int n = col0 + m;
            const long long bo = (long long)(n < N ? n : 0) * ldb + kc * 8;
            const int sz = (n < N) ? 16 : 0;
            CP_ASYNC16(base + 2 * BUFA + so,        BgH + bo, sz);
            CP_ASYNC16(base + 2 * BUFA + BUFB + so, BgL + bo, sz);
        }
        CP_COMMIT();
    };

    float acc[4][NFR][4];
#pragma unroll
    for (int i = 0; i < 4; i++)
#pragma unroll
        for (int j = 0; j < NFR; j++)
#pragma unroll
            for (int e = 0; e < 4; e++) acc[i][j][e] = 0.f;

    const int PRE = (KT < NSTAGE - 1) ? KT : (NSTAGE - 1);
    for (int kt = 0; kt < PRE; kt++) load_stage(kt);

    for (int kt = 0; kt < KT; kt++) {
        CP_WAIT(NSTAGE - 2);
        __syncthreads();
        const int pf = kt + NSTAGE - 1;
        if (pf < KT) load_stage(pf); else CP_COMMIT();

        const uint32_t sb   = sbase + (uint32_t)(kt % NSTAGE) * STB;
        const uint32_t aHiB = sb;
        const uint32_t aLoB = sb + BUFA;
        const uint32_t bHiB = sb + 2 * BUFA;
        const uint32_t bLoB = sb + 2 * BUFA + BUFB;

#pragma unroll
        for (int ks = 0; ks < 2; ks++) {
            const int kcb = ks * 2;
            unsigned ah[4][4], al[4][4], bh[NFR][2], bl[NFR][2];
#pragma unroll
            for (int mi = 0; mi < 4; mi++) {
                const uint32_t so = off_swz(m0 + mi * 16 + am_l, kcb + ak_l);
                LDSM4(ah[mi][0], ah[mi][1], ah[mi][2], ah[mi][3], aHiB + so);
                LDSM4(al[mi][0], al[mi][1], al[mi][2], al[mi][3], aLoB + so);
            }
#pragma unroll
            for (int hB = 0; hB < NLD; hB++) {
                const uint32_t so = off_swz(n0 + hB * 16 + bn_l, kcb + bk_l);
                LDSM4(bh[2*hB][0], bh[2*hB][1], bh[2*hB+1][0], bh[2*hB+1][1], bHiB + so);
                LDSM4(bl[2*hB][0], bl[2*hB][1], bl[2*hB+1][0], bl[2*hB+1][1], bLoB + so);
            }
#pragma unroll
            for (int mi = 0; mi < 4; mi++)
#pragma unroll
                for (int ni = 0; ni < NFR; ni++) {
                    mma_bf16(acc[mi][ni], ah[mi], bh[ni]);
                    mma_bf16(acc[mi][ni], ah[mi], bl[ni]);
                    mma_bf16(acc[mi][ni], al[mi], bh[ni]);
                }
        }
    }
    CP_WAIT(0);

    // ---------------- epilogue -----------------------------------------------
#pragma unroll
    for (int mi = 0; mi < 4; mi++) {
#pragma unroll
        for (int ni = 0; ni < NFR; ni++) {
            const int n = col0 + n0 + ni * 8 + 2 * c;
#pragma unroll
            for (int h = 0; h < 2; h++) {
                const int r = row0 + m0 + mi * 16 + g + h * 8;
                float v0 = alpha * acc[mi][ni][2 * h];
                float v1 = alpha * acc[mi][ni][2 * h + 1];
                if (flags & 4) {
                    if (n + 1 < N)
                        *reinterpret_cast<float2*>(&Cf[(long long)r * ldc + n]) =
                            make_float2(v0, v1);
                    else if (n < N) Cf[(long long)r * ldc + n] = v0;
                } else {
                    bf16 h0 = __float2bfloat16(v0), h1 = __float2bfloat16(v1);
                    bf16 l0 = __float2bfloat16(v0 - __bfloat162float(h0));
                    bf16 l1 = __float2bfloat16(v1 - __bfloat162float(h1));
                    const long long o = (long long)r * ldc + n;
                    if (n + 1 < N) {
                        __nv_bfloat162 hh; hh.x = h0; hh.y = h1;
                        __nv_bfloat162 ll; ll.x = l0; ll.y = l1;
                        *reinterpret_cast<__nv_bfloat162*>(&Chi[o]) = hh;
                        *reinterpret_cast<__nv_bfloat162*>(&Clo[o]) = ll;
                    } else if (n < N) { Chi[o] = h0; Clo[o] = l0; }
                }
            }
        }
    }
}

// ---------------- fp32 -> (hi, lo) split -------------------------------------
__global__ void split_f32(const float* __restrict__ x, bf16* __restrict__ hi,
                          bf16* __restrict__ lo, long long n)
{
    long long i = (long long)blockIdx.x * blockDim.x + threadIdx.x;
    if (i >= n) return;
    float v = x[i];
    bf16 h = __float2bfloat16(v);
    hi[i] = h;
    lo[i] = __float2bfloat16(v - __bfloat162float(h));
}

// ---------------- fp32 transpose -> K-major (hi, lo) -------------------------
__global__ void transpose_split(const float* __restrict__ X, bf16* __restrict__ Thi,
                                bf16* __restrict__ Tlo, int R, int C, int ldx,
                                long long sX, long long sT)
{
    __shared__ float t[32][33];
    X   += (long long)blockIdx.z * sX;
    Thi += (long long)blockIdx.z * sT;
    Tlo += (long long)blockIdx.z * sT;
    const int c0 = blockIdx.x * 32, r0 = blockIdx.y * 32;
    const int tx = threadIdx.x, ty = threadIdx.y;
#pragma unroll
    for (int i = 0; i < 32; i += 8) {
        int r = r0 + ty + i;
        if (r < R && c0 + tx < C) t[ty + i][tx] = X[(long long)r * ldx + c0 + tx];
    }
    __syncthreads();
#pragma unroll
    for (int i = 0; i < 32; i += 8) {
        int cc = c0 + ty + i;
        if (cc < C && r0 + tx < R) {
            float v = t[tx][ty + i];
            long long o = (long long)cc * R + r0 + tx;
            bf16 h = __float2bfloat16(v);
            Thi[o] = h;
            Tlo[o] = __float2bfloat16(v - __bfloat162float(h));
        }
    }
}

// ---------------- bf16 transpose ---------------------------------------------
__global__ void transpose_bf16(const bf16* __restrict__ X, bf16* __restrict__ T,
                               int R, int C, int ldx)
{
    __shared__ bf16 t[32][33];
    const int c0 = blockIdx.x * 32, r0 = blockIdx.y * 32;
    const int tx = threadIdx.x, ty = threadIdx.y;
#pragma unroll
    for (int i = 0; i < 32; i += 8) {
        int r = r0 + ty + i;
        if (r < R && c0 + tx < C) t[ty + i][tx] = X[(long long)r * ldx + c0 + tx];
    }
    __syncthreads();
#pragma unroll
    for (int i = 0; i < 32; i += 8) {
        int cc = c0 + ty + i;
        if (cc < C && r0 + tx < R) T[(long long)cc * R + r0 + tx] = t[tx][ty + i];
    }
}

// ---------------- RMSNorm (pair in place) ------------------------------------
__global__ void rmsnorm_q(bf16* __restrict__ xh, bf16* __restrict__ xl,
                          const float* __restrict__ w)
{
    const int s = blockIdx.x;
    const long long base = (long long)s * QL_;
    const int tid = threadIdx.x;
    __shared__ float red[256];
    float ss = 0.f;
    for (int j = tid; j < QL_; j += 256) { float v = pget(xh, xl, base + j); ss += v * v; }
    red[tid] = ss; __syncthreads();
    for (int off = 128; off > 0; off >>= 1) {
        if (tid < off) red[tid] += red[tid + off];
        __syncthreads();
    }
    const float inv = rsqrtf(red[0] / QL_ + 1e-6f) * SCALE_Q_;
    for (int j = tid; j < QL_; j += 256)
        pset(xh, xl, base + j, w[j] * pget(xh, xl, base + j) * inv);
}

// ---------------- kva RMSNorm + k_pe RoPE -> k_full (pairs) ------------------
__global__ void kva_norm_rope(const bf16* __restrict__ lh, const bf16* __restrict__ ll,
                              const float* __restrict__ w,
                              const float* __restrict__ cosb, const float* __restrict__ sinb,
                              bf16* __restrict__ kh, bf16* __restrict__ kl)
{
    const int s = blockIdx.x;
    const int tid = threadIdx.x;           // 128 threads
    const long long base = (long long)s * DF_;
    __shared__ float red[128];
    float ss = 0.f;
    for (int j = tid; j < KVL_; j += 128) { float v = pget(lh, ll, base + j); ss += v * v; }
    red[tid] = ss; __syncthreads();
    for (int off = 64; off > 0; off >>= 1) {
        if (tid < off) red[tid] += red[tid + off];
        __syncthreads();
    }
    const float inv = rsqrtf(red[0] / KVL_ + 1e-6f) * SCALE_KV_;
    for (int j = tid; j < KVL_; j += 128)
        pset(kh, kl, base + j, w[j] * pget(lh, ll, base + j) * inv);
    if (tid < DR_) {
        const int r = tid;
        float x = pget(lh, ll, base + KVL_ + r);
        float o = (r < 32) ? -pget(lh, ll, base + KVL_ + r + 32)
                           :  pget(lh, ll, base + KVL_ + r - 32);
        pset(kh, kl, base + KVL_ + r, x * cosb[s * DR_ + r] + o * sinb[s * DR_ + r]);
    }
}

// ---------------- q_pe RoPE -> q_full[h][s][512+r] (pairs) -------------------
__global__ void rope_q(const bf16* __restrict__ qh, const bf16* __restrict__ ql,
                       const float* __restrict__ cosb, const float* __restrict__ sinb,
                       bf16* __restrict__ fh, bf16* __restrict__ fl)
{
    long long idx = (long long)blockIdx.x * blockDim.x + threadIdx.x;
    if (idx >= (long long)S_ * NH_ * DR_) return;
    const int r = (int)(idx % DR_);
    const int h = (int)((idx / DR_) % NH_);
    const int s = (int)(idx / ((long long)DR_ * NH_));
    const long long qb = (long long)s * NH_ * QDIM_ + h * QDIM_ + DN_;
    float x = pget(qh, ql, qb + r);
    float o = (r < 32) ? -pget(qh, ql, qb + r + 32) : pget(qh, ql, qb + r - 32);
    pset(fh, fl, ((long long)h * S_ + s) * DF_ + KVL_ + r,
         x * cosb[s * DR_ + r] + o * sinb[s * DR_ + r]);
}

// ------- causal softmax on pairs (zero-fill up to row-block end) -------------
__global__ void softmax_causal(bf16* __restrict__ sh, bf16* __restrict__ sl)
{
    const int s = blockIdx.x, h = blockIdx.y;
    const long long base = ((long long)h * S_ + s) * (long long)S_;
    const int tid = threadIdx.x;
    __shared__ float red[256];

    float m = -1e30f;
    for (int t = tid; t <= s; t += 256) m = fmaxf(m, pget(sh, sl, base + t));
    red[tid] = m; __syncthreads();
    for (int off = 128; off > 0; off >>= 1) {
        if (tid < off) red[tid] = fmaxf(red[tid], red[tid + off]);
        __syncthreads();
    }
    m = red[0]; __syncthreads();

    float sum = 0.f;
    for (int t = tid; t <= s; t += 256) {
        float e = __expf(pget(sh, sl, base + t) - m);
        pset(sh, sl, base + t, e);
        sum += e;
    }
    red[tid] = sum; __syncthreads();
    for (int off = 128; off > 0; off >>= 1) {
        if (tid < off) red[tid] += red[tid + off];
        __syncthreads();
    }
    const float inv = 1.f / red[0];
    const int rowEnd = (s & ~(TILE_M - 1)) + TILE_M;
    for (int t = tid; t < rowEnd; t += 256) {
        float v = (t <= s) ? pget(sh, sl, base + t) * inv : 0.f;
        pset(sh, sl, base + t, v);
    }
}

// =============================================================================
extern "C" void kernel_launch(void* const* d_in, const int* in_sizes, int n_in,
                              void* d_out, int out_size)
{
    const float* hidden = (const float*)d_in[0];
    const float* cosb   = (const float*)d_in[1];
    const float* sinb   = (const float*)d_in[2];
    const float* w_qa   = (const float*)d_in[3];
    const float* qa_ln  = (const float*)d_in[4];
    const float* w_qb   = (const float*)d_in[5];
    const float* w_kva  = (const float*)d_in[6];
    const float* kva_ln = (const float*)d_in[7];
    const float* w_k    = (const float*)d_in[8];
    const float* w_v    = (const float*)d_in[9];
    const float* w_o    = (const float*)d_in[10];
    float* out = (float*)d_out;

    bf16 *hid, *qlat, *q, *lat, *kf, *qf, *sc, *ctx, *ao;
    bf16 *wqa, *wqb, *wkva, *wk, *wv, *wo, *ckvt;
    cudaGetSymbolAddress((void**)&hid,  g_hid2);
    cudaGetSymbolAddress((void**)&qlat, g_qlat2);
    cudaGetSymbolAddress((void**)&q,    g_q2);
    cudaGetSymbolAddress((void**)&lat,  g_lat2);
    cudaGetSymbolAddress((void**)&kf,   g_kf2);
    cudaGetSymbolAddress((void**)&qf,   g_qf2);
    cudaGetSymbolAddress((void**)&sc,   g_sc2);
    cudaGetSymbolAddress((void**)&ctx,  g_ctx2);
    cudaGetSymbolAddress((void**)&ao,   g_ao2);
    cudaGetSymbolAddress((void**)&wqa,  g_wqa2);
    cudaGetSymbolAddress((void**)&wqb,  g_wqb2);
    cudaGetSymbolAddress((void**)&wkva, g_wkva2);
    cudaGetSymbolAddress((void**)&wk,   g_wk2);
    cudaGetSymbolAddress((void**)&wv,   g_wv2);
    cudaGetSymbolAddress((void**)&wo,   g_wo2);
    cudaGetSymbolAddress((void**)&ckvt, g_ckvt2);

    bf16 *hidL = hid + N_HID,  *qlatL = qlat + N_QLAT, *qL = q + N_Q;
    bf16 *latL = lat + N_LAT,  *kfL = kf + N_KF,       *qfL = qf + N_QF;
    bf16 *scL  = sc + N_SC,    *ctxL = ctx + N_CTX,    *aoL = ao + N_AO;
    bf16 *wqaL = wqa + N_WQA,  *wqbL = wqb + N_WQB,    *wkvaL = wkva + N_WKVA;
    bf16 *wkL  = wk + N_WK,    *wvL = wv + N_WV,       *woL = wo + N_WO;
    bf16 *ckvtL = ckvt + N_CKVT;

    constexpr int SM128 = 4 * (2 * 8192 + 2 * 128 * 64);   // 131072
    constexpr int SM256 = 3 * (2 * 8192 + 2 * 256 * 64);   // 147456
    cudaFuncSetAttribute(mma_gemm<128, 4>, cudaFuncAttributeMaxDynamicSharedMemorySize, SM128);
    cudaFuncSetAttribute(mma_gemm<256, 3>, cudaFuncAttributeMaxDynamicSharedMemorySize, SM256);

    const dim3 tb(32, 8);

    {
        long long n = (long long)N_HID;
        split_f32<<<(unsigned)((n + 255) / 256), 256>>>(hidden, hid, hidL, n);
    }
    transpose_split<<<dim3(QL_ / 32, HID_ / 32, 1), tb>>>(w_qa, wqa, wqaL, HID_, QL_, QL_, 0, 0);
    transpose_split<<<dim3(NH_ * QDIM_ / 32, QL_ / 32, 1), tb>>>(w_qb, wqb, wqbL, QL_, NH_ * QDIM_, NH_ * QDIM_, 0, 0);
    transpose_split<<<dim3(DF_ / 32, HID_ / 32, 1), tb>>>(w_kva, wkva, wkvaL, HID_, DF_, DF_, 0, 0);
    transpose_split<<<dim3(KVL_ / 32, DN_ / 32, NH_), tb>>>(w_k, wk, wkL, DN_, KVL_, KVL_,
        (long long)DN_ * KVL_, (long long)KVL_ * DN_);
    transpose_split<<<dim3(DV_ / 32, KVL_ / 32, NH_), tb>>>(w_v, wv, wvL, KVL_, DV_, DV_,
        (long long)KVL_ * DV_, (long long)DV_ * KVL_);
    transpose_split<<<dim3(HID_ / 32, (NH_ * DV_) / 32, 1), tb>>>(w_o, wo, woL, NH_ * DV_, HID_, HID_, 0, 0);

    // 1) q_lat = hidden @ w_qa   (TN=128: 144 blocks ~ 1 wave)
    mma_gemm<128, 4><<<dim3(QL_ / 128, S_ / TILE_M, 1), 256, SM128>>>(
        hid, hidL, wqa, wqaL, qlat, qlatL, nullptr,
        S_, QL_, HID_, HID_, HID_, QL_, 0, 0, 0, 1.f, 0);
    // 2) RMSNorm
    rmsnorm_q<<<S_, 256>>>(qlat, qlatL, qa_ln);
    // 3) q = q_lat @ w_qb   (TN=256)
    mma_gemm<256, 3><<<dim3(NH_ * QDIM_ / 256, S_ / TILE_M, 1), 256, SM256>>>(
        qlat, qlatL, wqb, wqbL, q, qL, nullptr,
        S_, NH_ * QDIM_, QL_, QL_, QL_, NH_ * QDIM_, 0, 0, 0, 1.f, 0);
    // 4) latent = hidden @ w_kva   (N=576, TN=128)
    mma_gemm<128, 4><<<dim3((DF_ + 127) / 128, S_ / TILE_M, 1), 256, SM128>>>(
        hid, hidL, wkva, wkvaL, lat, latL, nullptr,
        S_, DF_, HID_, HID_, HID_, DF_, 0, 0, 0, 1.f, 0);
    // 5) k_full
    kva_norm_rope<<<S_, 128>>>(lat, latL, kva_ln, cosb, sinb, kf, kfL);
    transpose_bf16<<<dim3(KVL_ / 32, S_ / 32), tb>>>(kf,  ckvt,  S_, KVL_, DF_);
    transpose_bf16<<<dim3(KVL_ / 32, S_ / 32), tb>>>(kfL, ckvtL, S_, KVL_, DF_);
    // 6) rope q_pe
    {
        long long tot = (long long)S_ * NH_ * DR_;
        rope_q<<<(unsigned)((tot + 255) / 256), 256>>>(q, qL, cosb, sinb, qf, qfL);
    }
    // 7) q_abs   (TN=256, N=512)
    mma_gemm<256, 3><<<dim3(KVL_ / 256, S_ / TILE_M, NH_), 256, SM256>>>(
        q, qL, wk, wkL, qf, qfL, nullptr,
        S_, KVL_, DN_, NH_ * QDIM_, DN_, DF_,
        (long long)QDIM_, (long long)KVL_ * DN_, (long long)S_ * DF_, 1.f, 0);
    // 8) scores   (TN=256, causal skip)
    mma_gemm<256, 3><<<dim3(S_ / 256, S_ / TILE_M, NH_), 256, SM256>>>(
        qf, qfL, kf, kfL, sc, scL, nullptr,
        S_, S_, DF_, DF_, DF_, S_,
        (long long)S_ * DF_, 0LL, (long long)S_ * S_, SM_SCALE_, 1);
    // 9) softmax
    softmax_causal<<<dim3(S_, NH_), 256>>>(sc, scL);
    // 10) ctx   (TN=256, K-limit)
    mma_gemm<256, 3><<<dim3(KVL_ / 256, S_ / TILE_M, NH_), 256, SM256>>>(
        sc, scL, ckvt, ckvtL, ctx, ctxL, nullptr,
        S_, KVL_, S_, S_, S_, KVL_,
        (long long)S_ * S_, 0LL, (long long)S_ * KVL_, 1.f, 2);
    // 11) attn_out   (TN=128, N=128)
    mma_gemm<128, 4><<<dim3(1, S_ / TILE_M, NH_), 256, SM128>>>(
        ctx, ctxL, wv, wvL, ao, aoL, nullptr,
        S_, DV_, KVL_, KVL_, KVL_, NH_ * DV_,
        (long long)S_ * KVL_, (long long)DV_ * KVL_, (long long)DV_, 1.f, 0);
    // 12) out = ao @ w_o   (TN=256, fp32 out)
    mma_gemm<256, 3><<<dim3(HID_ / 256, S_ / TILE_M, 1), 256, SM256>>>(
        ao, aoL, wo, woL, nullptr, nullptr, out,
        S_, HID_, NH_ * DV_, NH_ * DV_, NH_ * DV_, HID_, 0, 0, 0, 1.f, 4);
}

// round 7
// speedup vs baseline: 3.7088x; 1.0491x over previous
#include <cuda_runtime.h>
#include <cuda_bf16.h>
#include <cstdint>
#include <math.h>

#define S_    1536
#define HID_  6144
#define NH_   64
#define DN_   128
#define DR_   64
#define DV_   128
#define QL_   1536
#define KVL_  512
#define DF_   576        // KVL + DR
#define QDIM_ 192        // DN + DR

#define SM_SCALE_  0.07216878364870322f
#define SCALE_Q_   2.0f
#define SCALE_KV_  3.4641016151377544f

#define TILE_M 128
#define KC     32

typedef __nv_bfloat16 bf16;

// ---------------- scratch: all activations/weights as (hi, lo) bf16 pairs ---
#define N_HID  ((size_t)S_ * HID_)
#define N_QLAT ((size_t)S_ * QL_)
#define N_Q    ((size_t)S_ * NH_ * QDIM_)
#define N_LAT  ((size_t)S_ * DF_)
#define N_KF   ((size_t)S_ * DF_)
#define N_QF   ((size_t)NH_ * S_ * DF_)
#define N_SC   ((size_t)NH_ * S_ * S_)
#define N_CTX  ((size_t)NH_ * S_ * KVL_)
#define N_AO   ((size_t)S_ * NH_ * DV_)
#define N_WQA  ((size_t)QL_ * HID_)
#define N_WQB  ((size_t)NH_ * QDIM_ * QL_)
#define N_WKVA ((size_t)DF_ * HID_)
#define N_WK   ((size_t)NH_ * KVL_ * DN_)
#define N_WV   ((size_t)NH_ * DV_ * KVL_)
#define N_WO   ((size_t)HID_ * NH_ * DV_)
#define N_CKVT ((size_t)KVL_ * S_)

__device__ __align__(256) unsigned short g_hid2 [2 * N_HID];
__device__ __align__(256) unsigned short g_qlat2[2 * N_QLAT];
__device__ __align__(256) unsigned short g_q2   [2 * N_Q];
__device__ __align__(256) unsigned short g_lat2 [2 * N_LAT];
__device__ __align__(256) unsigned short g_kf2  [2 * N_KF];
__device__ __align__(256) unsigned short g_qf2  [2 * N_QF];
__device__ __align__(256) unsigned short g_sc2  [2 * N_SC];
__device__ __align__(256) unsigned short g_ctx2 [2 * N_CTX];
__device__ __align__(256) unsigned short g_ao2  [2 * N_AO];
__device__ __align__(256) unsigned short g_wqa2 [2 * N_WQA];
__device__ __align__(256) unsigned short g_wqb2 [2 * N_WQB];
__device__ __align__(256) unsigned short g_wkva2[2 * N_WKVA];
__device__ __align__(256) unsigned short g_wk2  [2 * N_WK];
__device__ __align__(256) unsigned short g_wv2  [2 * N_WV];
__device__ __align__(256) unsigned short g_wo2  [2 * N_WO];
__device__ __align__(256) unsigned short g_ckvt2[2 * N_CKVT];

// ---------------- helpers ----------------------------------------------------
__device__ __forceinline__ uint32_t smem_u32(const void* p) {
    uint32_t a;
    asm("{ .reg .u64 t; cvta.to.shared.u64 t, %1; cvt.u32.u64 %0, t; }" : "=r"(a) : "l"(p));
    return a;
}
#define CP_ASYNC16(dst, src, sz) \
    asm volatile("cp.async.cg.shared.global [%0], [%1], 16, %2;" :: "r"(dst), "l"(src), "r"(sz))
#define CP_COMMIT() asm volatile("cp.async.commit_group;" ::: "memory")
#define CP_WAIT(n)  asm volatile("cp.async.wait_group %0;" :: "n"(n) : "memory")

#define LDSM4(r0, r1, r2, r3, a) \
    asm volatile("ldmatrix.sync.aligned.m8n8.x4.shared.b16 {%0,%1,%2,%3}, [%4];" \
                 : "=r"(r0), "=r"(r1), "=r"(r2), "=r"(r3) : "r"(a))

__device__ __forceinline__ void mma_bf16(float* d, const unsigned* a, const unsigned* b) {
    asm volatile(
        "mma.sync.aligned.m16n8k16.row.col.f32.bf16.bf16.f32 "
        "{%0,%1,%2,%3}, {%4,%5,%6,%7}, {%8,%9}, {%0,%1,%2,%3};"
        : "+f"(d[0]), "+f"(d[1]), "+f"(d[2]), "+f"(d[3])
        : "r"(a[0]), "r"(a[1]), "r"(a[2]), "r"(a[3]), "r"(b[0]), "r"(b[1]));
}

// swizzled byte offset of 16B chunk (row, kc) in a tile buffer
__device__ __forceinline__ uint32_t off_swz(int row, int kc) {
    return (uint32_t)(row >> 1) * 128u +
           (uint32_t)(((((row & 1) << 2) + kc) ^ ((row >> 1) & 7)) * 16);
}

__device__ __forceinline__ float pget(const bf16* h, const bf16* l, long long i) {
    return __bfloat162float(h[i]) + __bfloat162float(l[i]);
}
__device__ __forceinline__ void pset(bf16* h, bf16* l, long long i, float v) {
    bf16 a = __float2bfloat16(v);
    h[i] = a;
    l[i] = __float2bfloat16(v - __bfloat162float(a));
}
__device__ __forceinline__ void unpack2(unsigned h, unsigned l, float& a, float& b) {
    a = __uint_as_float(h << 16) + __uint_as_float(l << 16);
    b = __uint_as_float(h & 0xffff0000u) + __uint_as_float(l & 0xffff0000u);
}

// flags: bit0 = causal tile skip, bit1 = K limited to row0+128, bit2 = fp32 C
template <int TN, int NSTAGE>
__global__ __launch_bounds__(256, 1) void mma_gemm(
    const bf16* __restrict__ Ahi, const bf16* __restrict__ Alo,
    const bf16* __restrict__ Bhi, const bf16* __restrict__ Blo,
    bf16* __restrict__ Chi, bf16* __restrict__ Clo, float* __restrict__ Cf,
    int M, int N, int K, int lda, int ldb, int ldc,
    long long sA, long long sB, long long sC, float alpha, int flags)
{
    constexpr uint32_t BUFA = 8192u;
    constexpr uint32_t BUFB = (uint32_t)TN * 64u;
    constexpr uint32_t STB  = 2u * BUFA + 2u * BUFB;
    constexpr int NFR = TN / 32;
    constexpr int NLD = TN / 64;

    const int row0 = blockIdx.y * TILE_M;
    const int col0 = blockIdx.x * TN;
    if ((flags & 1) && col0 >= row0 + TILE_M) return;

    const long long bz = blockIdx.z;
    Ahi += bz * sA;  Alo += bz * sA;
    Bhi += bz * sB;  Blo += bz * sB;
    if (flags & 4) Cf += bz * sC; else { Chi += bz * sC; Clo += bz * sC; }

    const int Keff = (flags & 2) ? min(K, row0 + TILE_M) : K;
    const int KT = Keff / KC;

    extern __shared__ char smraw[];
    const uint32_t sbase = smem_u32(smraw);
    const int tid  = threadIdx.x;
    const int wid  = tid >> 5;
    const int lane = tid & 31;
    const int g    = lane >> 2;
    const int c    = lane & 3;
    const int m0   = (wid & 1) * 64;
    const int n0   = (wid >> 1) * (TN / 4);

    const int am_l = (lane & 7) + ((lane >> 3) & 1) * 8;
    const int ak_l = lane >> 4;
    const int bn_l = (lane & 7) + ((lane >> 4) & 1) * 8;
    const int bk_l = (lane >> 3) & 1;

    auto load_stage = [&](int kt) {
        const uint32_t base = sbase + (uint32_t)(kt % NSTAGE) * STB;
        const bf16* AgH = Ahi + (long long)row0 * lda + (long long)kt * KC;
        const bf16* AgL = Alo + (long long)row0 * lda + (long long)kt * KC;
        const bf16* BgH = Bhi + (long long)kt * KC;
        const bf16* BgL = Blo + (long long)kt * KC;
#pragma unroll
        for (int j = 0; j < 2; j++) {
            const int i  = tid + j * 256;
            const int m  = i >> 2;
            const int kc = i & 3;
            const uint32_t so = off_swz(m, kc);
            CP_ASYNC16(base + so,        AgH + (long long)m * lda + kc * 8, 16);
            CP_ASYNC16(base + BUFA + so, AgL + (long long)m * lda + kc * 8, 16);
        }
#pragma unroll
        for (int j = 0; j < TN / 64; j++) {
            const int i  = tid + j * 256;
            const int m  = i >> 2;
            const int kc = i & 3;
            const uint32_t so = off_swz(m, kc);
            const int n = col0 + m;
            const long long bo = (long long)(n < N ? n : 0) * ldb + kc * 8;
            const int sz = (n < N) ? 16 : 0;
            CP_ASYNC16(base + 2 * BUFA + so,        BgH + bo, sz);
            CP_ASYNC16(base + 2 * BUFA + BUFB + so, BgL + bo, sz);
        }
        CP_COMMIT();
    };

    float acc[4][NFR][4];
#pragma unroll
    for (int i = 0; i < 4; i++)
#pragma unroll
        for (int j = 0; j < NFR; j++)
#pragma unroll
            for (int e = 0; e < 4; e++) acc[i][j][e] = 0.f;

    const int PRE = (KT < NSTAGE - 1) ? KT : (NSTAGE - 1);
    for (int kt = 0; kt < PRE; kt++) load_stage(kt);

    for (int kt = 0; kt < KT; kt++) {
        CP_WAIT(NSTAGE - 2);
        __syncthreads();
        const int pf = kt + NSTAGE - 1;
        if (pf < KT) load_stage(pf); else CP_COMMIT();

        const uint32_t sb   = sbase + (uint32_t)(kt % NSTAGE) * STB;
        const uint32_t aHiB = sb;
        const uint32_t aLoB = sb + BUFA;
        const uint32_t bHiB = sb + 2 * BUFA;
        const uint32_t bLoB = sb + 2 * BUFA + BUFB;

#pragma unroll
        for (int ks = 0; ks < 2; ks++) {
            const int kcb = ks * 2;
            unsigned ah[4][4], al[4][4], bh[NFR][2], bl[NFR][2];
#pragma unroll
            for (int mi = 0; mi < 4; mi++) {
                const uint32_t so = off_swz(m0 + mi * 16 + am_l, kcb + ak_l);
                LDSM4(ah[mi][0], ah[mi][1], ah[mi][2], ah[mi][3], aHiB + so);
                LDSM4(al[mi][0], al[mi][1], al[mi][2], al[mi][3], aLoB + so);
            }
#pragma unroll
            for (int hB = 0; hB < NLD; hB++) {
                const uint32_t so = off_swz(n0 + hB * 16 + bn_l, kcb + bk_l);
                LDSM4(bh[2*hB][0], bh[2*hB][1], bh[2*hB+1][0], bh[2*hB+1][1], bHiB + so);
                LDSM4(bl[2*hB][0], bl[2*hB][1], bl[2*hB+1][0], bl[2*hB+1][1], bLoB + so);
            }
#pragma unroll
            for (int mi = 0; mi < 4; mi++)
#pragma unroll
                for (int ni = 0; ni < NFR; ni++) {
                    mma_bf16(acc[mi][ni], ah[mi], bh[ni]);
                    mma_bf16(acc[mi][ni], ah[mi], bl[ni]);
                    mma_bf16(acc[mi][ni], al[mi], bh[ni]);
                }
        }
    }
    CP_WAIT(0);

    // ---------------- epilogue -----------------------------------------------
#pragma unroll
    for (int mi = 0; mi < 4; mi++) {
#pragma unroll
        for (int ni = 0; ni < NFR; ni++) {
            const int n = col0 + n0 + ni * 8 + 2 * c;
#pragma unroll
            for (int h = 0; h < 2; h++) {
                const int r = row0 + m0 + mi * 16 + g + h * 8;
                float v0 = alpha * acc[mi][ni][2 * h];
                float v1 = alpha * acc[mi][ni][2 * h + 1];
                if (flags & 4) {
                    if (n + 1 < N)
                        *reinterpret_cast<float2*>(&Cf[(long long)r * ldc + n]) =
                            make_float2(v0, v1);
                    else if (n < N) Cf[(long long)r * ldc + n] = v0;
                } else {
                    bf16 h0 = __float2bfloat16(v0), h1 = __float2bfloat16(v1);
                    bf16 l0 = __float2bfloat16(v0 - __bfloat162float(h0));
                    bf16 l1 = __float2bfloat16(v1 - __bfloat162float(h1));
                    const long long o = (long long)r * ldc + n;
                    if (n + 1 < N) {
                        __nv_bfloat162 hh; hh.x = h0; hh.y = h1;
                        __nv_bfloat162 ll; ll.x = l0; ll.y = l1;
                        *reinterpret_cast<__nv_bfloat162*>(&Chi[o]) = hh;
                        *reinterpret_cast<__nv_bfloat162*>(&Clo[o]) = ll;
                    } else if (n < N) { Chi[o] = h0; Clo[o] = l0; }
                }
            }
        }
    }
}

// ---------------- fp32 -> (hi, lo) split -------------------------------------
__global__ void split_f32(const float* __restrict__ x, bf16* __restrict__ hi,
                          bf16* __restrict__ lo, long long n)
{
    long long i = (long long)blockIdx.x * blockDim.x + threadIdx.x;
    if (i >= n) return;
    float v = x[i];
    bf16 h = __float2bfloat16(v);
    hi[i] = h;
    lo[i] = __float2bfloat16(v - __bfloat162float(h));
}

// ---------------- fp32 transpose -> K-major (hi, lo) -------------------------
__global__ void transpose_split(const float* __restrict__ X, bf16* __restrict__ Thi,
                                bf16* __restrict__ Tlo, int R, int C, int ldx,
                                long long sX, long long sT)
{
    __shared__ float t[32][33];
    X   += (long long)blockIdx.z * sX;
    Thi += (long long)blockIdx.z * sT;
    Tlo += (long long)blockIdx.z * sT;
    const int c0 = blockIdx.x * 32, r0 = blockIdx.y * 32;
    const int tx = threadIdx.x, ty = threadIdx.y;
#pragma unroll
    for (int i = 0; i < 32; i += 8) {
        int r = r0 + ty + i;
        if (r < R && c0 + tx < C) t[ty + i][tx] = X[(long long)r * ldx + c0 + tx];
    }
    __syncthreads();
#pragma unroll
    for (int i = 0; i < 32; i += 8) {
        int cc = c0 + ty + i;
        if (cc < C && r0 + tx < R) {
            float v = t[tx][ty + i];
            long long o = (long long)cc * R + r0 + tx;
            bf16 h = __float2bfloat16(v);
            Thi[o] = h;
            Tlo[o] = __float2bfloat16(v - __bfloat162float(h));
        }
    }
}

// ---------------- bf16 transpose ---------------------------------------------
__global__ void transpose_bf16(const bf16* __restrict__ X, bf16* __restrict__ T,
                               int R, int C, int ldx)
{
    __shared__ bf16 t[32][33];
    const int c0 = blockIdx.x * 32, r0 = blockIdx.y * 32;
    const int tx = threadIdx.x, ty = threadIdx.y;
#pragma unroll
    for (int i = 0; i < 32; i += 8) {
        int r = r0 + ty + i;
        if (r < R && c0 + tx < C) t[ty + i][tx] = X[(long long)r * ldx + c0 + tx];
    }
    __syncthreads();
#pragma unroll
    for (int i = 0; i < 32; i += 8) {
        int cc = c0 + ty + i;
        if (cc < C && r0 + tx < R) T[(long long)cc * R + r0 + tx] = t[tx][ty + i];
    }
}

// ---------------- RMSNorm (pair in place) ------------------------------------
__global__ void rmsnorm_q(bf16* __restrict__ xh, bf16* __restrict__ xl,
                          const float* __restrict__ w)
{
    const int s = blockIdx.x;
    const long long base = (long long)s * QL_;
    const int tid = threadIdx.x;
    __shared__ float red[256];
    float ss = 0.f;
    for (int j = tid; j < QL_; j += 256) { float v = pget(xh, xl, base + j); ss += v * v; }
    red[tid] = ss; __syncthreads();
    for (int off = 128; off > 0; off >>= 1) {
        if (tid < off) red[tid] += red[tid + off];
        __syncthreads();
    }
    const float inv = rsqrtf(red[0] / QL_ + 1e-6f) * SCALE_Q_;
    for (int j = tid; j < QL_; j += 256)
        pset(xh, xl, base + j, w[j] * pget(xh, xl, base + j) * inv);
}

// ---------------- kva RMSNorm + k_pe RoPE -> k_full (pairs) ------------------
__global__ void kva_norm_rope(const bf16* __restrict__ lh, const bf16* __restrict__ ll,
                              const float* __restrict__ w,
                              const float* __restrict__ cosb, const float* __restrict__ sinb,
                              bf16* __restrict__ kh, bf16* __restrict__ kl)
{
    const int s = blockIdx.x;
    const int tid = threadIdx.x;           // 128 threads
    const long long base = (long long)s * DF_;
    __shared__ float red[128];
    float ss = 0.f;
    for (int j = tid; j < KVL_; j += 128) { float v = pget(lh, ll, base + j); ss += v * v; }
    red[tid] = ss; __syncthreads();
    for (int off = 64; off > 0; off >>= 1) {
        if (tid < off) red[tid] += red[tid + off];
        __syncthreads();
    }
    const float inv = rsqrtf(red[0] / KVL_ + 1e-6f) * SCALE_KV_;
    for (int j = tid; j < KVL_; j += 128)
        pset(kh, kl, base + j, w[j] * pget(lh, ll, base + j) * inv);
    if (tid < DR_) {
        const int r = tid;
        float x = pget(lh, ll, base + KVL_ + r);
        float o = (r < 32) ? -pget(lh, ll, base + KVL_ + r + 32)
                           :  pget(lh, ll, base + KVL_ + r - 32);
        pset(kh, kl, base + KVL_ + r, x * cosb[s * DR_ + r] + o * sinb[s * DR_ + r]);
    }
}

// ---------------- q_pe RoPE -> q_full[h][s][512+r] (pairs) -------------------
__global__ void rope_q(const bf16* __restrict__ qh, const bf16* __restrict__ ql,
                       const float* __restrict__ cosb, const float* __restrict__ sinb,
                       bf16* __restrict__ fh, bf16* __restrict__ fl)
{
    long long idx = (long long)blockIdx.x * blockDim.x + threadIdx.x;
    if (idx >= (long long)S_ * NH_ * DR_) return;
    const int r = (int)(idx % DR_);
    const int h = (int)((idx / DR_) % NH_);
    const int s = (int)(idx / ((long long)DR_ * NH_));
    const long long qb = (long long)s * NH_ * QDIM_ + h * QDIM_ + DN_;
    float x = pget(qh, ql, qb + r);
    float o = (r < 32) ? -pget(qh, ql, qb + r + 32) : pget(qh, ql, qb + r - 32);
    pset(fh, fl, ((long long)h * S_ + s) * DF_ + KVL_ + r,
         x * cosb[s * DR_ + r] + o * sinb[s * DR_ + r]);
}

// ------- causal softmax: smem row cache, uint4 vectorized, 1R + 1W ----------
__global__ __launch_bounds__(256) void softmax_causal(bf16* __restrict__ sh,
                                                      bf16* __restrict__ sl)
{
    const int s = blockIdx.x, h = blockIdx.y;
    const long long base = ((long long)h * S_ + s) * (long long)S_;
    __shared__ float vals[S_];
    __shared__ float red[256];
    const int tid = threadIdx.x;
    const int len = s + 1;
    const int len8 = len & ~7;

    float m = -1e30f;
    for (int t = tid * 8; t < len8; t += 2048) {
        uint4 vh = *reinterpret_cast<const uint4*>(&sh[base + t]);
        uint4 vl = *reinterpret_cast<const uint4*>(&sl[base + t]);
        float f[8];
        unpack2(vh.x, vl.x, f[0], f[1]);
        unpack2(vh.y, vl.y, f[2], f[3]);
        unpack2(vh.z, vl.z, f[4], f[5]);
        unpack2(vh.w, vl.w, f[6], f[7]);
#pragma unroll
        for (int j = 0; j < 8; j++) { vals[t + j] = f[j]; m = fmaxf(m, f[j]); }
    }
    for (int t = len8 + tid; t < len; t += 256) {
        float v = __bfloat162float(sh[base + t]) + __bfloat162float(sl[base + t]);
        vals[t] = v; m = fmaxf(m, v);
    }
    red[tid] = m; __syncthreads();
    for (int off = 128; off > 0; off >>= 1) {
        if (tid < off) red[tid] = fmaxf(red[tid], red[tid + off]);
        __syncthreads();
    }
    m = red[0]; __syncthreads();

    float sum = 0.f;
    for (int t = tid; t < len; t += 256) {
        float e = __expf(vals[t] - m);
        vals[t] = e; sum += e;
    }
    red[tid] = sum; __syncthreads();
    for (int off = 128; off > 0; off >>= 1) {
        if (tid < off) red[tid] += red[tid + off];
        __syncthreads();
    }
    const float inv = 1.f / red[0];

    const int rowEnd = (s & ~(TILE_M - 1)) + TILE_M;   // ctx GEMM reads k < rowEnd
    for (int t = tid * 8; t < rowEnd; t += 2048) {
        unsigned uh[4], ul[4];
#pragma unroll
        for (int p = 0; p < 4; p++) {
            float a = (t + 2 * p     < len) ? vals[t + 2 * p] * inv : 0.f;
            float b = (t + 2 * p + 1 < len) ? vals[t + 2 * p + 1] * inv : 0.f;
            bf16 ha = __float2bfloat16(a), hb = __float2bfloat16(b);
            bf16 la = __float2bfloat16(a - __bfloat162float(ha));
            bf16 lb = __float2bfloat16(b - __bfloat162float(hb));
            __nv_bfloat162 hv; hv.x = ha; hv.y = hb;
            __nv_bfloat162 lv; lv.x = la; lv.y = lb;
            uh[p] = *reinterpret_cast<unsigned*>(&hv);
            ul[p] = *reinterpret_cast<unsigned*>(&lv);
        }
        *reinterpret_cast<uint4*>(&sh[base + t]) = make_uint4(uh[0], uh[1], uh[2], uh[3]);
        *reinterpret_cast<uint4*>(&sl[base + t]) = make_uint4(ul[0], ul[1], ul[2], ul[3]);
    }
}

// =============================================================================
extern "C" void kernel_launch(void* const* d_in, const int* in_sizes, int n_in,
                              void* d_out, int out_size)
{
    const float* hidden = (const float*)d_in[0];
    const float* cosb   = (const float*)d_in[1];
    const float* sinb   = (const float*)d_in[2];
    const float* w_qa   = (const float*)d_in[3];
    const float* qa_ln  = (const float*)d_in[4];
    const float* w_qb   = (const float*)d_in[5];
    const float* w_kva  = (const float*)d_in[6];
    const float* kva_ln = (const float*)d_in[7];
    const float* w_k    = (const float*)d_in[8];
    const float* w_v    = (const float*)d_in[9];
    const float* w_o    = (const float*)d_in[10];
    float* out = (float*)d_out;

    bf16 *hid, *qlat, *q, *lat, *kf, *qf, *sc, *ctx, *ao;
    bf16 *wqa, *wqb, *wkva, *wk, *wv, *wo, *ckvt;
    cudaGetSymbolAddress((void**)&hid,  g_hid2);
    cudaGetSymbolAddress((void**)&qlat, g_qlat2);
    cudaGetSymbolAddress((void**)&q,    g_q2);
    cudaGetSymbolAddress((void**)&lat,  g_lat2);
    cudaGetSymbolAddress((void**)&kf,   g_kf2);
    cudaGetSymbolAddress((void**)&qf,   g_qf2);
    cudaGetSymbolAddress((void**)&sc,   g_sc2);
    cudaGetSymbolAddress((void**)&ctx,  g_ctx2);
    cudaGetSymbolAddress((void**)&ao,   g_ao2);
    cudaGetSymbolAddress((void**)&wqa,  g_wqa2);
    cudaGetSymbolAddress((void**)&wqb,  g_wqb2);
    cudaGetSymbolAddress((void**)&wkva, g_wkva2);
    cudaGetSymbolAddress((void**)&wk,   g_wk2);
    cudaGetSymbolAddress((void**)&wv,   g_wv2);
    cudaGetSymbolAddress((void**)&wo,   g_wo2);
    cudaGetSymbolAddress((void**)&ckvt, g_ckvt2);

    bf16 *hidL = hid + N_HID,  *qlatL = qlat + N_QLAT, *qL = q + N_Q;
    bf16 *latL = lat + N_LAT,  *kfL = kf + N_KF,       *qfL = qf + N_QF;
    bf16 *scL  = sc + N_SC,    *ctxL = ctx + N_CTX,    *aoL = ao + N_AO;
    bf16 *wqaL = wqa + N_WQA,  *wqbL = wqb + N_WQB,    *wkvaL = wkva + N_WKVA;
    bf16 *wkL  = wk + N_WK,    *wvL = wv + N_WV,       *woL = wo + N_WO;
    bf16 *ckvtL = ckvt + N_CKVT;

    constexpr int SM128 = 4 * (2 * 8192 + 2 * 128 * 64);   // 131072
    constexpr int SM256 = 4 * (2 * 8192 + 2 * 256 * 64);   // 196608
    cudaFuncSetAttribute(mma_gemm<128, 4>, cudaFuncAttributeMaxDynamicSharedMemorySize, SM128);
    cudaFuncSetAttribute(mma_gemm<256, 4>, cudaFuncAttributeMaxDynamicSharedMemorySize, SM256);

    const dim3 tb(32, 8);

    // launch 0
    {
        long long n = (long long)N_HID;
        split_f32<<<(unsigned)((n + 255) / 256), 256>>>(hidden, hid, hidL, n);
    }
    // launch 1
    transpose_split<<<dim3(QL_ / 32, HID_ / 32, 1), tb>>>(w_qa, wqa, wqaL, HID_, QL_, QL_, 0, 0);
    // launch 2: q_lat = hidden @ w_qa
    mma_gemm<128, 4><<<dim3(QL_ / 128, S_ / TILE_M, 1), 256, SM128>>>(
        hid, hidL, wqa, wqaL, qlat, qlatL, nullptr,
        S_, QL_, HID_, HID_, HID_, QL_, 0, 0, 0, 1.f, 0);
    // launch 3
    rmsnorm_q<<<S_, 256>>>(qlat, qlatL, qa_ln);
    // launch 4
    transpose_split<<<dim3(NH_ * QDIM_ / 32, QL_ / 32, 1), tb>>>(w_qb, wqb, wqbL, QL_, NH_ * QDIM_, NH_ * QDIM_, 0, 0);
    // launch 5: q = q_lat @ w_qb   <-- ncu -s 5 -c 1 profiles this GEMM
    mma_gemm<256, 4><<<dim3(NH_ * QDIM_ / 256, S_ / TILE_M, 1), 256, SM256>>>(
        qlat, qlatL, wqb, wqbL, q, qL, nullptr,
        S_, NH_ * QDIM_, QL_, QL_, QL_, NH_ * QDIM_, 0, 0, 0, 1.f, 0);
    // launch 6
    transpose_split<<<dim3(DF_ / 32, HID_ / 32, 1), tb>>>(w_kva, wkva, wkvaL, HID_, DF_, DF_, 0, 0);
    // launch 7: latent = hidden @ w_kva
    mma_gemm<128, 4><<<dim3((DF_ + 127) / 128, S_ / TILE_M, 1), 256, SM128>>>(
        hid, hidL, wkva, wkvaL, lat, latL, nullptr,
        S_, DF_, HID_, HID_, HID_, DF_, 0, 0, 0, 1.f, 0);
    // k_full
    kva_norm_rope<<<S_, 128>>>(lat, latL, kva_ln, cosb, sinb, kf, kfL);
    transpose_bf16<<<dim3(KVL_ / 32, S_ / 32), tb>>>(kf,  ckvt,  S_, KVL_, DF_);
    transpose_bf16<<<dim3(KVL_ / 32, S_ / 32), tb>>>(kfL, ckvtL, S_, KVL_, DF_);
    // rope q_pe
    {
        long long tot = (long long)S_ * NH_ * DR_;
        rope_q<<<(unsigned)((tot + 255) / 256), 256>>>(q, qL, cosb, sinb, qf, qfL);
    }
    // q_abs
    transpose_split<<<dim3(KVL_ / 32, DN_ / 32, NH_), tb>>>(w_k, wk, wkL, DN_, KVL_, KVL_,
        (long long)DN_ * KVL_, (long long)KVL_ * DN_);
    mma_gemm<256, 4><<<dim3(KVL_ / 256, S_ / TILE_M, NH_), 256, SM256>>>(
        q, qL, wk, wkL, qf, qfL, nullptr,
        S_, KVL_, DN_, NH_ * QDIM_, DN_, DF_,
        (long long)QDIM_, (long long)KVL_ * DN_, (long long)S_ * DF_, 1.f, 0);
    // scores (causal skip)
    mma_gemm<256, 4><<<dim3(S_ / 256, S_ / TILE_M, NH_), 256, SM256>>>(
        qf, qfL, kf, kfL, sc, scL, nullptr,
        S_, S_, DF_, DF_, DF_, S_,
        (long long)S_ * DF_, 0LL, (long long)S_ * S_, SM_SCALE_, 1);
    // softmax
    softmax_causal<<<dim3(S_, NH_), 256>>>(sc, scL);
    // ctx (K-limit)
    mma_gemm<256, 4><<<dim3(KVL_ / 256, S_ / TILE_M, NH_), 256, SM256>>>(
        sc, scL, ckvt, ckvtL, ctx, ctxL, nullptr,
        S_, KVL_, S_, S_, S_, KVL_,
        (long long)S_ * S_, 0LL, (long long)S_ * KVL_, 1.f, 2);
    // attn_out
    transpose_split<<<dim3(DV_ / 32, KVL_ / 32, NH_), tb>>>(w_v, wv, wvL, KVL_, DV_, DV_,
        (long long)KVL_ * DV_, (long long)DV_ * KVL_);
    mma_gemm<128, 4><<<dim3(1, S_ / TILE_M, NH_), 256, SM128>>>(
        ctx, ctxL, wv, wvL, ao, aoL, nullptr,
        S_, DV_, KVL_, KVL_, KVL_, NH_ * DV_,
        (long long)S_ * KVL_, (long long)DV_ * KVL_, (long long)DV_, 1.f, 0);
    // out = ao @ w_o
    transpose_split<<<dim3(HID_ / 32, (NH_ * DV_) / 32, 1), tb>>>(w_o, wo, woL, NH_ * DV_, HID_, HID_, 0, 0);
    mma_gemm<256, 4><<<dim3(HID_ / 256, S_ / TILE_M, 1), 256, SM256>>>(
        ao, aoL, wo, woL, nullptr, nullptr, out,
        S_, HID_, NH_ * DV_, NH_ * DV_, NH_ * DV_, HID_, 0, 0, 0, 1.f, 4);
}

// round 8
// speedup vs baseline: 3.7567x; 1.0129x over previous
#include <cuda_runtime.h>
#include <cuda_bf16.h>
#include <cstdint>
#include <math.h>

#define S_    1536
#define HID_  6144
#define NH_   64
#define DN_   128
#define DR_   64
#define DV_   128
#define QL_   1536
#define KVL_  512
#define DF_   576        // KVL + DR
#define QDIM_ 192        // DN + DR

#define SM_SCALE_  0.07216878364870322f
#define SCALE_Q_   2.0f
#define SCALE_KV_  3.4641016151377544f

#define TILE_M 128
#define KC     32

typedef __nv_bfloat16 bf16;

// ---------------- scratch: activations/weights as (hi, lo) bf16 pairs -------
#define N_HID  ((size_t)S_ * HID_)
#define N_QLAT ((size_t)S_ * QL_)
#define N_Q    ((size_t)S_ * NH_ * QDIM_)
#define N_LAT  ((size_t)S_ * DF_)
#define N_KF   ((size_t)S_ * DF_)
#define N_QF   ((size_t)NH_ * S_ * DF_)
#define N_SC   ((size_t)NH_ * S_ * S_)
#define N_CTX  ((size_t)NH_ * S_ * KVL_)
#define N_AO   ((size_t)S_ * NH_ * DV_)
#define N_WQA  ((size_t)QL_ * HID_)
#define N_WQB  ((size_t)NH_ * QDIM_ * QL_)
#define N_WKVA ((size_t)DF_ * HID_)
#define N_WK   ((size_t)NH_ * KVL_ * DN_)
#define N_WV   ((size_t)NH_ * DV_ * KVL_)
#define N_WO   ((size_t)HID_ * NH_ * DV_)
#define N_CKVT ((size_t)KVL_ * S_)

__device__ __align__(256) unsigned short g_hid2 [2 * N_HID];
__device__ __align__(256) unsigned short g_qlat2[2 * N_QLAT];
__device__ __align__(256) unsigned short g_q2   [2 * N_Q];
__device__ __align__(256) unsigned short g_lat2 [2 * N_LAT];
__device__ __align__(256) unsigned short g_kf2  [2 * N_KF];
__device__ __align__(256) unsigned short g_qf2  [2 * N_QF];
__device__ __align__(256) unsigned short g_sc2  [2 * N_SC];
__device__ __align__(256) float          g_scf  [N_SC];        // fp32 raw scores
__device__ __align__(256) unsigned short g_ctx2 [2 * N_CTX];
__device__ __align__(256) unsigned short g_ao2  [2 * N_AO];
__device__ __align__(256) unsigned short g_wqa2 [2 * N_WQA];
__device__ __align__(256) unsigned short g_wqb2 [2 * N_WQB];
__device__ __align__(256) unsigned short g_wkva2[2 * N_WKVA];
__device__ __align__(256) unsigned short g_wk2  [2 * N_WK];
__device__ __align__(256) unsigned short g_wv2  [2 * N_WV];
__device__ __align__(256) unsigned short g_wo2  [2 * N_WO];
__device__ __align__(256) unsigned short g_ckvt2[2 * N_CKVT];

// ---------------- helpers ----------------------------------------------------
__device__ __forceinline__ uint32_t smem_u32(const void* p) {
    uint32_t a;
    asm("{ .reg .u64 t; cvta.to.shared.u64 t, %1; cvt.u32.u64 %0, t; }" : "=r"(a) : "l"(p));
    return a;
}
#define CP_ASYNC16(dst, src, sz) \
    asm volatile("cp.async.cg.shared.global [%0], [%1], 16, %2;" :: "r"(dst), "l"(src), "r"(sz))
#define CP_COMMIT() asm volatile("cp.async.commit_group;" ::: "memory")
#define CP_WAIT(n)  asm volatile("cp.async.wait_group %0;" :: "n"(n) : "memory")

#define LDSM4(r0, r1, r2, r3, a) \
    asm volatile("ldmatrix.sync.aligned.m8n8.x4.shared.b16 {%0,%1,%2,%3}, [%4];" \
                 : "=r"(r0), "=r"(r1), "=r"(r2), "=r"(r3) : "r"(a))

__device__ __forceinline__ void mma_bf16(float* d, const unsigned* a, const unsigned* b) {
    asm volatile(
        "mma.sync.aligned.m16n8k16.row.col.f32.bf16.bf16.f32 "
        "{%0,%1,%2,%3}, {%4,%5,%6,%7}, {%8,%9}, {%0,%1,%2,%3};"
        : "+f"(d[0]), "+f"(d[1]), "+f"(d[2]), "+f"(d[3])
        : "r"(a[0]), "r"(a[1]), "r"(a[2]), "r"(a[3]), "r"(b[0]), "r"(b[1]));
}

__device__ __forceinline__ uint32_t off_swz(int row, int kc) {
    return (uint32_t)(row >> 1) * 128u +
           (uint32_t)(((((row & 1) << 2) + kc) ^ ((row >> 1) & 7)) * 16);
}

__device__ __forceinline__ float pget(const bf16* h, const bf16* l, long long i) {
    return __bfloat162float(h[i]) + __bfloat162float(l[i]);
}
__device__ __forceinline__ void pset(bf16* h, bf16* l, long long i, float v) {
    bf16 a = __float2bfloat16(v);
    h[i] = a;
    l[i] = __float2bfloat16(v - __bfloat162float(a));
}
__device__ __forceinline__ void unpack2(unsigned h, unsigned l, float& a, float& b) {
    a = __uint_as_float(h << 16) + __uint_as_float(l << 16);
    b = __uint_as_float(h & 0xffff0000u) + __uint_as_float(l & 0xffff0000u);
}
__device__ __forceinline__ void pack2(float a, float b, unsigned& h, unsigned& l) {
    bf16 ha = __float2bfloat16(a), hb = __float2bfloat16(b);
    bf16 la = __float2bfloat16(a - __bfloat162float(ha));
    bf16 lb = __float2bfloat16(b - __bfloat162float(hb));
    __nv_bfloat162 hv; hv.x = ha; hv.y = hb;
    __nv_bfloat162 lv; lv.x = la; lv.y = lb;
    h = *reinterpret_cast<unsigned*>(&hv);
    l = *reinterpret_cast<unsigned*>(&lv);
}

// flags: bit0 = causal tile skip, bit1 = K limited to row0+128, bit2 = fp32 C
template <int TN, int NSTAGE>
__global__ __launch_bounds__(256, 1) void mma_gemm(
    const bf16* __restrict__ Ahi, const bf16* __restrict__ Alo,
    const bf16* __restrict__ Bhi, const bf16* __restrict__ Blo,
    bf16* __restrict__ Chi, bf16* __restrict__ Clo, float* __restrict__ Cf,
    int M, int N, int K, int lda, int ldb, int ldc,
    long long sA, long long sB, long long sC, float alpha, int flags)
{
    constexpr uint32_t BUFA = 8192u;
    constexpr uint32_t BUFB = (uint32_t)TN * 64u;
    constexpr uint32_t STB  = 2u * BUFA + 2u * BUFB;
    constexpr int NFR = TN / 32;
    constexpr int NLD = TN / 64;

    const int row0 = blockIdx.y * TILE_M;
    const int col0 = blockIdx.x * TN;
    if ((flags & 1) && col0 >= row0 + TILE_M) return;

    const long long bz = blockIdx.z;
    Ahi += bz * sA;  Alo += bz * sA;
    Bhi += bz * sB;  Blo += bz * sB;
    if (flags & 4) Cf += bz * sC; else { Chi += bz * sC; Clo += bz * sC; }

    const int Keff = (flags & 2) ? min(K, row0 + TILE_M) : K;
    const int KT = Keff / KC;

    extern __shared__ char smraw[];
    const uint32_t sbase = smem_u32(smraw);
    const int tid  = threadIdx.x;
    const int wid  = tid >> 5;
    const int lane = tid & 31;
    const int g    = lane >> 2;
    const int c    = lane & 3;
    const int m0   = (wid & 1) * 64;
    const int n0   = (wid >> 1) * (TN / 4);

    const int am_l = (lane & 7) + ((lane >> 3) & 1) * 8;
    const int ak_l = lane >> 4;
    const int bn_l = (lane & 7) + ((lane >> 4) & 1) * 8;
    const int bk_l = (lane >> 3) & 1;

    auto load_stage = [&](int kt) {
        const uint32_t base = sbase + (uint32_t)(kt % NSTAGE) * STB;
        const bf16* AgH = Ahi + (long long)row0 * lda + (long long)kt * KC;
        const bf16* AgL = Alo + (long long)row0 * lda + (long long)kt * KC;
        const bf16* BgH = Bhi + (long long)kt * KC;
        const bf16* BgL = Blo + (long long)kt * KC;
#pragma unroll
        for (int j = 0; j < 2; j++) {
            const int i  = tid + j * 256;
            const int m  = i >> 2;
            const int kc = i & 3;
            const uint32_t so = off_swz(m, kc);
            CP_ASYNC16(base + so,        AgH + (long long)m * lda + kc * 8, 16);
            CP_ASYNC16(base + BUFA + so, AgL + (long long)m * lda + kc * 8, 16);
        }
#pragma unroll
        for (int j = 0; j < TN / 64; j++) {
            const int i  = tid + j * 256;
            const int m  = i >> 2;
            const int kc = i & 3;
            const uint32_t so = off_swz(m, kc);
            const int n = col0 + m;
            const long long bo = (long long)(n < N ? n : 0) * ldb + kc * 8;
            const int sz = (n < N) ? 16 : 0;
            CP_ASYNC16(base + 2 * BUFA + so,        BgH + bo, sz);
            CP_ASYNC16(base + 2 * BUFA + BUFB + so, BgL + bo, sz);
        }
        CP_COMMIT();
    };

    float acc[4][NFR][4];
#pragma unroll
    for (int i = 0; i < 4; i++)
#pragma unroll
        for (int j = 0; j < NFR; j++)
#pragma unroll
            for (int e = 0; e < 4; e++) acc[i][j][e] = 0.f;

    const int PRE = (KT < NSTAGE - 1) ? KT : (NSTAGE - 1);
    for (int kt = 0; kt < PRE; kt++) load_stage(kt);

    for (int kt = 0; kt < KT; kt++) {
        CP_WAIT(NSTAGE - 2);
        __syncthreads();
        const int pf = kt + NSTAGE - 1;
        if (pf < KT) load_stage(pf); else CP_COMMIT();

        const uint32_t sb   = sbase + (uint32_t)(kt % NSTAGE) * STB;
        const uint32_t aHiB = sb;
        const uint32_t aLoB = sb + BUFA;
        const uint32_t bHiB = sb + 2 * BUFA;
        const uint32_t bLoB = sb + 2 * BUFA + BUFB;

#pragma unroll
        for (int ks = 0; ks < 2; ks++) {
            const int kcb = ks * 2;
            unsigned ah[4][4], al[4][4], bh[NFR][2], bl[NFR][2];
#pragma unroll
            for (int hB = 0; hB < NLD; hB++) {
                const uint32_t so = off_swz(n0 + hB * 16 + bn_l, kcb + bk_l);
                LDSM4(bh[2*hB][0], bh[2*hB][1], bh[2*hB+1][0], bh[2*hB+1][1], bHiB + so);
                LDSM4(bl[2*hB][0], bl[2*hB][1], bl[2*hB+1][0], bl[2*hB+1][1], bLoB + so);
            }
#pragma unroll
            for (int mi = 0; mi < 4; mi++) {
                const uint32_t so = off_swz(m0 + mi * 16 + am_l, kcb + ak_l);
                LDSM4(ah[mi][0], ah[mi][1], ah[mi][2], ah[mi][3], aHiB + so);
                LDSM4(al[mi][0], al[mi][1], al[mi][2], al[mi][3], aLoB + so);
            }
#pragma unroll
            for (int mi = 0; mi < 4; mi++)
#pragma unroll
                for (int ni = 0; ni < NFR; ni++) {
                    mma_bf16(acc[mi][ni], ah[mi], bh[ni]);
                    mma_bf16(acc[mi][ni], ah[mi], bl[ni]);
                    mma_bf16(acc[mi][ni], al[mi], bh[ni]);
                }
        }
    }
    CP_WAIT(0);

    // ---------------- epilogue -----------------------------------------------
#pragma unroll
    for (int mi = 0; mi < 4; mi++) {
#pragma unroll
        for (int ni = 0; ni < NFR; ni++) {
            const int n = col0 + n0 + ni * 8 + 2 * c;
#pragma unroll
            for (int h = 0; h < 2; h++) {
                const int r = row0 + m0 + mi * 16 + g + h * 8;
                float v0 = alpha * acc[mi][ni][2 * h];
                float v1 = alpha * acc[mi][ni][2 * h + 1];
                if (flags & 4) {
                    if (n + 1 < N)
                        *reinterpret_cast<float2*>(&Cf[(long long)r * ldc + n]) =
                            make_float2(v0, v1);
                    else if (n < N) Cf[(long long)r * ldc + n] = v0;
                } else {
                    unsigned uh, ul;
                    pack2(v0, v1, uh, ul);
                    const long long o = (long long)r * ldc + n;
                    if (n + 1 < N) {
                        *reinterpret_cast<unsigned*>(&Chi[o]) = uh;
                        *reinterpret_cast<unsigned*>(&Clo[o]) = ul;
                    } else if (n < N) {
                        Chi[o] = __float2bfloat16(v0);
                        Clo[o] = __float2bfloat16(v0 - __bfloat162float(__float2bfloat16(v0)));
                    }
                }
            }
        }
    }
}

// ---------------- fp32 -> (hi, lo) split -------------------------------------
__global__ void split_f32(const float* __restrict__ x, bf16* __restrict__ hi,
                          bf16* __restrict__ lo, long long n)
{
    long long i = (long long)blockIdx.x * blockDim.x + threadIdx.x;
    if (i >= n) return;
    float v = x[i];
    bf16 h = __float2bfloat16(v);
    hi[i] = h;
    lo[i] = __float2bfloat16(v - __bfloat162float(h));
}

// ---------------- fp32 transpose -> K-major (hi, lo) -------------------------
__global__ void transpose_split(const float* __restrict__ X, bf16* __restrict__ Thi,
                                bf16* __restrict__ Tlo, int R, int C, int ldx,
                                long long sX, long long sT)
{
    __shared__ float t[32][33];
    X   += (long long)blockIdx.z * sX;
    Thi += (long long)blockIdx.z * sT;
    Tlo += (long long)blockIdx.z * sT;
    const int c0 = blockIdx.x * 32, r0 = blockIdx.y * 32;
    const int tx = threadIdx.x, ty = threadIdx.y;
#pragma unroll
    for (int i = 0; i < 32; i += 8) {
        int r = r0 + ty + i;
        if (r < R && c0 + tx < C) t[ty + i][tx] = X[(long long)r * ldx + c0 + tx];
    }
    __syncthreads();
#pragma unroll
    for (int i = 0; i < 32; i += 8) {
        int cc = c0 + ty + i;
        if (cc < C && r0 + tx < R) {
            float v = t[tx][ty + i];
            long long o = (long long)cc * R + r0 + tx;
            bf16 h = __float2bfloat16(v);
            Thi[o] = h;
            Tlo[o] = __float2bfloat16(v - __bfloat162float(h));
        }
    }
}

// ---------------- bf16 transpose ---------------------------------------------
__global__ void transpose_bf16(const bf16* __restrict__ X, bf16* __restrict__ T,
                               int R, int C, int ldx)
{
    __shared__ bf16 t[32][33];
    const int c0 = blockIdx.x * 32, r0 = blockIdx.y * 32;
    const int tx = threadIdx.x, ty = threadIdx.y;
#pragma unroll
    for (int i = 0; i < 32; i += 8) {
        int r = r0 + ty + i;
        if (r < R && c0 + tx < C) t[ty + i][tx] = X[(long long)r * ldx + c0 + tx];
    }
    __syncthreads();
#pragma unroll
    for (int i = 0; i < 32; i += 8) {
        int cc = c0 + ty + i;
        if (cc < C && r0 + tx < R) T[(long long)cc * R + r0 + tx] = t[tx][ty + i];
    }
}

// ---------------- RMSNorm (pair in place, vectorized) -----------------------
__global__ __launch_bounds__(256) void rmsnorm_q(bf16* __restrict__ xh,
                                                 bf16* __restrict__ xl,
                                                 const float* __restrict__ w)
{
    const int s = blockIdx.x;
    const long long base = (long long)s * QL_;
    const int tid = threadIdx.x;
    const int t = tid * 8;                 // 192 of 256 threads active (QL=1536)
    __shared__ float red[256];
    float f[8];
    float ss = 0.f;
    if (t < QL_) {
        uint4 vh = *reinterpret_cast<const uint4*>(&xh[base + t]);
        uint4 vl = *reinterpret_cast<const uint4*>(&xl[base + t]);
        unpack2(vh.x, vl.x, f[0], f[1]);
        unpack2(vh.y, vl.y, f[2], f[3]);
        unpack2(vh.z, vl.z, f[4], f[5]);
        unpack2(vh.w, vl.w, f[6], f[7]);
#pragma unroll
        for (int j = 0; j < 8; j++) ss += f[j] * f[j];
    }
    red[tid] = ss; __syncthreads();
    for (int off = 128; off > 0; off >>= 1) {
        if (tid < off) red[tid] += red[tid + off];
        __syncthreads();
    }
    const float inv = rsqrtf(red[0] / QL_ + 1e-6f) * SCALE_Q_;
    if (t < QL_) {
        unsigned uh[4], ul[4];
#pragma unroll
        for (int p = 0; p < 4; p++) {
            float a = w[t + 2 * p] * f[2 * p] * inv;
            float b = w[t + 2 * p + 1] * f[2 * p + 1] * inv;
            pack2(a, b, uh[p], ul[p]);
        }
        *reinterpret_cast<uint4*>(&xh[base + t]) = make_uint4(uh[0], uh[1], uh[2], uh[3]);
        *reinterpret_cast<uint4*>(&xl[base + t]) = make_uint4(ul[0], ul[1], ul[2], ul[3]);
    }
}

// ---------------- kva RMSNorm + k_pe RoPE -> k_full (pairs) ------------------
__global__ void kva_norm_rope(const bf16* __restrict__ lh, const bf16* __restrict__ ll,
                              const float* __restrict__ w,
                              const float* __restrict__ cosb, const float* __restrict__ sinb,
                              bf16* __restrict__ kh, bf16* __restrict__ kl)
{
    const int s = blockIdx.x;
    const int tid = threadIdx.x;           // 128 threads
    const long long base = (long long)s * DF_;
    __shared__ float red[128];
    float ss = 0.f;
    for (int j = tid; j < KVL_; j += 128) { float v = pget(lh, ll, base + j); ss += v * v; }
    red[tid] = ss; __syncthreads();
    for (int off = 64; off > 0; off >>= 1) {
        if (tid < off) red[tid] += red[tid + off];
        __syncthreads();
    }
    const float inv = rsqrtf(red[0] / KVL_ + 1e-6f) * SCALE_KV_;
    for (int j = tid; j < KVL_; j += 128)
        pset(kh, kl, base + j, w[j] * pget(lh, ll, base + j) * inv);
    if (tid < DR_) {
        const int r = tid;
        float x = pget(lh, ll, base + KVL_ + r);
        float o = (r < 32) ? -pget(lh, ll, base + KVL_ + r + 32)
                           :  pget(lh, ll, base + KVL_ + r - 32);
        pset(kh, kl, base + KVL_ + r, x * cosb[s * DR_ + r] + o * sinb[s * DR_ + r]);
    }
}

// ---------------- q_pe RoPE -> q_full[h][s][512+r] (pairs) -------------------
__global__ void rope_q(const bf16* __restrict__ qh, const bf16* __restrict__ ql,
                       const float* __restrict__ cosb, const float* __restrict__ sinb,
                       bf16* __restrict__ fh, bf16* __restrict__ fl)
{
    long long idx = (long long)blockIdx.x * blockDim.x + threadIdx.x;
    if (idx >= (long long)S_ * NH_ * DR_) return;
    const int r = (int)(idx % DR_);
    const int h = (int)((idx / DR_) % NH_);
    const int s = (int)(idx / ((long long)DR_ * NH_));
    const long long qb = (long long)s * NH_ * QDIM_ + h * QDIM_ + DN_;
    float x = pget(qh, ql, qb + r);
    float o = (r < 32) ? -pget(qh, ql, qb + r + 32) : pget(qh, ql, qb + r - 32);
    pset(fh, fl, ((long long)h * S_ + s) * DF_ + KVL_ + r,
         x * cosb[s * DR_ + r] + o * sinb[s * DR_ + r]);
}

// ------- causal softmax: fp32 in, (hi,lo) pairs out, smem row cache ----------
__global__ __launch_bounds__(256) void softmax_causal(const float* __restrict__ sf,
                                                      bf16* __restrict__ sh,
                                                      bf16* __restrict__ sl)
{
    const int s = blockIdx.x, h = blockIdx.y;
    const long long base = ((long long)h * S_ + s) * (long long)S_;
    __shared__ float vals[S_];
    __shared__ float red[256];
    const int tid = threadIdx.x;
    const int len = s + 1;
    const int len4 = len & ~3;

    float m = -1e30f;
    for (int t = tid * 4; t < len4; t += 1024) {
        float4 v = *reinterpret_cast<const float4*>(&sf[base + t]);
        vals[t] = v.x; vals[t + 1] = v.y; vals[t + 2] = v.z; vals[t + 3] = v.w;
        m = fmaxf(fmaxf(m, fmaxf(v.x, v.y)), fmaxf(v.z, v.w));
    }
    for (int t = len4 + tid; t < len; t += 256) {
        float v = sf[base + t];
        vals[t] = v; m = fmaxf(m, v);
    }
    red[tid] = m; __syncthreads();
    for (int off = 128; off > 0; off >>= 1) {
        if (tid < off) red[tid] = fmaxf(red[tid], red[tid + off]);
        __syncthreads();
    }
    m = red[0]; __syncthreads();

    float sum = 0.f;
    for (int t = tid; t < len; t += 256) {
        float e = __expf(vals[t] - m);
        vals[t] = e; sum += e;
    }
    red[tid] = sum; __syncthreads();
    for (int off = 128; off > 0; off >>= 1) {
        if (tid < off) red[tid] += red[tid + off];
        __syncthreads();
    }
    const float inv = 1.f / red[0];

    const int rowEnd = (s & ~(TILE_M - 1)) + TILE_M;   // ctx GEMM reads k < rowEnd
    for (int t = tid * 8; t < rowEnd; t += 2048) {
        unsigned uh[4], ul[4];
#pragma unroll
        for (int p = 0; p < 4; p++) {
            float a = (t + 2 * p     < len) ? vals[t + 2 * p] * inv : 0.f;
            float b = (t + 2 * p + 1 < len) ? vals[t + 2 * p + 1] * inv : 0.f;
            pack2(a, b, uh[p], ul[p]);
        }
        *reinterpret_cast<uint4*>(&sh[base + t]) = make_uint4(uh[0], uh[1], uh[2], uh[3]);
        *reinterpret_cast<uint4*>(&sl[base + t]) = make_uint4(ul[0], ul[1], ul[2], ul[3]);
    }
}

// =============================================================================
extern "C" void kernel_launch(void* const* d_in, const int* in_sizes, int n_in,
                              void* d_out, int out_size)
{
    const float* hidden = (const float*)d_in[0];
    const float* cosb   = (const float*)d_in[1];
    const float* sinb   = (const float*)d_in[2];
    const float* w_qa   = (const float*)d_in[3];
    const float* qa_ln  = (const float*)d_in[4];
    const float* w_qb   = (const float*)d_in[5];
    const float* w_kva  = (const float*)d_in[6];
    const float* kva_ln = (const float*)d_in[7];
    const float* w_k    = (const float*)d_in[8];
    const float* w_v    = (const float*)d_in[9];
    const float* w_o    = (const float*)d_in[10];
    float* out = (float*)d_out;

    bf16 *hid, *qlat, *q, *lat, *kf, *qf, *sc, *ctx, *ao;
    bf16 *wqa, *wqb, *wkva, *wk, *wv, *wo, *ckvt;
    float *scf;
    cudaGetSymbolAddress((void**)&hid,  g_hid2);
    cudaGetSymbolAddress((void**)&qlat, g_qlat2);
    cudaGetSymbolAddress((void**)&q,    g_q2);
    cudaGetSymbolAddress((void**)&lat,  g_lat2);
    cudaGetSymbolAddress((void**)&kf,   g_kf2);
    cudaGetSymbolAddress((void**)&qf,   g_qf2);
    cudaGetSymbolAddress((void**)&sc,   g_sc2);
    cudaGetSymbolAddress((void**)&scf,  g_scf);
    cudaGetSymbolAddress((void**)&ctx,  g_ctx2);
    cudaGetSymbolAddress((void**)&ao,   g_ao2);
    cudaGetSymbolAddress((void**)&wqa,  g_wqa2);
    cudaGetSymbolAddress((void**)&wqb,  g_wqb2);
    cudaGetSymbolAddress((void**)&wkva, g_wkva2);
    cudaGetSymbolAddress((void**)&wk,   g_wk2);
    cudaGetSymbolAddress((void**)&wv,   g_wv2);
    cudaGetSymbolAddress((void**)&wo,   g_wo2);
    cudaGetSymbolAddress((void**)&ckvt, g_ckvt2);

    bf16 *hidL = hid + N_HID,  *qlatL = qlat + N_QLAT, *qL = q + N_Q;
    bf16 *latL = lat + N_LAT,  *kfL = kf + N_KF,       *qfL = qf + N_QF;
    bf16 *scL  = sc + N_SC,    *ctxL = ctx + N_CTX,    *aoL = ao + N_AO;
    bf16 *wqaL = wqa + N_WQA,  *wqbL = wqb + N_WQB,    *wkvaL = wkva + N_WKVA;
    bf16 *wkL  = wk + N_WK,    *wvL = wv + N_WV,       *woL = wo + N_WO;
    bf16 *ckvtL = ckvt + N_CKVT;

    constexpr int SM128 = 5 * (2 * 8192 + 2 * 128 * 64);   // 163840
    constexpr int SM256 = 4 * (2 * 8192 + 2 * 256 * 64);   // 196608
    cudaFuncSetAttribute(mma_gemm<128, 5>, cudaFuncAttributeMaxDynamicSharedMemorySize, SM128);
    cudaFuncSetAttribute(mma_gemm<256, 4>, cudaFuncAttributeMaxDynamicSharedMemorySize, SM256);

    const dim3 tb(32, 8);

    // launch 0, 1: weight transposes (input-only deps)
    transpose_split<<<dim3(QL_ / 32, HID_ / 32, 1), tb>>>(w_qa, wqa, wqaL, HID_, QL_, QL_, 0, 0);
    transpose_split<<<dim3(NH_ * QDIM_ / 32, QL_ / 32, 1), tb>>>(w_qb, wqb, wqbL, QL_, NH_ * QDIM_, NH_ * QDIM_, 0, 0);
    // launch 2: split hidden
    {
        long long n = (long long)N_HID;
        split_f32<<<(unsigned)((n + 255) / 256), 256>>>(hidden, hid, hidL, n);
    }
    // launch 3: q_lat = hidden @ w_qa   <-- observed profile slot
    mma_gemm<128, 5><<<dim3(QL_ / 128, S_ / TILE_M, 1), 256, SM128>>>(
        hid, hidL, wqa, wqaL, qlat, qlatL, nullptr,
        S_, QL_, HID_, HID_, HID_, QL_, 0, 0, 0, 1.f, 0);
    // launch 4
    rmsnorm_q<<<S_, 256>>>(qlat, qlatL, qa_ln);
    // launch 5: q = q_lat @ w_qb
    mma_gemm<256, 4><<<dim3(NH_ * QDIM_ / 256, S_ / TILE_M, 1), 256, SM256>>>(
        qlat, qlatL, wqb, wqbL, q, qL, nullptr,
        S_, NH_ * QDIM_, QL_, QL_, QL_, NH_ * QDIM_, 0, 0, 0, 1.f, 0);
    // latent path
    transpose_split<<<dim3(DF_ / 32, HID_ / 32, 1), tb>>>(w_kva, wkva, wkvaL, HID_, DF_, DF_, 0, 0);
    mma_gemm<128, 5><<<dim3((DF_ + 127) / 128, S_ / TILE_M, 1), 256, SM128>>>(
        hid, hidL, wkva, wkvaL, lat, latL, nullptr,
        S_, DF_, HID_, HID_, HID_, DF_, 0, 0, 0, 1.f, 0);
    kva_norm_rope<<<S_, 128>>>(lat, latL, kva_ln, cosb, sinb, kf, kfL);
    transpose_bf16<<<dim3(KVL_ / 32, S_ / 32), tb>>>(kf,  ckvt,  S_, KVL_, DF_);
    transpose_bf16<<<dim3(KVL_ / 32, S_ / 32), tb>>>(kfL, ckvtL, S_, KVL_, DF_);
    // rope q_pe
    {
        long long tot = (long long)S_ * NH_ * DR_;
        rope_q<<<(unsigned)((tot + 255) / 256), 256>>>(q, qL, cosb, sinb, qf, qfL);
    }
    // q_abs
    transpose_split<<<dim3(KVL_ / 32, DN_ / 32, NH_), tb>>>(w_k, wk, wkL, DN_, KVL_, KVL_,
        (long long)DN_ * KVL_, (long long)KVL_ * DN_);
    mma_gemm<256, 4><<<dim3(KVL_ / 256, S_ / TILE_M, NH_), 256, SM256>>>(
        q, qL, wk, wkL, qf, qfL, nullptr,
        S_, KVL_, DN_, NH_ * QDIM_, DN_, DF_,
        (long long)QDIM_, (long long)KVL_ * DN_, (long long)S_ * DF_, 1.f, 0);
    // scores -> fp32 (causal skip)
    mma_gemm<256, 4><<<dim3(S_ / 256, S_ / TILE_M, NH_), 256, SM256>>>(
        qf, qfL, kf, kfL, nullptr, nullptr, scf,
        S_, S_, DF_, DF_, DF_, S_,
        (long long)S_ * DF_, 0LL, (long long)S_ * S_, SM_SCALE_, 1 | 4);
    // softmax: fp32 -> pairs
    softmax_causal<<<dim3(S_, NH_), 256>>>(scf, sc, scL);
    // ctx (K-limit)
    mma_gemm<256, 4><<<dim3(KVL_ / 256, S_ / TILE_M, NH_), 256, SM256>>>(
        sc, scL, ckvt, ckvtL, ctx, ctxL, nullptr,
        S_, KVL_, S_, S_, S_, KVL_,
        (long long)S_ * S_, 0LL, (long long)S_ * KVL_, 1.f, 2);
    // attn_out
    transpose_split<<<dim3(DV_ / 32, KVL_ / 32, NH_), tb>>>(w_v, wv, wvL, KVL_, DV_, DV_,
        (long long)KVL_ * DV_, (long long)DV_ * KVL_);
    mma_gemm<128, 5><<<dim3(1, S_ / TILE_M, NH_), 256, SM128>>>(
        ctx, ctxL, wv, wvL, ao, aoL, nullptr,
        S_, DV_, KVL_, KVL_, KVL_, NH_ * DV_,
        (long long)S_ * KVL_, (long long)DV_ * KVL_, (long long)DV_, 1.f, 0);
    // out = ao @ w_o
    transpose_split<<<dim3(HID_ / 32, (NH_ * DV_) / 32, 1), tb>>>(w_o, wo, woL, NH_ * DV_, HID_, HID_, 0, 0);
    mma_gemm<256, 4><<<dim3(HID_ / 256, S_ / TILE_M, 1), 256, SM256>>>(
        ao, aoL, wo, woL, nullptr, nullptr, out,
        S_, HID_, NH_ * DV_, NH_ * DV_, NH_ * DV_, HID_, 0, 0, 0, 1.f, 4);
}

// round 9
// speedup vs baseline: 4.0016x; 1.0652x over previous
#include <cuda_runtime.h>
#include <cuda_bf16.h>
#include <cstdint>
#include <math.h>

#define S_    1536
#define HID_  6144
#define NH_   64
#define DN_   128
#define DR_   64
#define DV_   128
#define QL_   1536
#define KVL_  512
#define DF_   576        // KVL + DR
#define QDIM_ 192        // DN + DR

#define SM_SCALE_  0.07216878364870322f
#define SCALE_Q_   2.0f
#define SCALE_KV_  3.4641016151377544f

#define KC 32

typedef __nv_bfloat16 bf16;

// ---------------- scratch: activations/weights as (hi, lo) bf16 pairs -------
#define N_HID  ((size_t)S_ * HID_)
#define N_QLAT ((size_t)S_ * QL_)
#define N_Q    ((size_t)S_ * NH_ * QDIM_)
#define N_LAT  ((size_t)S_ * DF_)
#define N_KF   ((size_t)S_ * DF_)
#define N_QF   ((size_t)NH_ * S_ * DF_)
#define N_SC   ((size_t)NH_ * S_ * S_)
#define N_CTX  ((size_t)NH_ * S_ * KVL_)
#define N_AO   ((size_t)S_ * NH_ * DV_)
#define N_WQA  ((size_t)QL_ * HID_)
#define N_WQB  ((size_t)NH_ * QDIM_ * QL_)
#define N_WKVA ((size_t)DF_ * HID_)
#define N_WK   ((size_t)NH_ * KVL_ * DN_)
#define N_WV   ((size_t)NH_ * DV_ * KVL_)
#define N_WO   ((size_t)HID_ * NH_ * DV_)
#define N_CKVT ((size_t)KVL_ * S_)

__device__ __align__(256) unsigned short g_hid2 [2 * N_HID];
__device__ __align__(256) unsigned short g_qlat2[2 * N_QLAT];
__device__ __align__(256) unsigned short g_q2   [2 * N_Q];
__device__ __align__(256) unsigned short g_lat2 [2 * N_LAT];
__device__ __align__(256) unsigned short g_kf2  [2 * N_KF];
__device__ __align__(256) unsigned short g_qf2  [2 * N_QF];
__device__ __align__(256) unsigned short g_sc2  [2 * N_SC];
__device__ __align__(256) float          g_scf  [N_SC];
__device__ __align__(256) unsigned short g_ctx2 [2 * N_CTX];
__device__ __align__(256) unsigned short g_ao2  [2 * N_AO];
__device__ __align__(256) unsigned short g_wqa2 [2 * N_WQA];
__device__ __align__(256) unsigned short g_wqb2 [2 * N_WQB];
__device__ __align__(256) unsigned short g_wkva2[2 * N_WKVA];
__device__ __align__(256) unsigned short g_wk2  [2 * N_WK];
__device__ __align__(256) unsigned short g_wv2  [2 * N_WV];
__device__ __align__(256) unsigned short g_wo2  [2 * N_WO];
__device__ __align__(256) unsigned short g_ckvt2[2 * N_CKVT];

// ---------------- helpers ----------------------------------------------------
__device__ __forceinline__ uint32_t smem_u32(const void* p) {
    uint32_t a;
    asm("{ .reg .u64 t; cvta.to.shared.u64 t, %1; cvt.u32.u64 %0, t; }" : "=r"(a) : "l"(p));
    return a;
}
#define CP_ASYNC16(dst, src, sz) \
    asm volatile("cp.async.cg.shared.global [%0], [%1], 16, %2;" :: "r"(dst), "l"(src), "r"(sz))
#define CP_COMMIT() asm volatile("cp.async.commit_group;" ::: "memory")
#define CP_WAIT(n)  asm volatile("cp.async.wait_group %0;" :: "n"(n) : "memory")

#define LDSM4(r0, r1, r2, r3, a) \
    asm volatile("ldmatrix.sync.aligned.m8n8.x4.shared.b16 {%0,%1,%2,%3}, [%4];" \
                 : "=r"(r0), "=r"(r1), "=r"(r2), "=r"(r3) : "r"(a))

__device__ __forceinline__ void mma_bf16(float* d, const unsigned* a, const unsigned* b) {
    asm volatile(
        "mma.sync.aligned.m16n8k16.row.col.f32.bf16.bf16.f32 "
        "{%0,%1,%2,%3}, {%4,%5,%6,%7}, {%8,%9}, {%0,%1,%2,%3};"
        : "+f"(d[0]), "+f"(d[1]), "+f"(d[2]), "+f"(d[3])
        : "r"(a[0]), "r"(a[1]), "r"(a[2]), "r"(a[3]), "r"(b[0]), "r"(b[1]));
}

__device__ __forceinline__ uint32_t off_swz(int row, int kc) {
    return (uint32_t)(row >> 1) * 128u +
           (uint32_t)(((((row & 1) << 2) + kc) ^ ((row >> 1) & 7)) * 16);
}

__device__ __forceinline__ float pget(const bf16* h, const bf16* l, long long i) {
    return __bfloat162float(h[i]) + __bfloat162float(l[i]);
}
__device__ __forceinline__ void pset(bf16* h, bf16* l, long long i, float v) {
    bf16 a = __float2bfloat16(v);
    h[i] = a;
    l[i] = __float2bfloat16(v - __bfloat162float(a));
}
__device__ __forceinline__ void unpack2(unsigned h, unsigned l, float& a, float& b) {
    a = __uint_as_float(h << 16) + __uint_as_float(l << 16);
    b = __uint_as_float(h & 0xffff0000u) + __uint_as_float(l & 0xffff0000u);
}
__device__ __forceinline__ void pack2(float a, float b, unsigned& h, unsigned& l) {
    bf16 ha = __float2bfloat16(a), hb = __float2bfloat16(b);
    bf16 la = __float2bfloat16(a - __bfloat162float(ha));
    bf16 lb = __float2bfloat16(b - __bfloat162float(hb));
    __nv_bfloat162 hv; hv.x = ha; hv.y = hb;
    __nv_bfloat162 lv; lv.x = la; lv.y = lb;
    h = *reinterpret_cast<unsigned*>(&hv);
    l = *reinterpret_cast<unsigned*>(&lv);
}

// flags: bit0 = causal tile skip, bit1 = K limited to row0+TM, bit2 = fp32 C
// 2 CTAs/SM: NSTAGE=3, 96KB smem (TM=128), regs capped at 128 by launch bounds.
template <int TM, int TN>
__global__ __launch_bounds__(256, 2) void mma_gemm(
    const bf16* __restrict__ Ahi, const bf16* __restrict__ Alo,
    const bf16* __restrict__ Bhi, const bf16* __restrict__ Blo,
    bf16* __restrict__ Chi, bf16* __restrict__ Clo, float* __restrict__ Cf,
    int M, int N, int K, int lda, int ldb, int ldc,
    long long sA, long long sB, long long sC, float alpha, int flags)
{
    constexpr int NSTAGE = 3;
    constexpr uint32_t BUFA = (uint32_t)TM * 64u;
    constexpr uint32_t BUFB = (uint32_t)TN * 64u;
    constexpr uint32_t STB  = 2u * BUFA + 2u * BUFB;
    constexpr int NFR = TN / 32;     // B n8-fragments per warp
    constexpr int NLD = TN / 64;     // B LDSM4 pairs per ks
    constexpr int NMI = TM / 32;     // m16 tiles per warp

    const int row0 = blockIdx.y * TM;
    const int col0 = blockIdx.x * TN;
    if ((flags & 1) && col0 >= row0 + TM) return;

    const long long bz = blockIdx.z;
    Ahi += bz * sA;  Alo += bz * sA;
    Bhi += bz * sB;  Blo += bz * sB;
    if (flags & 4) Cf += bz * sC; else { Chi += bz * sC; Clo += bz * sC; }

    const int Keff = (flags & 2) ? min(K, row0 + TM) : K;
    const int KT = Keff / KC;

    extern __shared__ char smraw[];
    const uint32_t sbase = smem_u32(smraw);
    const int tid  = threadIdx.x;
    const int wid  = tid >> 5;
    const int lane = tid & 31;
    const int g    = lane >> 2;
    const int c    = lane & 3;
    const int m0   = (wid & 1) * (TM / 2);
    const int n0   = (wid >> 1) * (TN / 4);

    const int am_l = (lane & 7) + ((lane >> 3) & 1) * 8;
    const int ak_l = lane >> 4;
    const int bn_l = (lane & 7) + ((lane >> 4) & 1) * 8;
    const int bk_l = (lane >> 3) & 1;

    auto load_stage = [&](int kt) {
        const uint32_t base = sbase + (uint32_t)(kt % NSTAGE) * STB;
        const bf16* AgH = Ahi + (long long)row0 * lda + (long long)kt * KC;
        const bf16* AgL = Alo + (long long)row0 * lda + (long long)kt * KC;
        const bf16* BgH = Bhi + (long long)kt * KC;
        const bf16* BgL = Blo + (long long)kt * KC;
#pragma unroll
        for (int j = 0; j < TM / 64; j++) {
            const int i  = tid + j * 256;
            const int m  = i >> 2;
            const int kc = i & 3;
            const uint32_t so = off_swz(m, kc);
            CP_ASYNC16(base + so,        AgH + (long long)m * lda + kc * 8, 16);
            CP_ASYNC16(base + BUFA + so, AgL + (long long)m * lda + kc * 8, 16);
        }
#pragma unroll
        for (int j = 0; j < TN / 64; j++) {
            const int i  = tid + j * 256;
            const int m  = i >> 2;
            const int kc = i & 3;
            const uint32_t so = off_swz(m, kc);
            const int n = col0 + m;
            const long long bo = (long long)(n < N ? n : 0) * ldb + kc * 8;
            const int sz = (n < N) ? 16 : 0;
            CP_ASYNC16(base + 2 * BUFA + so,        BgH + bo, sz);
            CP_ASYNC16(base + 2 * BUFA + BUFB + so, BgL + bo, sz);
        }
        CP_COMMIT();
    };

    float acc[NMI][NFR][4];
#pragma unroll
    for (int i = 0; i < NMI; i++)
#pragma unroll
        for (int j = 0; j < NFR; j++)
#pragma unroll
            for (int e = 0; e < 4; e++) acc[i][j][e] = 0.f;

    const int PRE = (KT < NSTAGE - 1) ? KT : (NSTAGE - 1);
    for (int kt = 0; kt < PRE; kt++) load_stage(kt);

    for (int kt = 0; kt < KT; kt++) {
        CP_WAIT(NSTAGE - 2);
        __syncthreads();
        const int pf = kt + NSTAGE - 1;
        if (pf < KT) load_stage(pf); else CP_COMMIT();

        const uint32_t sb   = sbase + (uint32_t)(kt % NSTAGE) * STB;
        const uint32_t aHiB = sb;
        const uint32_t aLoB = sb + BUFA;
        const uint32_t bHiB = sb + 2 * BUFA;
        const uint32_t bLoB = sb + 2 * BUFA + BUFB;

#pragma unroll
        for (int ks = 0; ks < 2; ks++) {
            const int kcb = ks * 2;
            unsigned bh[NFR][2], bl[NFR][2];
#pragma unroll
            for (int hB = 0; hB < NLD; hB++) {
                const uint32_t so = off_swz(n0 + hB * 16 + bn_l, kcb + bk_l);
                LDSM4(bh[2*hB][0], bh[2*hB][1], bh[2*hB+1][0], bh[2*hB+1][1], bHiB + so);
                LDSM4(bl[2*hB][0], bl[2*hB][1], bl[2*hB+1][0], bl[2*hB+1][1], bLoB + so);
            }
            // A fragments short-lived per mi -> fits 128-reg budget at 2 CTAs/SM
#pragma unroll
            for (int mi = 0; mi < NMI; mi++) {
                unsigned ah[4], al[4];
                const uint32_t so = off_swz(m0 + mi * 16 + am_l, kcb + ak_l);
                LDSM4(ah[0], ah[1], ah[2], ah[3], aHiB + so);
                LDSM4(al[0], al[1], al[2], al[3], aLoB + so);
#pragma unroll
                for (int ni = 0; ni < NFR; ni++) {
                    mma_bf16(acc[mi][ni], ah, bh[ni]);
                    mma_bf16(acc[mi][ni], ah, bl[ni]);
                    mma_bf16(acc[mi][ni], al, bh[ni]);
                }
            }
        }
    }
    CP_WAIT(0);

    // ---------------- epilogue -----------------------------------------------
#pragma unroll
    for (int mi = 0; mi < NMI; mi++) {
#pragma unroll
        for (int ni = 0; ni < NFR; ni++) {
            const int n = col0 + n0 + ni * 8 + 2 * c;
#pragma unroll
            for (int h = 0; h < 2; h++) {
                const int r = row0 + m0 + mi * 16 + g + h * 8;
                float v0 = alpha * acc[mi][ni][2 * h];
                float v1 = alpha * acc[mi][ni][2 * h + 1];
                if (flags & 4) {
                    if (n + 1 < N)
                        *reinterpret_cast<float2*>(&Cf[(long long)r * ldc + n]) =
                            make_float2(v0, v1);
                    else if (n < N) Cf[(long long)r * ldc + n] = v0;
                } else {
                    unsigned uh, ul;
                    pack2(v0, v1, uh, ul);
                    const long long o = (long long)r * ldc + n;
                    if (n + 1 < N) {
                        *reinterpret_cast<unsigned*>(&Chi[o]) = uh;
                        *reinterpret_cast<unsigned*>(&Clo[o]) = ul;
                    } else if (n < N) {
                        Chi[o] = __float2bfloat16(v0);
                        Clo[o] = __float2bfloat16(v0 - __bfloat162float(__float2bfloat16(v0)));
                    }
                }
            }
        }
    }
}

// ---------------- fp32 -> (hi, lo) split -------------------------------------
__global__ void split_f32(const float* __restrict__ x, bf16* __restrict__ hi,
                          bf16* __restrict__ lo, long long n)
{
    long long i = (long long)blockIdx.x * blockDim.x + threadIdx.x;
    if (i >= n) return;
    float v = x[i];
    bf16 h = __float2bfloat16(v);
    hi[i] = h;
    lo[i] = __float2bfloat16(v - __bfloat162float(h));
}

// ---------------- fp32 transpose -> K-major (hi, lo) -------------------------
__global__ void transpose_split(const float* __restrict__ X, bf16* __restrict__ Thi,
                                bf16* __restrict__ Tlo, int R, int C, int ldx,
                                long long sX, long long sT)
{
    __shared__ float t[32][33];
    X   += (long long)blockIdx.z * sX;
    Thi += (long long)blockIdx.z * sT;
    Tlo += (long long)blockIdx.z * sT;
    const int c0 = blockIdx.x * 32, r0 = blockIdx.y * 32;
    const int tx = threadIdx.x, ty = threadIdx.y;
#pragma unroll
    for (int i = 0; i < 32; i += 8) {
        int r = r0 + ty + i;
        if (r < R && c0 + tx < C) t[ty + i][tx] = X[(long long)r * ldx + c0 + tx];
    }
    __syncthreads();
#pragma unroll
    for (int i = 0; i < 32; i += 8) {
        int cc = c0 + ty + i;
        if (cc < C && r0 + tx < R) {
            float v = t[tx][ty + i];
            long long o = (long long)cc * R + r0 + tx;
            bf16 h = __float2bfloat16(v);
            Thi[o] = h;
            Tlo[o] = __float2bfloat16(v - __bfloat162float(h));
        }
    }
}

// ---------------- bf16 transpose ---------------------------------------------
__global__ void transpose_bf16(const bf16* __restrict__ X, bf16* __restrict__ T,
                               int R, int C, int ldx)
{
    __shared__ bf16 t[32][33];
    const int c0 = blockIdx.x * 32, r0 = blockIdx.y * 32;
    const int tx = threadIdx.x, ty = threadIdx.y;
#pragma unroll
    for (int i = 0; i < 32; i += 8) {
        int r = r0 + ty + i;
        if (r < R && c0 + tx < C) t[ty + i][tx] = X[(long long)r * ldx + c0 + tx];
    }
    __syncthreads();
#pragma unroll
    for (int i = 0; i < 32; i += 8) {
        int cc = c0 + ty + i;
        if (cc < C && r0 + tx < R) T[(long long)cc * R + r0 + tx] = t[tx][ty + i];
    }
}

// ---------------- RMSNorm (pair in place, vectorized) -----------------------
__global__ __launch_bounds__(256) void rmsnorm_q(bf16* __restrict__ xh,
                                                 bf16* __restrict__ xl,
                                                 const float* __restrict__ w)
{
    const int s = blockIdx.x;
    const long long base = (long long)s * QL_;
    const int tid = threadIdx.x;
    const int t = tid * 8;
    __shared__ float red[256];
    float f[8];
    float ss = 0.f;
    if (t < QL_) {
        uint4 vh = *reinterpret_cast<const uint4*>(&xh[base + t]);
        uint4 vl = *reinterpret_cast<const uint4*>(&xl[base + t]);
        unpack2(vh.x, vl.x, f[0], f[1]);
        unpack2(vh.y, vl.y, f[2], f[3]);
        unpack2(vh.z, vl.z, f[4], f[5]);
        unpack2(vh.w, vl.w, f[6], f[7]);
#pragma unroll
        for (int j = 0; j < 8; j++) ss += f[j] * f[j];
    }
    red[tid] = ss; __syncthreads();
    for (int off = 128; off > 0; off >>= 1) {
        if (tid < off) red[tid] += red[tid + off];
        __syncthreads();
    }
    const float inv = rsqrtf(red[0] / QL_ + 1e-6f) * SCALE_Q_;
    if (t < QL_) {
        unsigned uh[4], ul[4];
#pragma unroll
        for (int p = 0; p < 4; p++) {
            float a = w[t + 2 * p] * f[2 * p] * inv;
            float b = w[t + 2 * p + 1] * f[2 * p + 1] * inv;
            pack2(a, b, uh[p], ul[p]);
        }
        *reinterpret_cast<uint4*>(&xh[base + t]) = make_uint4(uh[0], uh[1], uh[2], uh[3]);
        *reinterpret_cast<uint4*>(&xl[base + t]) = make_uint4(ul[0], ul[1], ul[2], ul[3]);
    }
}

// ---------------- kva RMSNorm + k_pe RoPE -> k_full (pairs) ------------------
__global__ void kva_norm_rope(const bf16* __restrict__ lh, const bf16* __restrict__ ll,
                              const float* __restrict__ w,
                              const float* __restrict__ cosb, const float* __restrict__ sinb,
                              bf16* __restrict__ kh, bf16* __restrict__ kl)
{
    const int s = blockIdx.x;
    const int tid = threadIdx.x;           // 128 threads
    const long long base = (long long)s * DF_;
    __shared__ float red[128];
    float ss = 0.f;
    for (int j = tid; j < KVL_; j += 128) { float v = pget(lh, ll, base + j); ss += v * v; }
    red[tid] = ss; __syncthreads();
    for (int off = 64; off > 0; off >>= 1) {
        if (tid < off) red[tid] += red[tid + off];
        __syncthreads();
    }
    const float inv = rsqrtf(red[0] / KVL_ + 1e-6f) * SCALE_KV_;
    for (int j = tid; j < KVL_; j += 128)
        pset(kh, kl, base + j, w[j] * pget(lh, ll, base + j) * inv);
    if (tid < DR_) {
        const int r = tid;
        float x = pget(lh, ll, base + KVL_ + r);
        float o = (r < 32) ? -pget(lh, ll, base + KVL_ + r + 32)
                           :  pget(lh, ll, base + KVL_ + r - 32);
        pset(kh, kl, base + KVL_ + r, x * cosb[s * DR_ + r] + o * sinb[s * DR_ + r]);
    }
}

// ---------------- q_pe RoPE -> q_full[h][s][512+r] (pairs) -------------------
__global__ void rope_q(const bf16* __restrict__ qh, const bf16* __restrict__ ql,
                       const float* __restrict__ cosb, const float* __restrict__ sinb,
                       bf16* __restrict__ fh, bf16* __restrict__ fl)
{
    long long idx = (long long)blockIdx.x * blockDim.x + threadIdx.x;
    if (idx >= (long long)S_ * NH_ * DR_) return;
    const int r = (int)(idx % DR_);
    const int h = (int)((idx / DR_) % NH_);
    const int s = (int)(idx / ((long long)DR_ * NH_));
    const long long qb = (long long)s * NH_ * QDIM_ + h * QDIM_ + DN_;
    float x = pget(qh, ql, qb + r);
    float o = (r < 32) ? -pget(qh, ql, qb + r + 32) : pget(qh, ql, qb + r - 32);
    pset(fh, fl, ((long long)h * S_ + s) * DF_ + KVL_ + r,
         x * cosb[s * DR_ + r] + o * sinb[s * DR_ + r]);
}

// ------- causal softmax: fp32 in, (hi,lo) pairs out, smem row cache ----------
__global__ __launch_bounds__(256) void softmax_causal(const float* __restrict__ sf,
                                                      bf16* __restrict__ sh,
                                                      bf16* __restrict__ sl)
{
    const int s = blockIdx.x, h = blockIdx.y;
    const long long base = ((long long)h * S_ + s) * (long long)S_;
    __shared__ float vals[S_];
    __shared__ float red[256];
    const int tid = threadIdx.x;
    const int len = s + 1;
    const int len4 = len & ~3;

    float m = -1e30f;
    for (int t = tid * 4; t < len4; t += 1024) {
        float4 v = *reinterpret_cast<const float4*>(&sf[base + t]);
        vals[t] = v.x; vals[t + 1] = v.y; vals[t + 2] = v.z; vals[t + 3] = v.w;
        m = fmaxf(fmaxf(m, fmaxf(v.x, v.y)), fmaxf(v.z, v.w));
    }
    for (int t = len4 + tid; t < len; t += 256) {
        float v = sf[base + t];
        vals[t] = v; m = fmaxf(m, v);
    }
    red[tid] = m; __syncthreads();
    for (int off = 128; off > 0; off >>= 1) {
        if (tid < off) red[tid] = fmaxf(red[tid], red[tid + off]);
        __syncthreads();
    }
    m = red[0]; __syncthreads();

    float sum = 0.f;
    for (int t = tid; t < len; t += 256) {
        float e = __expf(vals[t] - m);
        vals[t] = e; sum += e;
    }
    red[tid] = sum; __syncthreads();
    for (int off = 128; off > 0; off >>= 1) {
        if (tid < off) red[tid] += red[tid + off];
        __syncthreads();
    }
    const float inv = 1.f / red[0];

    const int rowEnd = (s & ~127) + 128;   // ctx GEMM (TM=128) reads k < rowEnd
    for (int t = tid * 8; t < rowEnd; t += 2048) {
        unsigned uh[4], ul[4];
#pragma unroll
        for (int p = 0; p < 4; p++) {
            float a = (t + 2 * p     < len) ? vals[t + 2 * p] * inv : 0.f;
            float b = (t + 2 * p + 1 < len) ? vals[t + 2 * p + 1] * inv : 0.f;
            pack2(a, b, uh[p], ul[p]);
        }
        *reinterpret_cast<uint4*>(&sh[base + t]) = make_uint4(uh[0], uh[1], uh[2], uh[3]);
        *reinterpret_cast<uint4*>(&sl[base + t]) = make_uint4(ul[0], ul[1], ul[2], ul[3]);
    }
}

// =============================================================================
extern "C" void kernel_launch(void* const* d_in, const int* in_sizes, int n_in,
                              void* d_out, int out_size)
{
    const float* hidden = (const float*)d_in[0];
    const float* cosb   = (const float*)d_in[1];
    const float* sinb   = (const float*)d_in[2];
    const float* w_qa   = (const float*)d_in[3];
    const float* qa_ln  = (const float*)d_in[4];
    const float* w_qb   = (const float*)d_in[5];
    const float* w_kva  = (const float*)d_in[6];
    const float* kva_ln = (const float*)d_in[7];
    const float* w_k    = (const float*)d_in[8];
    const float* w_v    = (const float*)d_in[9];
    const float* w_o    = (const float*)d_in[10];
    float* out = (float*)d_out;

    bf16 *hid, *qlat, *q, *lat, *kf, *qf, *sc, *ctx, *ao;
    bf16 *wqa, *wqb, *wkva, *wk, *wv, *wo, *ckvt;
    float *scf;
    cudaGetSymbolAddress((void**)&hid,  g_hid2);
    cudaGetSymbolAddress((void**)&qlat, g_qlat2);
    cudaGetSymbolAddress((void**)&q,    g_q2);
    cudaGetSymbolAddress((void**)&lat,  g_lat2);
    cudaGetSymbolAddress((void**)&kf,   g_kf2);
    cudaGetSymbolAddress((void**)&qf,   g_qf2);
    cudaGetSymbolAddress((void**)&sc,   g_sc2);
    cudaGetSymbolAddress((void**)&scf,  g_scf);
    cudaGetSymbolAddress((void**)&ctx,  g_ctx2);
    cudaGetSymbolAddress((void**)&ao,   g_ao2);
    cudaGetSymbolAddress((void**)&wqa,  g_wqa2);
    cudaGetSymbolAddress((void**)&wqb,  g_wqb2);
    cudaGetSymbolAddress((void**)&wkva, g_wkva2);
    cudaGetSymbolAddress((void**)&wk,   g_wk2);
    cudaGetSymbolAddress((void**)&wv,   g_wv2);
    cudaGetSymbolAddress((void**)&wo,   g_wo2);
    cudaGetSymbolAddress((void**)&ckvt, g_ckvt2);

    bf16 *hidL = hid + N_HID,  *qlatL = qlat + N_QLAT, *qL = q + N_Q;
    bf16 *latL = lat + N_LAT,  *kfL = kf + N_KF,       *qfL = qf + N_QF;
    bf16 *scL  = sc + N_SC,    *ctxL = ctx + N_CTX,    *aoL = ao + N_AO;
    bf16 *wqaL = wqa + N_WQA,  *wqbL = wqb + N_WQB,    *wkvaL = wkva + N_WKVA;
    bf16 *wkL  = wk + N_WK,    *wvL = wv + N_WV,       *woL = wo + N_WO;
    bf16 *ckvtL = ckvt + N_CKVT;

    constexpr int SM128 = 3 * (2 * 128 * 64 + 2 * 128 * 64);  // 98304
    constexpr int SM64  = 3 * (2 * 64 * 64 + 2 * 128 * 64);   // 73728
    cudaFuncSetAttribute(mma_gemm<128, 128>, cudaFuncAttributeMaxDynamicSharedMemorySize, SM128);
    cudaFuncSetAttribute(mma_gemm<64, 128>,  cudaFuncAttributeMaxDynamicSharedMemorySize, SM64);

    const dim3 tb(32, 8);

    // weight transposes (input-only deps)
    transpose_split<<<dim3(QL_ / 32, HID_ / 32, 1), tb>>>(w_qa, wqa, wqaL, HID_, QL_, QL_, 0, 0);
    transpose_split<<<dim3(NH_ * QDIM_ / 32, QL_ / 32, 1), tb>>>(w_qb, wqb, wqbL, QL_, NH_ * QDIM_, NH_ * QDIM_, 0, 0);
    // split hidden
    {
        long long n = (long long)N_HID;
        split_f32<<<(unsigned)((n + 255) / 256), 256>>>(hidden, hid, hidL, n);
    }
    // launch 3 (profile slot): q_lat = hidden @ w_qa  (TM=64 -> 288 blocks, 2/SM)
    mma_gemm<64, 128><<<dim3(QL_ / 128, S_ / 64, 1), 256, SM64>>>(
        hid, hidL, wqa, wqaL, qlat, qlatL, nullptr,
        S_, QL_, HID_, HID_, HID_, QL_, 0, 0, 0, 1.f, 0);
    rmsnorm_q<<<S_, 256>>>(qlat, qlatL, qa_ln);
    // q = q_lat @ w_qb
    mma_gemm<128, 128><<<dim3(NH_ * QDIM_ / 128, S_ / 128, 1), 256, SM128>>>(
        qlat, qlatL, wqb, wqbL, q, qL, nullptr,
        S_, NH_ * QDIM_, QL_, QL_, QL_, NH_ * QDIM_, 0, 0, 0, 1.f, 0);
    // latent path (TM=64 -> 120 blocks)
    transpose_split<<<dim3(DF_ / 32, HID_ / 32, 1), tb>>>(w_kva, wkva, wkvaL, HID_, DF_, DF_, 0, 0);
    mma_gemm<64, 128><<<dim3((DF_ + 127) / 128, S_ / 64, 1), 256, SM64>>>(
        hid, hidL, wkva, wkvaL, lat, latL, nullptr,
        S_, DF_, HID_, HID_, HID_, DF_, 0, 0, 0, 1.f, 0);
    kva_norm_rope<<<S_, 128>>>(lat, latL, kva_ln, cosb, sinb, kf, kfL);
    transpose_bf16<<<dim3(KVL_ / 32, S_ / 32), tb>>>(kf,  ckvt,  S_, KVL_, DF_);
    transpose_bf16<<<dim3(KVL_ / 32, S_ / 32), tb>>>(kfL, ckvtL, S_, KVL_, DF_);
    // rope q_pe
    {
        long long tot = (long long)S_ * NH_ * DR_;
        rope_q<<<(unsigned)((tot + 255) / 256), 256>>>(q, qL, cosb, sinb, qf, qfL);
    }
    // q_abs
    transpose_split<<<dim3(KVL_ / 32, DN_ / 32, NH_), tb>>>(w_k, wk, wkL, DN_, KVL_, KVL_,
        (long long)DN_ * KVL_, (long long)KVL_ * DN_);
    mma_gemm<128, 128><<<dim3(KVL_ / 128, S_ / 128, NH_), 256, SM128>>>(
        q, qL, wk, wkL, qf, qfL, nullptr,
        S_, KVL_, DN_, NH_ * QDIM_, DN_, DF_,
        (long long)QDIM_, (long long)KVL_ * DN_, (long long)S_ * DF_, 1.f, 0);
    // scores -> fp32 (causal skip)
    mma_gemm<128, 128><<<dim3(S_ / 128, S_ / 128, NH_), 256, SM128>>>(
        qf, qfL, kf, kfL, nullptr, nullptr, scf,
        S_, S_, DF_, DF_, DF_, S_,
        (long long)S_ * DF_, 0LL, (long long)S_ * S_, SM_SCALE_, 1 | 4);
    // softmax
    softmax_causal<<<dim3(S_, NH_), 256>>>(scf, sc, scL);
    // ctx (K-limit, TM=128 matches softmax rowEnd)
    mma_gemm<128, 128><<<dim3(KVL_ / 128, S_ / 128, NH_), 256, SM128>>>(
        sc, scL, ckvt, ckvtL, ctx, ctxL, nullptr,
        S_, KVL_, S_, S_, S_, KVL_,
        (long long)S_ * S_, 0LL, (long long)S_ * KVL_, 1.f, 2);
    // attn_out
    transpose_split<<<dim3(DV_ / 32, KVL_ / 32, NH_), tb>>>(w_v, wv, wvL, KVL_, DV_, DV_,
        (long long)KVL_ * DV_, (long long)DV_ * KVL_);
    mma_gemm<128, 128><<<dim3(1, S_ / 128, NH_), 256, SM128>>>(
        ctx, ctxL, wv, wvL, ao, aoL, nullptr,
        S_, DV_, KVL_, KVL_, KVL_, NH_ * DV_,
        (long long)S_ * KVL_, (long long)DV_ * KVL_, (long long)DV_, 1.f, 0);
    // out = ao @ w_o
    transpose_split<<<dim3(HID_ / 32, (NH_ * DV_) / 32, 1), tb>>>(w_o, wo, woL, NH_ * DV_, HID_, HID_, 0, 0);
    mma_gemm<128, 128><<<dim3(HID_ / 128, S_ / 128, 1), 256, SM128>>>(
        ao, aoL, wo, woL, nullptr, nullptr, out,
        S_, HID_, NH_ * DV_, NH_ * DV_, NH_ * DV_, HID_, 0, 0, 0, 1.f, 4);
}

// round 10
// speedup vs baseline: 5.0838x; 1.2704x over previous
#include <cuda_runtime.h>
#include <cuda_bf16.h>
#include <cstdint>
#include <math.h>

#define S_    1536
#define HID_  6144
#define NH_   64
#define DN_   128
#define DR_   64
#define DV_   128
#define QL_   1536
#define KVL_  512
#define DF_   576        // KVL + DR
#define QDIM_ 192        // DN + DR
#define KCAT_ 192        // DN + DR (scores K)

#define SM_SCALE_  0.07216878364870322f
#define SCALE_Q_   2.0f
#define SCALE_KV_  3.4641016151377544f

#define KC 32

typedef __nv_bfloat16 bf16;

// ---------------- scratch: activations/weights as (hi, lo) bf16 pairs -------
#define N_HID  ((size_t)S_ * HID_)
#define N_QLAT ((size_t)S_ * QL_)
#define N_Q    ((size_t)S_ * NH_ * QDIM_)
#define N_LAT  ((size_t)S_ * DF_)
#define N_KF   ((size_t)S_ * DF_)
#define N_KCAT ((size_t)NH_ * S_ * KCAT_)
#define N_VEFF ((size_t)NH_ * DV_ * S_)
#define N_SC   ((size_t)NH_ * S_ * S_)
#define N_AO   ((size_t)S_ * NH_ * DV_)
#define N_WQA  ((size_t)QL_ * HID_)
#define N_WQB  ((size_t)NH_ * QDIM_ * QL_)
#define N_WKVA ((size_t)DF_ * HID_)
#define N_WK   ((size_t)NH_ * DN_ * KVL_)
#define N_WV   ((size_t)NH_ * DV_ * KVL_)
#define N_WO   ((size_t)HID_ * NH_ * DV_)

__device__ __align__(256) unsigned short g_hid2 [2 * N_HID];
__device__ __align__(256) unsigned short g_qlat2[2 * N_QLAT];
__device__ __align__(256) unsigned short g_q2   [2 * N_Q];
__device__ __align__(256) unsigned short g_lat2 [2 * N_LAT];
__device__ __align__(256) unsigned short g_kf2  [2 * N_KF];
__device__ __align__(256) unsigned short g_kcat2[2 * N_KCAT];
__device__ __align__(256) unsigned short g_veff2[2 * N_VEFF];
__device__ __align__(256) unsigned short g_sc2  [2 * N_SC];
__device__ __align__(256) float          g_scf  [N_SC];
__device__ __align__(256) unsigned short g_ao2  [2 * N_AO];
__device__ __align__(256) unsigned short g_wqa2 [2 * N_WQA];
__device__ __align__(256) unsigned short g_wqb2 [2 * N_WQB];
__device__ __align__(256) unsigned short g_wkva2[2 * N_WKVA];
__device__ __align__(256) unsigned short g_wk2  [2 * N_WK];
__device__ __align__(256) unsigned short g_wv2  [2 * N_WV];
__device__ __align__(256) unsigned short g_wo2  [2 * N_WO];

// ---------------- helpers ----------------------------------------------------
__device__ __forceinline__ uint32_t smem_u32(const void* p) {
    uint32_t a;
    asm("{ .reg .u64 t; cvta.to.shared.u64 t, %1; cvt.u32.u64 %0, t; }" : "=r"(a) : "l"(p));
    return a;
}
#define CP_ASYNC16(dst, src, sz) \
    asm volatile("cp.async.cg.shared.global [%0], [%1], 16, %2;" :: "r"(dst), "l"(src), "r"(sz))
#define CP_COMMIT() asm volatile("cp.async.commit_group;" ::: "memory")
#define CP_WAIT(n)  asm volatile("cp.async.wait_group %0;" :: "n"(n) : "memory")

#define LDSM4(r0, r1, r2, r3, a) \
    asm volatile("ldmatrix.sync.aligned.m8n8.x4.shared.b16 {%0,%1,%2,%3}, [%4];" \
                 : "=r"(r0), "=r"(r1), "=r"(r2), "=r"(r3) : "r"(a))

__device__ __forceinline__ void mma_bf16(float* d, const unsigned* a, const unsigned* b) {
    asm volatile(
        "mma.sync.aligned.m16n8k16.row.col.f32.bf16.bf16.f32 "
        "{%0,%1,%2,%3}, {%4,%5,%6,%7}, {%8,%9}, {%0,%1,%2,%3};"
        : "+f"(d[0]), "+f"(d[1]), "+f"(d[2]), "+f"(d[3])
        : "r"(a[0]), "r"(a[1]), "r"(a[2]), "r"(a[3]), "r"(b[0]), "r"(b[1]));
}

__device__ __forceinline__ uint32_t off_swz(int row, int kc) {
    return (uint32_t)(row >> 1) * 128u +
           (uint32_t)(((((row & 1) << 2) + kc) ^ ((row >> 1) & 7)) * 16);
}

__device__ __forceinline__ float pget(const bf16* h, const bf16* l, long long i) {
    return __bfloat162float(h[i]) + __bfloat162float(l[i]);
}
__device__ __forceinline__ void pset(bf16* h, bf16* l, long long i, float v) {
    bf16 a = __float2bfloat16(v);
    h[i] = a;
    l[i] = __float2bfloat16(v - __bfloat162float(a));
}
__device__ __forceinline__ void unpack2(unsigned h, unsigned l, float& a, float& b) {
    a = __uint_as_float(h << 16) + __uint_as_float(l << 16);
    b = __uint_as_float(h & 0xffff0000u) + __uint_as_float(l & 0xffff0000u);
}
__device__ __forceinline__ void pack2(float a, float b, unsigned& h, unsigned& l) {
    bf16 ha = __float2bfloat16(a), hb = __float2bfloat16(b);
    bf16 la = __float2bfloat16(a - __bfloat162float(ha));
    bf16 lb = __float2bfloat16(b - __bfloat162float(hb));
    __nv_bfloat162 hv; hv.x = ha; hv.y = hb;
    __nv_bfloat162 lv; lv.x = la; lv.y = lb;
    h = *reinterpret_cast<unsigned*>(&hv);
    l = *reinterpret_cast<unsigned*>(&lv);
}

// flags: bit0 = causal tile skip, bit1 = K limited to row0+TM, bit2 = fp32 C
template <int TM, int TN>
__global__ __launch_bounds__(256, 2) void mma_gemm(
    const bf16* __restrict__ Ahi, const bf16* __restrict__ Alo,
    const bf16* __restrict__ Bhi, const bf16* __restrict__ Blo,
    bf16* __restrict__ Chi, bf16* __restrict__ Clo, float* __restrict__ Cf,
    int M, int N, int K, int lda, int ldb, int ldc,
    long long sA, long long sB, long long sC, float alpha, int flags)
{
    constexpr int NSTAGE = 3;
    constexpr uint32_t BUFA = (uint32_t)TM * 64u;
    constexpr uint32_t BUFB = (uint32_t)TN * 64u;
    constexpr uint32_t STB  = 2u * BUFA + 2u * BUFB;
    constexpr int NFR = TN / 32;
    constexpr int NLD = TN / 64;
    constexpr int NMI = TM / 32;

    const int row0 = blockIdx.y * TM;
    const int col0 = blockIdx.x * TN;
    if ((flags & 1) && col0 >= row0 + TM) return;

    const long long bz = blockIdx.z;
    Ahi += bz * sA;  Alo += bz * sA;
    Bhi += bz * sB;  Blo += bz * sB;
    if (flags & 4) Cf += bz * sC; else { Chi += bz * sC; Clo += bz * sC; }

    const int Keff = (flags & 2) ? min(K, row0 + TM) : K;
    const int KT = Keff / KC;

    extern __shared__ char smraw[];
    const uint32_t sbase = smem_u32(smraw);
    const int tid  = threadIdx.x;
    const int wid  = tid >> 5;
    const int lane = tid & 31;
    const int g    = lane >> 2;
    const int c    = lane & 3;
    const int m0   = (wid & 1) * (TM / 2);
    const int n0   = (wid >> 1) * (TN / 4);

    const int am_l = (lane & 7) + ((lane >> 3) & 1) * 8;
    const int ak_l = lane >> 4;
    const int bn_l = (lane & 7) + ((lane >> 4) & 1) * 8;
    const int bk_l = (lane >> 3) & 1;

    auto load_stage = [&](int kt) {
        const uint32_t base = sbase + (uint32_t)(kt % NSTAGE) * STB;
        const bf16* AgH = Ahi + (long long)row0 * lda + (long long)kt * KC;
        const bf16* AgL = Alo + (long long)row0 * lda + (long long)kt * KC;
        const bf16* BgH = Bhi + (long long)kt * KC;
        const bf16* BgL = Blo + (long long)kt * KC;
#pragma unroll
        for (int j = 0; j < TM / 64; j++) {
            const int i  = tid + j * 256;
            const int m  = i >> 2;
            const int kc = i & 3;
            const uint32_t so = off_swz(m, kc);
            CP_ASYNC16(base + so,        AgH + (long long)m * lda + kc * 8, 16);
            CP_ASYNC16(base + BUFA + so, AgL + (long long)m * lda + kc * 8, 16);
        }
#pragma unroll
        for (int j = 0; j < TN / 64; j++) {
            const int i  = tid + j * 256;
            const int m  = i >> 2;
            const int kc = i & 3;
            const uint32_t so = off_swz(m, kc);
            const int n = col0 + m;
            const long long bo = (long long)(n < N ? n : 0) * ldb + kc * 8;
            const int sz = (n < N) ? 16 : 0;
            CP_ASYNC16(base + 2 * BUFA + so,        BgH + bo, sz);
            CP_ASYNC16(base + 2 * BUFA + BUFB + so, BgL + bo, sz);
        }
        CP_COMMIT();
    };

    float acc[NMI][NFR][4];
#pragma unroll
    for (int i = 0; i < NMI; i++)
#pragma unroll
        for (int j = 0; j < NFR; j++)
#pragma unroll
            for (int e = 0; e < 4; e++) acc[i][j][e] = 0.f;

    const int PRE = (KT < NSTAGE - 1) ? KT : (NSTAGE - 1);
    for (int kt = 0; kt < PRE; kt++) load_stage(kt);

    for (int kt = 0; kt < KT; kt++) {
        CP_WAIT(NSTAGE - 2);
        __syncthreads();
        const int pf = kt + NSTAGE - 1;
        if (pf < KT) load_stage(pf); else CP_COMMIT();

        const uint32_t sb   = sbase + (uint32_t)(kt % NSTAGE) * STB;
        const uint32_t aHiB = sb;
        const uint32_t aLoB = sb + BUFA;
        const uint32_t bHiB = sb + 2 * BUFA;
        const uint32_t bLoB = sb + 2 * BUFA + BUFB;

#pragma unroll
        for (int ks = 0; ks < 2; ks++) {
            const int kcb = ks * 2;
            unsigned bh[NFR][2], bl[NFR][2];
#pragma unroll
            for (int hB = 0; hB < NLD; hB++) {
                const uint32_t so = off_swz(n0 + hB * 16 + bn_l, kcb + bk_l);
                LDSM4(bh[2*hB][0], bh[2*hB][1], bh[2*hB+1][0], bh[2*hB+1][1], bHiB + so);
                LDSM4(bl[2*hB][0], bl[2*hB][1], bl[2*hB+1][0], bl[2*hB+1][1], bLoB + so);
            }
#pragma unroll
            for (int mi = 0; mi < NMI; mi++) {
                unsigned ah[4], al[4];
                const uint32_t so = off_swz(m0 + mi * 16 + am_l, kcb + ak_l);
                LDSM4(ah[0], ah[1], ah[2], ah[3], aHiB + so);
                LDSM4(al[0], al[1], al[2], al[3], aLoB + so);
#pragma unroll
                for (int ni = 0; ni < NFR; ni++) {
                    mma_bf16(acc[mi][ni], ah, bh[ni]);
                    mma_bf16(acc[mi][ni], ah, bl[ni]);
                    mma_bf16(acc[mi][ni], al, bh[ni]);
                }
            }
        }
    }
    CP_WAIT(0);

    // ---------------- epilogue -----------------------------------------------
#pragma unroll
    for (int mi = 0; mi < NMI; mi++) {
#pragma unroll
        for (int ni = 0; ni < NFR; ni++) {
            const int n = col0 + n0 + ni * 8 + 2 * c;
#pragma unroll
            for (int h = 0; h < 2; h++) {
                const int r = row0 + m0 + mi * 16 + g + h * 8;
                float v0 = alpha * acc[mi][ni][2 * h];
                float v1 = alpha * acc[mi][ni][2 * h + 1];
                if (flags & 4) {
                    if (n + 1 < N)
                        *reinterpret_cast<float2*>(&Cf[(long long)r * ldc + n]) =
                            make_float2(v0, v1);
                    else if (n < N) Cf[(long long)r * ldc + n] = v0;
                } else {
                    unsigned uh, ul;
                    pack2(v0, v1, uh, ul);
                    const long long o = (long long)r * ldc + n;
                    if (n + 1 < N) {
                        *reinterpret_cast<unsigned*>(&Chi[o]) = uh;
                        *reinterpret_cast<unsigned*>(&Clo[o]) = ul;
                    } else if (n < N) {
                        Chi[o] = __float2bfloat16(v0);
                        Clo[o] = __float2bfloat16(v0 - __bfloat162float(__float2bfloat16(v0)));
                    }
                }
            }
        }
    }
}

// ---------------- fp32 -> (hi, lo) split -------------------------------------
__global__ void split_f32(const float* __restrict__ x, bf16* __restrict__ hi,
                          bf16* __restrict__ lo, long long n)
{
    long long i = (long long)blockIdx.x * blockDim.x + threadIdx.x;
    if (i >= n) return;
    float v = x[i];
    bf16 h = __float2bfloat16(v);
    hi[i] = h;
    lo[i] = __float2bfloat16(v - __bfloat162float(h));
}

// ---------------- fp32 transpose -> K-major (hi, lo) -------------------------
__global__ void transpose_split(const float* __restrict__ X, bf16* __restrict__ Thi,
                                bf16* __restrict__ Tlo, int R, int C, int ldx,
                                long long sX, long long sT)
{
    __shared__ float t[32][33];
    X   += (long long)blockIdx.z * sX;
    Thi += (long long)blockIdx.z * sT;
    Tlo += (long long)blockIdx.z * sT;
    const int c0 = blockIdx.x * 32, r0 = blockIdx.y * 32;
    const int tx = threadIdx.x, ty = threadIdx.y;
#pragma unroll
    for (int i = 0; i < 32; i += 8) {
        int r = r0 + ty + i;
        if (r < R && c0 + tx < C) t[ty + i][tx] = X[(long long)r * ldx + c0 + tx];
    }
    __syncthreads();
#pragma unroll
    for (int i = 0; i < 32; i += 8) {
        int cc = c0 + ty + i;
        if (cc < C && r0 + tx < R) {
            float v = t[tx][ty + i];
            long long o = (long long)cc * R + r0 + tx;
            bf16 h = __float2bfloat16(v);
            Thi[o] = h;
            Tlo[o] = __float2bfloat16(v - __bfloat162float(h));
        }
    }
}

// ---------------- RMSNorm (pair in place, vectorized) -----------------------
__global__ __launch_bounds__(256) void rmsnorm_q(bf16* __restrict__ xh,
                                                 bf16* __restrict__ xl,
                                                 const float* __restrict__ w)
{
    const int s = blockIdx.x;
    const long long base = (long long)s * QL_;
    const int tid = threadIdx.x;
    const int t = tid * 8;
    __shared__ float red[256];
    float f[8];
    float ss = 0.f;
    if (t < QL_) {
        uint4 vh = *reinterpret_cast<const uint4*>(&xh[base + t]);
        uint4 vl = *reinterpret_cast<const uint4*>(&xl[base + t]);
        unpack2(vh.x, vl.x, f[0], f[1]);
        unpack2(vh.y, vl.y, f[2], f[3]);
        unpack2(vh.z, vl.z, f[4], f[5]);
        unpack2(vh.w, vl.w, f[6], f[7]);
#pragma unroll
        for (int j = 0; j < 8; j++) ss += f[j] * f[j];
    }
    red[tid] = ss; __syncthreads();
    for (int off = 128; off > 0; off >>= 1) {
        if (tid < off) red[tid] += red[tid + off];
        __syncthreads();
    }
    const float inv = rsqrtf(red[0] / QL_ + 1e-6f) * SCALE_Q_;
    if (t < QL_) {
        unsigned uh[4], ul[4];
#pragma unroll
        for (int p = 0; p < 4; p++) {
            float a = w[t + 2 * p] * f[2 * p] * inv;
            float b = w[t + 2 * p + 1] * f[2 * p + 1] * inv;
            pack2(a, b, uh[p], ul[p]);
        }
        *reinterpret_cast<uint4*>(&xh[base + t]) = make_uint4(uh[0], uh[1], uh[2], uh[3]);
        *reinterpret_cast<uint4*>(&xl[base + t]) = make_uint4(ul[0], ul[1], ul[2], ul[3]);
    }
}

// ---------------- kva RMSNorm + k_pe RoPE -> k_full (pairs) ------------------
__global__ void kva_norm_rope(const bf16* __restrict__ lh, const bf16* __restrict__ ll,
                              const float* __restrict__ w,
                              const float* __restrict__ cosb, const float* __restrict__ sinb,
                              bf16* __restrict__ kh, bf16* __restrict__ kl)
{
    const int s = blockIdx.x;
    const int tid = threadIdx.x;           // 128 threads
    const long long base = (long long)s * DF_;
    __shared__ float red[128];
    float ss = 0.f;
    for (int j = tid; j < KVL_; j += 128) { float v = pget(lh, ll, base + j); ss += v * v; }
    red[tid] = ss; __syncthreads();
    for (int off = 64; off > 0; off >>= 1) {
        if (tid < off) red[tid] += red[tid + off];
        __syncthreads();
    }
    const float inv = rsqrtf(red[0] / KVL_ + 1e-6f) * SCALE_KV_;
    for (int j = tid; j < KVL_; j += 128)
        pset(kh, kl, base + j, w[j] * pget(lh, ll, base + j) * inv);
    if (tid < DR_) {
        const int r = tid;
        float x = pget(lh, ll, base + KVL_ + r);
        float o = (r < 32) ? -pget(lh, ll, base + KVL_ + r + 32)
                           :  pget(lh, ll, base + KVL_ + r - 32);
        pset(kh, kl, base + KVL_ + r, x * cosb[s * DR_ + r] + o * sinb[s * DR_ + r]);
    }
}

// ---------------- q_pe RoPE in place (pair-safe: one thread per (r, r+32)) --
__global__ void rope_q_inplace(bf16* __restrict__ qh, bf16* __restrict__ ql,
                               const float* __restrict__ cosb, const float* __restrict__ sinb)
{
    long long idx = (long long)blockIdx.x * blockDim.x + threadIdx.x;
    if (idx >= (long long)S_ * NH_ * 32) return;
    const int r2 = (int)(idx % 32);
    const int h  = (int)((idx / 32) % NH_);
    const int s  = (int)(idx / (32LL * NH_));
    const long long base = (long long)s * NH_ * QDIM_ + h * QDIM_ + DN_;
    float x1 = pget(qh, ql, base + r2);
    float x2 = pget(qh, ql, base + 32 + r2);
    const float c1 = cosb[s * DR_ + r2],      s1 = sinb[s * DR_ + r2];
    const float c2 = cosb[s * DR_ + 32 + r2], s2 = sinb[s * DR_ + 32 + r2];
    pset(qh, ql, base + r2,      x1 * c1 - x2 * s1);
    pset(qh, ql, base + 32 + r2, x2 * c2 + x1 * s2);
}

// ------- broadcast roped k_pe into kcat[h][t][128:192] (uint4 copies) --------
__global__ void kcat_pe(const bf16* __restrict__ kfh, const bf16* __restrict__ kfl,
                        bf16* __restrict__ kch, bf16* __restrict__ kcl)
{
    long long idx = (long long)blockIdx.x * blockDim.x + threadIdx.x;  // NH*S*8
    if (idx >= (long long)NH_ * S_ * 8) return;
    const int r8 = (int)(idx % 8);
    const int t  = (int)((idx / 8) % S_);
    const int h  = (int)(idx / (8LL * S_));
    const long long src = (long long)t * DF_ + KVL_ + r8 * 8;
    const long long dst = ((long long)h * S_ + t) * KCAT_ + DN_ + r8 * 8;
    *reinterpret_cast<uint4*>(&kch[dst]) = *reinterpret_cast<const uint4*>(&kfh[src]);
    *reinterpret_cast<uint4*>(&kcl[dst]) = *reinterpret_cast<const uint4*>(&kfl[src]);
}

// ------- causal softmax: fp32 in, (hi,lo) pairs out, smem row cache ----------
__global__ __launch_bounds__(256) void softmax_causal(const float* __restrict__ sf,
                                                      bf16* __restrict__ sh,
                                                      bf16* __restrict__ sl)
{
    const int s = blockIdx.x, h = blockIdx.y;
    const long long base = ((long long)h * S_ + s) * (long long)S_;
    __shared__ float vals[S_];
    __shared__ float red[256];
    const int tid = threadIdx.x;
    const int len = s + 1;
    const int len4 = len & ~3;

    float m = -1e30f;
    for (int t = tid * 4; t < len4; t += 1024) {
        float4 v = *reinterpret_cast<const float4*>(&sf[base + t]);
        vals[t] = v.x; vals[t + 1] = v.y; vals[t + 2] = v.z; vals[t + 3] = v.w;
        m = fmaxf(fmaxf(m, fmaxf(v.x, v.y)), fmaxf(v.z, v.w));
    }
    for (int t = len4 + tid; t < len; t += 256) {
        float v = sf[base + t];
        vals[t] = v; m = fmaxf(m, v);
    }
    red[tid] = m; __syncthreads();
    for (int off = 128; off > 0; off >>= 1) {
        if (tid < off) red[tid] = fmaxf(red[tid], red[tid + off]);
        __syncthreads();
    }
    m = red[0]; __syncthreads();

    float sum = 0.f;
    for (int t = tid; t < len; t += 256) {
        float e = __expf(vals[t] - m);
        vals[t] = e; sum += e;
    }
    red[tid] = sum; __syncthreads();
    for (int off = 128; off > 0; off >>= 1) {
        if (tid < off) red[tid] += red[tid + off];
        __syncthreads();
    }
    const float inv = 1.f / red[0];

    const int rowEnd = (s & ~127) + 128;   // out_v GEMM (TM=128) reads k < rowEnd
    for (int t = tid * 8; t < rowEnd; t += 2048) {
        unsigned uh[4], ul[4];
#pragma unroll
        for (int p = 0; p < 4; p++) {
            float a = (t + 2 * p     < len) ? vals[t + 2 * p] * inv : 0.f;
            float b = (t + 2 * p + 1 < len) ? vals[t + 2 * p + 1] * inv : 0.f;
            pack2(a, b, uh[p], ul[p]);
        }
        *reinterpret_cast<uint4*>(&sh[base + t]) = make_uint4(uh[0], uh[1], uh[2], uh[3]);
        *reinterpret_cast<uint4*>(&sl[base + t]) = make_uint4(ul[0], ul[1], ul[2], ul[3]);
    }
}

// =============================================================================
extern "C" void kernel_launch(void* const* d_in, const int* in_sizes, int n_in,
                              void* d_out, int out_size)
{
    const float* hidden = (const float*)d_in[0];
    const float* cosb   = (const float*)d_in[1];
    const float* sinb   = (const float*)d_in[2];
    const float* w_qa   = (const float*)d_in[3];
    const float* qa_ln  = (const float*)d_in[4];
    const float* w_qb   = (const float*)d_in[5];
    const float* w_kva  = (const float*)d_in[6];
    const float* kva_ln = (const float*)d_in[7];
    const float* w_k    = (const float*)d_in[8];
    const float* w_v    = (const float*)d_in[9];
    const float* w_o    = (const float*)d_in[10];
    float* out = (float*)d_out;

    bf16 *hid, *qlat, *q, *lat, *kf, *kcat, *veff, *sc, *ao;
    bf16 *wqa, *wqb, *wkva, *wk, *wvT, *woT;
    float *scf;
    cudaGetSymbolAddress((void**)&hid,  g_hid2);
    cudaGetSymbolAddress((void**)&qlat, g_qlat2);
    cudaGetSymbolAddress((void**)&q,    g_q2);
    cudaGetSymbolAddress((void**)&lat,  g_lat2);
    cudaGetSymbolAddress((void**)&kf,   g_kf2);
    cudaGetSymbolAddress((void**)&kcat, g_kcat2);
    cudaGetSymbolAddress((void**)&veff, g_veff2);
    cudaGetSymbolAddress((void**)&sc,   g_sc2);
    cudaGetSymbolAddress((void**)&scf,  g_scf);
    cudaGetSymbolAddress((void**)&ao,   g_ao2);
    cudaGetSymbolAddress((void**)&wqa,  g_wqa2);
    cudaGetSymbolAddress((void**)&wqb,  g_wqb2);
    cudaGetSymbolAddress((void**)&wkva, g_wkva2);
    cudaGetSymbolAddress((void**)&wk,   g_wk2);
    cudaGetSymbolAddress((void**)&wvT,  g_wv2);
    cudaGetSymbolAddress((void**)&woT,  g_wo2);

    bf16 *hidL = hid + N_HID,  *qlatL = qlat + N_QLAT, *qL = q + N_Q;
    bf16 *latL = lat + N_LAT,  *kfL = kf + N_KF;
    bf16 *kcatL = kcat + N_KCAT, *veffL = veff + N_VEFF;
    bf16 *scL  = sc + N_SC,    *aoL = ao + N_AO;
    bf16 *wqaL = wqa + N_WQA,  *wqbL = wqb + N_WQB,    *wkvaL = wkva + N_WKVA;
    bf16 *wkL  = wk + N_WK,    *wvTL = wvT + N_WV,     *woTL = woT + N_WO;

    constexpr int SM128 = 3 * (2 * 128 * 64 + 2 * 128 * 64);  // 98304
    constexpr int SM64  = 3 * (2 * 64 * 64 + 2 * 128 * 64);   // 73728
    cudaFuncSetAttribute(mma_gemm<128, 128>, cudaFuncAttributeMaxDynamicSharedMemorySize, SM128);
    cudaFuncSetAttribute(mma_gemm<64, 128>,  cudaFuncAttributeMaxDynamicSharedMemorySize, SM64);

    const dim3 tb(32, 8);

    // weight prep
    transpose_split<<<dim3(QL_ / 32, HID_ / 32, 1), tb>>>(w_qa, wqa, wqaL, HID_, QL_, QL_, 0, 0);
    transpose_split<<<dim3(NH_ * QDIM_ / 32, QL_ / 32, 1), tb>>>(w_qb, wqb, wqbL, QL_, NH_ * QDIM_, NH_ * QDIM_, 0, 0);
    // split hidden
    {
        long long n = (long long)N_HID;
        split_f32<<<(unsigned)((n + 255) / 256), 256>>>(hidden, hid, hidL, n);
    }
    // launch 3 (profile slot): q_lat = hidden @ w_qa
    mma_gemm<64, 128><<<dim3(QL_ / 128, S_ / 64, 1), 256, SM64>>>(
        hid, hidL, wqa, wqaL, qlat, qlatL, nullptr,
        S_, QL_, HID_, HID_, HID_, QL_, 0, 0, 0, 1.f, 0);
    rmsnorm_q<<<S_, 256>>>(qlat, qlatL, qa_ln);
    // q = q_lat @ w_qb
    mma_gemm<128, 128><<<dim3(NH_ * QDIM_ / 128, S_ / 128, 1), 256, SM128>>>(
        qlat, qlatL, wqb, wqbL, q, qL, nullptr,
        S_, NH_ * QDIM_, QL_, QL_, QL_, NH_ * QDIM_, 0, 0, 0, 1.f, 0);
    // rope q_pe in place in q
    {
        long long tot = (long long)S_ * NH_ * 32;
        rope_q_inplace<<<(unsigned)((tot + 255) / 256), 256>>>(q, qL, cosb, sinb);
    }
    // latent path
    transpose_split<<<dim3(DF_ / 32, HID_ / 32, 1), tb>>>(w_kva, wkva, wkvaL, HID_, DF_, DF_, 0, 0);
    mma_gemm<64, 128><<<dim3((DF_ + 127) / 128, S_ / 64, 1), 256, SM64>>>(
        hid, hidL, wkva, wkvaL, lat, latL, nullptr,
        S_, DF_, HID_, HID_, HID_, DF_, 0, 0, 0, 1.f, 0);
    kva_norm_rope<<<S_, 128>>>(lat, latL, kva_ln, cosb, sinb, kf, kfL);

    // ---- K_eff: kcat[h][t][0:128] = c_kv @ w_k[h]^T  (w_k natively K-major) --
    {
        long long n = (long long)N_WK;
        split_f32<<<(unsigned)((n + 255) / 256), 256>>>(w_k, wk, wkL, n);
    }
    mma_gemm<128, 128><<<dim3(1, S_ / 128, NH_), 256, SM128>>>(
        kf, kfL, wk, wkL, kcat, kcatL, nullptr,
        S_, DN_, KVL_, DF_, KVL_, KCAT_,
        0LL, (long long)DN_ * KVL_, (long long)S_ * KCAT_, 1.f, 0);
    // kcat pe broadcast
    {
        long long tot = (long long)NH_ * S_ * 8;
        kcat_pe<<<(unsigned)((tot + 255) / 256), 256>>>(kf, kfL, kcat, kcatL);
    }
    // ---- V_eff^T[h] = w_v[h]^T @ c_kv^T  -> [h][128][S] ----
    transpose_split<<<dim3(DV_ / 32, KVL_ / 32, NH_), tb>>>(w_v, wvT, wvTL, KVL_, DV_, DV_,
        (long long)KVL_ * DV_, (long long)DV_ * KVL_);
    mma_gemm<128, 128><<<dim3(S_ / 128, 1, NH_), 256, SM128>>>(
        wvT, wvTL, kf, kfL, veff, veffL, nullptr,
        DV_, S_, KVL_, KVL_, DF_, S_,
        (long long)DV_ * KVL_, 0LL, (long long)DV_ * S_, 1.f, 0);

    // ---- scores = SM_SCALE * q[h] @ kcat[h]^T  (K=192, causal skip) ----
    mma_gemm<128, 128><<<dim3(S_ / 128, S_ / 128, NH_), 256, SM128>>>(
        q, qL, kcat, kcatL, nullptr, nullptr, scf,
        S_, S_, KCAT_, NH_ * QDIM_, KCAT_, S_,
        (long long)QDIM_, (long long)S_ * KCAT_, (long long)S_ * S_, SM_SCALE_, 1 | 4);
    // softmax
    softmax_causal<<<dim3(S_, NH_), 256>>>(scf, sc, scL);
    // ---- ao[:, h*128:+128] = attn[h] @ V_eff[h]  (K-limit) ----
    mma_gemm<128, 128><<<dim3(1, S_ / 128, NH_), 256, SM128>>>(
        sc, scL, veff, veffL, ao, aoL, nullptr,
        S_, DV_, S_, S_, S_, NH_ * DV_,
        (long long)S_ * S_, (long long)DV_ * S_, (long long)DV_, 1.f, 2);
    // out = ao @ w_o
    transpose_split<<<dim3(HID_ / 32, (NH_ * DV_) / 32, 1), tb>>>(w_o, woT, woTL, NH_ * DV_, HID_, HID_, 0, 0);
    mma_gemm<128, 128><<<dim3(HID_ / 128, S_ / 128, 1), 256, SM128>>>(
        ao, aoL, woT, woTL, nullptr, nullptr, out,
        S_, HID_, NH_ * DV_, NH_ * DV_, NH_ * DV_, HID_, 0, 0, 0, 1.f, 4);
}